// round 2
// baseline (speedup 1.0000x reference)
#include <cuda_runtime.h>
#include <math.h>

#define BB 2
#define LL 4096
#define CC 256
#define C2 512
#define HH 8
#define DD 32
#define KK 9
#define MS (BB*LL)        /* 8192 token rows  */
#define MD (BB*LL*KK)     /* 73728 descriptor rows */

/* ------------------------------------------------------------------ */
/* scratch (device globals: allocation-free rule)                      */
/* ------------------------------------------------------------------ */
__device__ float g_x0[MS*CC];
__device__ float g_x1[MS*CC];
__device__ float g_desc0[MD*CC];   /* sampled from feat0 @ kp0 -> feeds feat1 update */
__device__ float g_desc1[MD*CC];   /* sampled from feat1 @ kp1 -> feeds feat0 update */
__device__ float g_qb[MS*CC];
__device__ float g_kb[MD*CC];
__device__ float g_vb[MD*CC];
__device__ float g_attb[MS*CC];
__device__ float g_tb[MS*CC];
__device__ float g_msgb[MS*CC];
__device__ float g_catb[MS*C2];
__device__ float g_ub[MS*C2];
__device__ float g_kvb[BB*HH*DD*DD];
__device__ float g_ksb[BB*HH*DD];

__device__ __forceinline__ float elu1(float x) { return x > 0.f ? x + 1.f : expf(x); }

/* masks arrive as 4-byte scalars (bool -> int32 or float32); nonzero == true
   for both encodings (int 1, float 1.0f = 0x3f800000) */
typedef const unsigned int* maskp;

/* ------------------------------------------------------------------ */
/* SGEMM: C[M,N] = A[M,Kd] @ B[Kd,N], 128x128 tile, 8-deep k, dbl buf  */
/* EPI: 0 = none, 1 = tanh                                             */
/* requires M%128==0, N%128==0, Kd%8==0                                */
/* ------------------------------------------------------------------ */
template<int EPI>
__global__ void __launch_bounds__(256) sgemm_kernel(
    const float* __restrict__ A, const float* __restrict__ Bw,
    float* __restrict__ Cmat, int M, int N, int Kd)
{
    __shared__ float As[2][8][128];
    __shared__ float Bs[2][8][128];
    int tid = threadIdx.x;
    int m0 = blockIdx.y << 7, n0 = blockIdx.x << 7;

    int arow = tid >> 1, acol = (tid & 1) << 2;
    const float* Ap = A + (size_t)(m0 + arow) * Kd + acol;
    int brow = tid >> 5, bcol = (tid & 31) << 2;
    const float* Bp = Bw + (size_t)brow * N + n0 + bcol;

    int tx = tid & 15, ty = tid >> 4;
    float acc[8][8];
#pragma unroll
    for (int i = 0; i < 8; ++i)
#pragma unroll
        for (int j = 0; j < 8; ++j) acc[i][j] = 0.f;

    float4 av = *(const float4*)Ap;
    float4 bv = *(const float4*)Bp;
    As[0][acol+0][arow] = av.x; As[0][acol+1][arow] = av.y;
    As[0][acol+2][arow] = av.z; As[0][acol+3][arow] = av.w;
    *(float4*)&Bs[0][brow][bcol] = bv;
    __syncthreads();

    int KT = Kd >> 3;
    for (int kt = 0; kt < KT; ++kt) {
        int cur = kt & 1;
        if (kt + 1 < KT) {
            av = *(const float4*)(Ap + ((kt + 1) << 3));
            bv = *(const float4*)(Bp + (size_t)((kt + 1) << 3) * N);
            int nxt = cur ^ 1;
            As[nxt][acol+0][arow] = av.x; As[nxt][acol+1][arow] = av.y;
            As[nxt][acol+2][arow] = av.z; As[nxt][acol+3][arow] = av.w;
            *(float4*)&Bs[nxt][brow][bcol] = bv;
        }
#pragma unroll
        for (int k = 0; k < 8; ++k) {
            float4 a0 = *(const float4*)&As[cur][k][ty << 3];
            float4 a1 = *(const float4*)&As[cur][k][(ty << 3) + 4];
            float4 b0 = *(const float4*)&Bs[cur][k][tx << 3];
            float4 b1 = *(const float4*)&Bs[cur][k][(tx << 3) + 4];
            float ar[8] = {a0.x,a0.y,a0.z,a0.w,a1.x,a1.y,a1.z,a1.w};
            float br[8] = {b0.x,b0.y,b0.z,b0.w,b1.x,b1.y,b1.z,b1.w};
#pragma unroll
            for (int i = 0; i < 8; ++i)
#pragma unroll
                for (int j = 0; j < 8; ++j)
                    acc[i][j] += ar[i] * br[j];
        }
        __syncthreads();
    }

#pragma unroll
    for (int i = 0; i < 8; ++i) {
        int r = m0 + (ty << 3) + i;
        float* Cp = Cmat + (size_t)r * N + n0 + (tx << 3);
        float o[8];
#pragma unroll
        for (int j = 0; j < 8; ++j)
            o[j] = (EPI == 1) ? tanhf(acc[i][j]) : acc[i][j];
        *(float4*)Cp       = make_float4(o[0], o[1], o[2], o[3]);
        *(float4*)(Cp + 4) = make_float4(o[4], o[5], o[6], o[7]);
    }
}

/* ------------------------------------------------------------------ */
/* Self linear attention: KV[b,h,d,e] = sum_s Kf[s,d]*Vm[s,e], Ksum    */
/* Kf = (elu(k)+1)*mask, Vm = v*mask   (v_len/L scaling cancels)       */
/* grid: BB*HH*16 blocks (16 chunks of 256 rows), 256 threads          */
/* ------------------------------------------------------------------ */
__global__ void __launch_bounds__(256) self_kv_kernel(
    const float* __restrict__ Kp, const float* __restrict__ Vp,
    maskp __restrict__ mask,
    float* __restrict__ KV, float* __restrict__ Ks)
{
    int blk = blockIdx.x;
    int ch = blk & 15;
    int h  = (blk >> 4) & 7;
    int b  = blk >> 7;
    int tid = threadIdx.x;
    int srow = tid >> 5, dloc = tid & 31;
    int d = tid >> 3, eq = tid & 7, e0 = eq << 2;
    __shared__ float sk[8][32], sv[8][32];
    float a0 = 0.f, a1 = 0.f, a2 = 0.f, a3 = 0.f, accs = 0.f;
    int sbase = ch << 8;
    for (int s0 = 0; s0 < 256; s0 += 8) {
        int row = b * LL + sbase + s0 + srow;
        float m = mask[row] ? 1.f : 0.f;
        float kr = Kp[(size_t)row * CC + h * DD + dloc];
        float vr = Vp[(size_t)row * CC + h * DD + dloc];
        sk[srow][dloc] = m * elu1(kr);
        sv[srow][dloc] = m * vr;
        __syncthreads();
#pragma unroll
        for (int j = 0; j < 8; ++j) {
            float kf = sk[j][d];
            a0 += kf * sv[j][e0 + 0];
            a1 += kf * sv[j][e0 + 1];
            a2 += kf * sv[j][e0 + 2];
            a3 += kf * sv[j][e0 + 3];
            if (eq == 0) accs += kf;
        }
        __syncthreads();
    }
    float* kvp = KV + ((size_t)((b * HH + h) * DD + d) * DD + e0);
    atomicAdd(kvp + 0, a0);
    atomicAdd(kvp + 1, a1);
    atomicAdd(kvp + 2, a2);
    atomicAdd(kvp + 3, a3);
    if (eq == 0) atomicAdd(Ks + (b * HH + h) * DD + d, accs);
}

/* out[b,l,h,e] = (sum_d Qf_d * KV[h,d,e]) / (Qf . Ksum[h] + 1e-6)     */
/* grid MS/16 blocks x 256 threads, 16 tokens per block                */
__global__ void __launch_bounds__(256) self_att_kernel(
    const float* __restrict__ Q, const float* __restrict__ KV,
    const float* __restrict__ Ks, float* __restrict__ Out)
{
    __shared__ float sKV[HH][DD][DD];
    __shared__ float sKs[HH][DD];
    __shared__ float sQf[CC];
    int tid = threadIdx.x;
    int t0 = blockIdx.x << 4;
    int b = t0 >> 12;
    for (int i = tid; i < HH * DD * DD; i += 256)
        (&sKV[0][0][0])[i] = KV[(size_t)b * HH * DD * DD + i];
    for (int i = tid; i < HH * DD; i += 256)
        (&sKs[0][0])[i] = Ks[b * HH * DD + i];
    __syncthreads();
    int h = tid >> 5, e = tid & 31;
    for (int tt = 0; tt < 16; ++tt) {
        int tok = t0 + tt;
        sQf[tid] = elu1(Q[(size_t)tok * CC + tid]);
        __syncthreads();
        float den = sQf[(h << 5) + e] * sKs[h][e];
#pragma unroll
        for (int o = 16; o; o >>= 1) den += __shfl_xor_sync(0xffffffffu, den, o);
        float out = 0.f;
#pragma unroll
        for (int d = 0; d < 32; ++d)
            out += sQf[(h << 5) + d] * sKV[h][d][e];
        Out[(size_t)tok * CC + tid] = out / (den + 1e-6f);
        __syncthreads();
    }
}

/* Cross attention (L=1, S=9): standard 9-key attention per token      */
/* one block (256 thr) per token; warp == head                         */
__global__ void __launch_bounds__(256) cross_att_kernel(
    const float* __restrict__ Q, const float* __restrict__ Kp,
    const float* __restrict__ Vp, maskp __restrict__ mask,
    float* __restrict__ Out)
{
    int tok = blockIdx.x;
    int tid = threadIdx.x;
    int h = tid >> 5, lane = tid & 31;
    __shared__ float sQf[CC];
    __shared__ float sm[KK];
    sQf[tid] = elu1(Q[(size_t)tok * CC + tid]);
    if (tid < KK) sm[tid] = mask[tok * KK + tid] ? 1.f : 0.f;
    __syncthreads();
    float qf = sQf[(h << 5) + lane];
    float w[KK];
    float den = 0.f;
#pragma unroll
    for (int s = 0; s < KK; ++s) {
        float kf = elu1(Kp[((size_t)tok * KK + s) * CC + (h << 5) + lane]) * sm[s];
        float p = qf * kf;
#pragma unroll
        for (int o = 16; o; o >>= 1) p += __shfl_xor_sync(0xffffffffu, p, o);
        w[s] = p;
        den += p;
    }
    float inv = 1.f / (den + 1e-6f);
    float out = 0.f;
#pragma unroll
    for (int s = 0; s < KK; ++s)
        out += w[s] * Vp[((size_t)tok * KK + s) * CC + (h << 5) + lane];
    Out[(size_t)tok * CC + tid] = out * inv;
}

/* LayerNorm over C=256 (eps 1e-5), warp per row. ADD: Out += ln else = */
template<bool ADD>
__global__ void __launch_bounds__(256) ln_kernel(
    const float* __restrict__ X, const float* __restrict__ gam,
    const float* __restrict__ bet, float* __restrict__ Out)
{
    int warp = threadIdx.x >> 5, lane = threadIdx.x & 31;
    int row = (blockIdx.x << 3) + warp;
    const float* xr = X + (size_t)row * CC;
    float v[8];
    float s = 0.f;
#pragma unroll
    for (int j = 0; j < 8; ++j) { v[j] = xr[lane + (j << 5)]; s += v[j]; }
#pragma unroll
    for (int o = 16; o; o >>= 1) s += __shfl_xor_sync(0xffffffffu, s, o);
    float mean = s * (1.f / 256.f);
    float q = 0.f;
#pragma unroll
    for (int j = 0; j < 8; ++j) { float d = v[j] - mean; q += d * d; }
#pragma unroll
    for (int o = 16; o; o >>= 1) q += __shfl_xor_sync(0xffffffffu, q, o);
    float rstd = rsqrtf(q * (1.f / 256.f) + 1e-5f);
#pragma unroll
    for (int j = 0; j < 8; ++j) {
        int c = lane + (j << 5);
        float o = (v[j] - mean) * rstd * gam[c] + bet[c];
        if (ADD) Out[(size_t)row * CC + c] += o;
        else     Out[(size_t)row * CC + c]  = o;
    }
}

__global__ void concat_kernel(const float* __restrict__ X,
                              const float* __restrict__ Msg,
                              float* __restrict__ Cat)
{
    int i = blockIdx.x * blockDim.x + threadIdx.x;
    if (i >= MS * C2) return;
    int m = i >> 9, c = i & 511;
    Cat[i] = (c < CC) ? X[(size_t)m * CC + c] : Msg[(size_t)m * CC + c - CC];
}

/* Bilinear sample + L2 normalize. warp per point, 8 points/block.     */
__global__ void __launch_bounds__(256) sample_kernel(
    const float* __restrict__ feat, const float* __restrict__ kp,
    float* __restrict__ desc)
{
    int p = (blockIdx.x << 3) + (threadIdx.x >> 5);
    int lane = threadIdx.x & 31;
    int b = p / (LL * KK);
    float kx = kp[(size_t)p * 2 + 0];
    float ky = kp[(size_t)p * 2 + 1];
    /* kp - s/2 + 0.5 -> /denom*2-1 -> (+1)*0.5*(W-1), W=H=64, s=8 */
    float nx = (kx - 3.5f) / 507.5f * 2.f - 1.f;
    float ny = (ky - 3.5f) / 507.5f * 2.f - 1.f;
    float px = (nx + 1.f) * 0.5f * 63.f;
    float py = (ny + 1.f) * 0.5f * 63.f;
    float x0f = floorf(px), y0f = floorf(py);
    float wx = px - x0f, wy = py - y0f;
    int ix0 = min(max((int)x0f, 0), 63);
    int ix1 = min(max((int)x0f + 1, 0), 63);
    int iy0 = min(max((int)y0f, 0), 63);
    int iy1 = min(max((int)y0f + 1, 0), 63);
    const float* f00 = feat + (size_t)(b * LL + (iy0 << 6) + ix0) * CC;
    const float* f01 = feat + (size_t)(b * LL + (iy0 << 6) + ix1) * CC;
    const float* f10 = feat + (size_t)(b * LL + (iy1 << 6) + ix0) * CC;
    const float* f11 = feat + (size_t)(b * LL + (iy1 << 6) + ix1) * CC;
    float w00 = (1.f - wy) * (1.f - wx), w01 = (1.f - wy) * wx;
    float w10 = wy * (1.f - wx),         w11 = wy * wx;
    float vals[8];
    float sq = 0.f;
#pragma unroll
    for (int j = 0; j < 8; ++j) {
        int c = lane + (j << 5);
        float val = w00 * f00[c] + w01 * f01[c] + w10 * f10[c] + w11 * f11[c];
        vals[j] = val;
        sq += val * val;
    }
#pragma unroll
    for (int o = 16; o; o >>= 1) sq += __shfl_xor_sync(0xffffffffu, sq, o);
    float inv = 1.f / (sqrtf(sq) + 1e-8f);
#pragma unroll
    for (int j = 0; j < 8; ++j)
        desc[(size_t)p * CC + lane + (j << 5)] = vals[j] * inv;
}

/* ------------------------------------------------------------------ */
/* host orchestration                                                  */
/* ------------------------------------------------------------------ */
struct LayerW {
    const float *wq, *wk, *wv, *wm, *w1, *w2, *g1, *b1, *g2, *b2;
};
struct Scratch {
    float *q, *k, *v, *att, *t, *msg, *cat, *u, *kv, *ks;
};

static void mlp_tail(float* x, const LayerW& w, const Scratch& s)
{
    dim3 gA(CC / 128, MS / 128);
    sgemm_kernel<0><<<gA, 256>>>(s.att, w.wm, s.t, MS, CC, CC);
    ln_kernel<false><<<MS / 8, 256>>>(s.t, w.g1, w.b1, s.msg);
    concat_kernel<<<(MS * C2 + 255) / 256, 256>>>(x, s.msg, s.cat);
    dim3 gB(C2 / 128, MS / 128);
    sgemm_kernel<1><<<gB, 256>>>(s.cat, w.w1, s.u, MS, C2, C2);
    dim3 gC(CC / 128, MS / 128);
    sgemm_kernel<0><<<gC, 256>>>(s.u, w.w2, s.t, MS, CC, C2);
    ln_kernel<true><<<MS / 8, 256>>>(s.t, w.g2, w.b2, x);
}

static void self_pass(float* x, maskp mask, const LayerW& w, const Scratch& s)
{
    dim3 g(CC / 128, MS / 128);
    sgemm_kernel<0><<<g, 256>>>(x, w.wq, s.q, MS, CC, CC);
    sgemm_kernel<0><<<g, 256>>>(x, w.wk, s.k, MS, CC, CC);
    sgemm_kernel<0><<<g, 256>>>(x, w.wv, s.v, MS, CC, CC);
    cudaMemsetAsync(s.kv, 0, (size_t)BB * HH * DD * DD * sizeof(float), 0);
    cudaMemsetAsync(s.ks, 0, (size_t)BB * HH * DD * sizeof(float), 0);
    self_kv_kernel<<<BB * HH * 16, 256>>>(s.k, s.v, mask, s.kv, s.ks);
    self_att_kernel<<<MS / 16, 256>>>(s.q, s.kv, s.ks, s.att);
    mlp_tail(x, w, s);
}

static void cross_pass(float* x, const float* desc, maskp maskc,
                       const LayerW& w, const Scratch& s)
{
    dim3 gq(CC / 128, MS / 128);
    sgemm_kernel<0><<<gq, 256>>>(x, w.wq, s.q, MS, CC, CC);
    dim3 gd(CC / 128, MD / 128);
    sgemm_kernel<0><<<gd, 256>>>(desc, w.wk, s.k, MD, CC, CC);
    sgemm_kernel<0><<<gd, 256>>>(desc, w.wv, s.v, MD, CC, CC);
    cross_att_kernel<<<MS, 256>>>(s.q, s.k, s.v, maskc, s.att);
    mlp_tail(x, w, s);
}

extern "C" void kernel_launch(void* const* d_in, const int* in_sizes, int n_in,
                              void* d_out, int out_size)
{
    (void)in_sizes; (void)n_in; (void)out_size;
    const float* feat0 = (const float*)d_in[0];
    const float* feat1 = (const float*)d_in[1];
    const float* kp0   = (const float*)d_in[2];
    const float* kp1   = (const float*)d_in[3];
    maskp ms0 = (maskp)d_in[4];
    maskp ms1 = (maskp)d_in[5];
    maskp mc0 = (maskp)d_in[6];
    maskp mc1 = (maskp)d_in[7];
    const float* Wq = (const float*)d_in[8];
    const float* Wk = (const float*)d_in[9];
    const float* Wv = (const float*)d_in[10];
    const float* Wm = (const float*)d_in[11];
    const float* W1 = (const float*)d_in[12];
    const float* W2 = (const float*)d_in[13];
    const float* G1 = (const float*)d_in[14];
    const float* B1 = (const float*)d_in[15];
    const float* G2 = (const float*)d_in[16];
    const float* B2 = (const float*)d_in[17];

    float *px0, *px1, *pd0, *pd1;
    Scratch s;
    cudaGetSymbolAddress((void**)&px0, g_x0);
    cudaGetSymbolAddress((void**)&px1, g_x1);
    cudaGetSymbolAddress((void**)&pd0, g_desc0);
    cudaGetSymbolAddress((void**)&pd1, g_desc1);
    cudaGetSymbolAddress((void**)&s.q, g_qb);
    cudaGetSymbolAddress((void**)&s.k, g_kb);
    cudaGetSymbolAddress((void**)&s.v, g_vb);
    cudaGetSymbolAddress((void**)&s.att, g_attb);
    cudaGetSymbolAddress((void**)&s.t, g_tb);
    cudaGetSymbolAddress((void**)&s.msg, g_msgb);
    cudaGetSymbolAddress((void**)&s.cat, g_catb);
    cudaGetSymbolAddress((void**)&s.u, g_ub);
    cudaGetSymbolAddress((void**)&s.kv, g_kvb);
    cudaGetSymbolAddress((void**)&s.ks, g_ksb);

    cudaMemcpyAsync(px0, feat0, (size_t)MS * CC * sizeof(float),
                    cudaMemcpyDeviceToDevice, 0);
    cudaMemcpyAsync(px1, feat1, (size_t)MS * CC * sizeof(float),
                    cudaMemcpyDeviceToDevice, 0);

    for (int i = 0; i < 4; ++i) {
        LayerW w;
        w.wq = Wq + (size_t)i * CC * CC;
        w.wk = Wk + (size_t)i * CC * CC;
        w.wv = Wv + (size_t)i * CC * CC;
        w.wm = Wm + (size_t)i * CC * CC;
        w.w1 = W1 + (size_t)i * C2 * C2;
        w.w2 = W2 + (size_t)i * C2 * CC;
        w.g1 = G1 + (size_t)i * CC;
        w.b1 = B1 + (size_t)i * CC;
        w.g2 = G2 + (size_t)i * CC;
        w.b2 = B2 + (size_t)i * CC;
        if ((i & 1) == 0) {
            /* self layer on both feature sets */
            self_pass(px0, ms0, w, s);
            self_pass(px1, ms1, w, s);
        } else {
            /* sample BOTH descriptor sets from pre-update features */
            sample_kernel<<<MD / 8, 256>>>(px1, kp1, pd1);
            sample_kernel<<<MD / 8, 256>>>(px0, kp0, pd0);
            /* feat0 attends to descriptors sampled from feat1 (mask_cross1) */
            cross_pass(px0, pd1, mc1, w, s);
            /* feat1 attends to descriptors sampled from feat0 (mask_cross0) */
            cross_pass(px1, pd0, mc0, w, s);
        }
    }

    cudaMemcpyAsync(d_out, px0, (size_t)MS * CC * sizeof(float),
                    cudaMemcpyDeviceToDevice, 0);
    cudaMemcpyAsync((float*)d_out + (size_t)MS * CC, px1,
                    (size_t)MS * CC * sizeof(float),
                    cudaMemcpyDeviceToDevice, 0);
}

// round 3
// speedup vs baseline: 1.2873x; 1.2873x over previous
#include <cuda_runtime.h>
#include <math.h>

#define BB 2
#define LL 4096
#define CC 256
#define C2 512
#define QS 768            /* packed qkv row stride */
#define HH 8
#define DD 32
#define KK 9
#define MS (BB*LL)        /* 8192 token rows  */
#define MD (BB*LL*KK)     /* 73728 sample points */

/* ------------------------------------------------------------------ */
/* scratch (device globals: allocation-free rule)                      */
/* ------------------------------------------------------------------ */
__device__ float g_x0[MS*CC];
__device__ float g_x1[MS*CC];
__device__ float g_qkv0[MS*QS];
__device__ float g_qkv1[MS*QS];
__device__ float g_invn0[MD];
__device__ float g_invn1[MD];
__device__ float g_attb[MS*CC];
__device__ float g_tb[MS*CC];
__device__ float g_msgb[MS*CC];
__device__ float g_ub[MS*C2];
__device__ float g_wp[CC*QS];
__device__ float g_kvb[BB*HH*DD*DD];
__device__ float g_ksb[BB*HH*DD];

__device__ __forceinline__ float elu1(float x) { return x > 0.f ? x + 1.f : expf(x); }

/* masks arrive as 4-byte scalars; nonzero == true for int32/float32 */
typedef const unsigned int* maskp;

/* ------------------------------------------------------------------ */
/* pack Wq|Wk|Wv -> [256,768]                                          */
/* ------------------------------------------------------------------ */
__global__ void pack3_kernel(const float* __restrict__ Wq,
                             const float* __restrict__ Wk,
                             const float* __restrict__ Wv,
                             float* __restrict__ Wp)
{
    int i = blockIdx.x * 256 + threadIdx.x;     /* 256*768 total */
    int k = i / QS, c = i - k * QS;
    float v;
    if (c < 256)      v = Wq[k * 256 + c];
    else if (c < 512) v = Wk[k * 256 + c - 256];
    else              v = Wv[k * 256 + c - 512];
    Wp[i] = v;
}

/* ------------------------------------------------------------------ */
/* SGEMM: C[M,N] = A @ B, 128x128 tile, 8-deep k, double buffered      */
/* SPLIT: A is [x | A2] halves, each row-stride 256 (Kd must be 512)   */
/* EPI: 0 none, 1 tanh                                                 */
/* ------------------------------------------------------------------ */
template<int EPI, bool SPLIT>
__global__ void __launch_bounds__(256) sgemm_kernel(
    const float* __restrict__ A, const float* __restrict__ A2,
    const float* __restrict__ Bw, float* __restrict__ Cmat,
    int M, int N, int Kd)
{
    __shared__ float As[2][8][128];
    __shared__ float Bs[2][8][128];
    int tid = threadIdx.x;
    int m0 = blockIdx.y << 7, n0 = blockIdx.x << 7;

    int arow = tid >> 1, acol = (tid & 1) << 2;
    int brow = tid >> 5, bcol = (tid & 31) << 2;
    const float* Bp = Bw + (size_t)brow * N + n0 + bcol;
    const float* ArowA  = A  + (size_t)(m0 + arow) * (SPLIT ? 256 : Kd);
    const float* ArowA2 = SPLIT ? A2 + (size_t)(m0 + arow) * 256 : nullptr;

    int tx = tid & 15, ty = tid >> 4;
    float acc[8][8];
#pragma unroll
    for (int i = 0; i < 8; ++i)
#pragma unroll
        for (int j = 0; j < 8; ++j) acc[i][j] = 0.f;

    float4 av, bv;
    {
        int col = acol;
        av = SPLIT ? (col < 256 ? *(const float4*)(ArowA + col)
                                : *(const float4*)(ArowA2 + col - 256))
                   : *(const float4*)(ArowA + col);
        bv = *(const float4*)Bp;
    }
    As[0][acol+0][arow] = av.x; As[0][acol+1][arow] = av.y;
    As[0][acol+2][arow] = av.z; As[0][acol+3][arow] = av.w;
    *(float4*)&Bs[0][brow][bcol] = bv;
    __syncthreads();

    int KT = Kd >> 3;
    for (int kt = 0; kt < KT; ++kt) {
        int cur = kt & 1;
        if (kt + 1 < KT) {
            int col = ((kt + 1) << 3) + acol;
            av = SPLIT ? (col < 256 ? *(const float4*)(ArowA + col)
                                    : *(const float4*)(ArowA2 + col - 256))
                       : *(const float4*)(ArowA + col);
            bv = *(const float4*)(Bp + (size_t)((kt + 1) << 3) * N);
            int nxt = cur ^ 1;
            As[nxt][acol+0][arow] = av.x; As[nxt][acol+1][arow] = av.y;
            As[nxt][acol+2][arow] = av.z; As[nxt][acol+3][arow] = av.w;
            *(float4*)&Bs[nxt][brow][bcol] = bv;
        }
#pragma unroll
        for (int k = 0; k < 8; ++k) {
            float4 a0 = *(const float4*)&As[cur][k][ty << 3];
            float4 a1 = *(const float4*)&As[cur][k][(ty << 3) + 4];
            float4 b0 = *(const float4*)&Bs[cur][k][tx << 3];
            float4 b1 = *(const float4*)&Bs[cur][k][(tx << 3) + 4];
            float ar[8] = {a0.x,a0.y,a0.z,a0.w,a1.x,a1.y,a1.z,a1.w};
            float br[8] = {b0.x,b0.y,b0.z,b0.w,b1.x,b1.y,b1.z,b1.w};
#pragma unroll
            for (int i = 0; i < 8; ++i)
#pragma unroll
                for (int j = 0; j < 8; ++j)
                    acc[i][j] += ar[i] * br[j];
        }
        __syncthreads();
    }

#pragma unroll
    for (int i = 0; i < 8; ++i) {
        int r = m0 + (ty << 3) + i;
        float* Cp = Cmat + (size_t)r * N + n0 + (tx << 3);
        float o[8];
#pragma unroll
        for (int j = 0; j < 8; ++j)
            o[j] = (EPI == 1) ? tanhf(acc[i][j]) : acc[i][j];
        *(float4*)Cp       = make_float4(o[0], o[1], o[2], o[3]);
        *(float4*)(Cp + 4) = make_float4(o[4], o[5], o[6], o[7]);
    }
}

/* ------------------------------------------------------------------ */
/* Self linear attention KV accumulation (qkv packed, stride 768)      */
/* ------------------------------------------------------------------ */
__global__ void __launch_bounds__(256) self_kv_kernel(
    const float* __restrict__ qkv, maskp __restrict__ mask,
    float* __restrict__ KV, float* __restrict__ Ks)
{
    int blk = blockIdx.x;
    int ch = blk & 15;
    int h  = (blk >> 4) & 7;
    int b  = blk >> 7;
    int tid = threadIdx.x;
    int srow = tid >> 5, dloc = tid & 31;
    int d = tid >> 3, eq = tid & 7, e0 = eq << 2;
    __shared__ float sk[8][32], sv[8][32];
    float a0 = 0.f, a1 = 0.f, a2 = 0.f, a3 = 0.f, accs = 0.f;
    int sbase = ch << 8;
    for (int s0 = 0; s0 < 256; s0 += 8) {
        int row = b * LL + sbase + s0 + srow;
        float m = mask[row] ? 1.f : 0.f;
        float kr = qkv[(size_t)row * QS + 256 + h * DD + dloc];
        float vr = qkv[(size_t)row * QS + 512 + h * DD + dloc];
        sk[srow][dloc] = m * elu1(kr);
        sv[srow][dloc] = m * vr;
        __syncthreads();
#pragma unroll
        for (int j = 0; j < 8; ++j) {
            float kf = sk[j][d];
            a0 += kf * sv[j][e0 + 0];
            a1 += kf * sv[j][e0 + 1];
            a2 += kf * sv[j][e0 + 2];
            a3 += kf * sv[j][e0 + 3];
            if (eq == 0) accs += kf;
        }
        __syncthreads();
    }
    float* kvp = KV + ((size_t)((b * HH + h) * DD + d) * DD + e0);
    atomicAdd(kvp + 0, a0);
    atomicAdd(kvp + 1, a1);
    atomicAdd(kvp + 2, a2);
    atomicAdd(kvp + 3, a3);
    if (eq == 0) atomicAdd(Ks + (b * HH + h) * DD + d, accs);
}

__global__ void __launch_bounds__(256) self_att_kernel(
    const float* __restrict__ qkv, const float* __restrict__ KV,
    const float* __restrict__ Ks, float* __restrict__ Out)
{
    __shared__ float sKV[HH][DD][DD];
    __shared__ float sKs[HH][DD];
    __shared__ float sQf[CC];
    int tid = threadIdx.x;
    int t0 = blockIdx.x << 4;
    int b = t0 >> 12;
    for (int i = tid; i < HH * DD * DD; i += 256)
        (&sKV[0][0][0])[i] = KV[(size_t)b * HH * DD * DD + i];
    for (int i = tid; i < HH * DD; i += 256)
        (&sKs[0][0])[i] = Ks[b * HH * DD + i];
    __syncthreads();
    int h = tid >> 5, e = tid & 31;
    for (int tt = 0; tt < 16; ++tt) {
        int tok = t0 + tt;
        sQf[tid] = elu1(qkv[(size_t)tok * QS + tid]);
        __syncthreads();
        float den = sQf[(h << 5) + e] * sKs[h][e];
#pragma unroll
        for (int o = 16; o; o >>= 1) den += __shfl_xor_sync(0xffffffffu, den, o);
        float out = 0.f;
#pragma unroll
        for (int d = 0; d < 32; ++d)
            out += sQf[(h << 5) + d] * sKV[h][d][e];
        Out[(size_t)tok * CC + tid] = out / (den + 1e-6f);
        __syncthreads();
    }
}

/* ------------------------------------------------------------------ */
/* bilinear tap computation (shared by invnorm + cross att)            */
/* ------------------------------------------------------------------ */
__device__ __forceinline__ void taps_of(float kx, float ky, int base,
                                        int* r, float* w)
{
    float px = (((kx - 3.5f) / 507.5f * 2.f - 1.f) + 1.f) * 0.5f * 63.f;
    float py = (((ky - 3.5f) / 507.5f * 2.f - 1.f) + 1.f) * 0.5f * 63.f;
    float x0f = floorf(px), y0f = floorf(py);
    float wx = px - x0f, wy = py - y0f;
    int ix0 = min(max((int)x0f, 0), 63);
    int ix1 = min(max((int)x0f + 1, 0), 63);
    int iy0 = min(max((int)y0f, 0), 63);
    int iy1 = min(max((int)y0f + 1, 0), 63);
    r[0] = base + (iy0 << 6) + ix0;
    r[1] = base + (iy0 << 6) + ix1;
    r[2] = base + (iy1 << 6) + ix0;
    r[3] = base + (iy1 << 6) + ix1;
    w[0] = (1.f - wy) * (1.f - wx);
    w[1] = (1.f - wy) * wx;
    w[2] = wy * (1.f - wx);
    w[3] = wy * wx;
}

/* inverse L2 norm of bilerped raw features; warp per point            */
__global__ void __launch_bounds__(256) invnorm_kernel(
    const float* __restrict__ feat, const float* __restrict__ kp,
    float* __restrict__ invn)
{
    int p = (blockIdx.x << 3) + (threadIdx.x >> 5);
    int lane = threadIdx.x & 31;
    int b = p / (LL * KK);
    int r[4]; float w[4];
    taps_of(kp[(size_t)p * 2], kp[(size_t)p * 2 + 1], b * LL, r, w);
    const float* f0 = feat + (size_t)r[0] * CC;
    const float* f1 = feat + (size_t)r[1] * CC;
    const float* f2 = feat + (size_t)r[2] * CC;
    const float* f3 = feat + (size_t)r[3] * CC;
    float sq = 0.f;
#pragma unroll
    for (int j = 0; j < 8; ++j) {
        int c = lane + (j << 5);
        float val = w[0]*f0[c] + w[1]*f1[c] + w[2]*f2[c] + w[3]*f3[c];
        sq += val * val;
    }
#pragma unroll
    for (int o = 16; o; o >>= 1) sq += __shfl_xor_sync(0xffffffffu, sq, o);
    if (lane == 0) invn[p] = 1.f / (sqrtf(sq) + 1e-8f);
}

/* ------------------------------------------------------------------ */
/* Fused cross attention: gathers projected K/V rows (bilerp of Gk/Gv) */
/* one block per token; warp == head                                   */
/* ------------------------------------------------------------------ */
__global__ void __launch_bounds__(256) cross_att_kernel(
    const float* __restrict__ qkv_x, const float* __restrict__ qkv_src,
    const float* __restrict__ kp, const float* __restrict__ invn,
    maskp __restrict__ mask, float* __restrict__ Out)
{
    int t = blockIdx.x;
    int tid = threadIdx.x;
    int h = tid >> 5, lane = tid & 31;
    __shared__ float sQf[CC];
    __shared__ int   sTap[KK][4];
    __shared__ float sW[KK][4];
    __shared__ float sInv[KK];
    __shared__ float sM[KK];
    sQf[tid] = elu1(qkv_x[(size_t)t * QS + tid]);
    if (tid < KK) {
        int p = t * KK + tid;
        int b = t >> 12;
        int r[4]; float w[4];
        taps_of(kp[(size_t)p * 2], kp[(size_t)p * 2 + 1], b * LL, r, w);
#pragma unroll
        for (int i = 0; i < 4; ++i) { sTap[tid][i] = r[i]; sW[tid][i] = w[i]; }
        sInv[tid] = invn[p];
        sM[tid] = mask[p] ? 1.f : 0.f;
    }
    __syncthreads();
    int c = (h << 5) + lane;
    float qf = sQf[c];
    float wgt[KK];
    float den = 0.f;
#pragma unroll
    for (int s = 0; s < KK; ++s) {
        float kraw =
            sW[s][0] * qkv_src[(size_t)sTap[s][0] * QS + 256 + c] +
            sW[s][1] * qkv_src[(size_t)sTap[s][1] * QS + 256 + c] +
            sW[s][2] * qkv_src[(size_t)sTap[s][2] * QS + 256 + c] +
            sW[s][3] * qkv_src[(size_t)sTap[s][3] * QS + 256 + c];
        float kf = elu1(kraw * sInv[s]) * sM[s];
        float p = qf * kf;
#pragma unroll
        for (int o = 16; o; o >>= 1) p += __shfl_xor_sync(0xffffffffu, p, o);
        wgt[s] = p;
        den += p;
    }
    float inv = 1.f / (den + 1e-6f);
    float out = 0.f;
#pragma unroll
    for (int s = 0; s < KK; ++s) {
        float vraw =
            sW[s][0] * qkv_src[(size_t)sTap[s][0] * QS + 512 + c] +
            sW[s][1] * qkv_src[(size_t)sTap[s][1] * QS + 512 + c] +
            sW[s][2] * qkv_src[(size_t)sTap[s][2] * QS + 512 + c] +
            sW[s][3] * qkv_src[(size_t)sTap[s][3] * QS + 512 + c];
        out += wgt[s] * (vraw * sInv[s]);
    }
    Out[(size_t)t * CC + tid] = out * inv;
}

/* LayerNorm over C=256 (eps 1e-5), warp per row                       */
template<bool ADD>
__global__ void __launch_bounds__(256) ln_kernel(
    const float* __restrict__ X, const float* __restrict__ gam,
    const float* __restrict__ bet, float* __restrict__ Out)
{
    int warp = threadIdx.x >> 5, lane = threadIdx.x & 31;
    int row = (blockIdx.x << 3) + warp;
    const float* xr = X + (size_t)row * CC;
    float v[8];
    float s = 0.f;
#pragma unroll
    for (int j = 0; j < 8; ++j) { v[j] = xr[lane + (j << 5)]; s += v[j]; }
#pragma unroll
    for (int o = 16; o; o >>= 1) s += __shfl_xor_sync(0xffffffffu, s, o);
    float mean = s * (1.f / 256.f);
    float q = 0.f;
#pragma unroll
    for (int j = 0; j < 8; ++j) { float d = v[j] - mean; q += d * d; }
#pragma unroll
    for (int o = 16; o; o >>= 1) q += __shfl_xor_sync(0xffffffffu, q, o);
    float rstd = rsqrtf(q * (1.f / 256.f) + 1e-5f);
#pragma unroll
    for (int j = 0; j < 8; ++j) {
        int cc = lane + (j << 5);
        float o = (v[j] - mean) * rstd * gam[cc] + bet[cc];
        if (ADD) Out[(size_t)row * CC + cc] += o;
        else     Out[(size_t)row * CC + cc]  = o;
    }
}

/* ------------------------------------------------------------------ */
/* host orchestration                                                  */
/* ------------------------------------------------------------------ */
struct LayerW {
    const float *wq, *wk, *wv, *wm, *w1, *w2, *g1, *b1, *g2, *b2;
};
struct Scratch {
    float *att, *t, *msg, *u, *wp, *kv, *ks;
};

static void mlp_tail(float* x, const LayerW& w, const Scratch& s)
{
    dim3 gA(CC / 128, MS / 128);
    sgemm_kernel<0,false><<<gA, 256>>>(s.att, nullptr, w.wm, s.t, MS, CC, CC);
    ln_kernel<false><<<MS / 8, 256>>>(s.t, w.g1, w.b1, s.msg);
    dim3 gB(C2 / 128, MS / 128);
    sgemm_kernel<1,true><<<gB, 256>>>(x, s.msg, w.w1, s.u, MS, C2, C2);
    dim3 gC(CC / 128, MS / 128);
    sgemm_kernel<0,false><<<gC, 256>>>(s.u, nullptr, w.w2, s.t, MS, CC, C2);
    ln_kernel<true><<<MS / 8, 256>>>(s.t, w.g2, w.b2, x);
}

extern "C" void kernel_launch(void* const* d_in, const int* in_sizes, int n_in,
                              void* d_out, int out_size)
{
    (void)in_sizes; (void)n_in; (void)out_size;
    const float* feat0 = (const float*)d_in[0];
    const float* feat1 = (const float*)d_in[1];
    const float* kp0   = (const float*)d_in[2];
    const float* kp1   = (const float*)d_in[3];
    maskp ms0 = (maskp)d_in[4];
    maskp ms1 = (maskp)d_in[5];
    maskp mc0 = (maskp)d_in[6];
    maskp mc1 = (maskp)d_in[7];
    const float* Wq = (const float*)d_in[8];
    const float* Wk = (const float*)d_in[9];
    const float* Wv = (const float*)d_in[10];
    const float* Wm = (const float*)d_in[11];
    const float* W1 = (const float*)d_in[12];
    const float* W2 = (const float*)d_in[13];
    const float* G1 = (const float*)d_in[14];
    const float* B1 = (const float*)d_in[15];
    const float* G2 = (const float*)d_in[16];
    const float* B2 = (const float*)d_in[17];

    float *px0, *px1, *pq0, *pq1, *pin0, *pin1;
    Scratch s;
    cudaGetSymbolAddress((void**)&px0, g_x0);
    cudaGetSymbolAddress((void**)&px1, g_x1);
    cudaGetSymbolAddress((void**)&pq0, g_qkv0);
    cudaGetSymbolAddress((void**)&pq1, g_qkv1);
    cudaGetSymbolAddress((void**)&pin0, g_invn0);
    cudaGetSymbolAddress((void**)&pin1, g_invn1);
    cudaGetSymbolAddress((void**)&s.att, g_attb);
    cudaGetSymbolAddress((void**)&s.t, g_tb);
    cudaGetSymbolAddress((void**)&s.msg, g_msgb);
    cudaGetSymbolAddress((void**)&s.u, g_ub);
    cudaGetSymbolAddress((void**)&s.wp, g_wp);
    cudaGetSymbolAddress((void**)&s.kv, g_kvb);
    cudaGetSymbolAddress((void**)&s.ks, g_ksb);

    cudaMemcpyAsync(px0, feat0, (size_t)MS * CC * sizeof(float),
                    cudaMemcpyDeviceToDevice, 0);
    cudaMemcpyAsync(px1, feat1, (size_t)MS * CC * sizeof(float),
                    cudaMemcpyDeviceToDevice, 0);

    for (int i = 0; i < 4; ++i) {
        LayerW w;
        w.wq = Wq + (size_t)i * CC * CC;
        w.wk = Wk + (size_t)i * CC * CC;
        w.wv = Wv + (size_t)i * CC * CC;
        w.wm = Wm + (size_t)i * CC * CC;
        w.w1 = W1 + (size_t)i * C2 * C2;
        w.w2 = W2 + (size_t)i * C2 * CC;
        w.g1 = G1 + (size_t)i * CC;
        w.b1 = B1 + (size_t)i * CC;
        w.g2 = G2 + (size_t)i * CC;
        w.b2 = B2 + (size_t)i * CC;

        /* packed projection for both features (pre-update sources) */
        pack3_kernel<<<CC * QS / 256, 256>>>(w.wq, w.wk, w.wv, s.wp);
        dim3 gp(QS / 128, MS / 128);
        sgemm_kernel<0,false><<<gp, 256>>>(px0, nullptr, s.wp, pq0, MS, QS, CC);
        sgemm_kernel<0,false><<<gp, 256>>>(px1, nullptr, s.wp, pq1, MS, QS, CC);

        if ((i & 1) == 0) {
            /* self layers */
            cudaMemsetAsync(s.kv, 0, (size_t)BB*HH*DD*DD*sizeof(float), 0);
            cudaMemsetAsync(s.ks, 0, (size_t)BB*HH*DD*sizeof(float), 0);
            self_kv_kernel<<<BB * HH * 16, 256>>>(pq0, ms0, s.kv, s.ks);
            self_att_kernel<<<MS / 16, 256>>>(pq0, s.kv, s.ks, s.att);
            mlp_tail(px0, w, s);
            cudaMemsetAsync(s.kv, 0, (size_t)BB*HH*DD*DD*sizeof(float), 0);
            cudaMemsetAsync(s.ks, 0, (size_t)BB*HH*DD*sizeof(float), 0);
            self_kv_kernel<<<BB * HH * 16, 256>>>(pq1, ms1, s.kv, s.ks);
            self_att_kernel<<<MS / 16, 256>>>(pq1, s.kv, s.ks, s.att);
            mlp_tail(px1, w, s);
        } else {
            /* cross layers: inverse norms from PRE-update raw features */
            invnorm_kernel<<<MD / 8, 256>>>(px0, kp0, pin0);
            invnorm_kernel<<<MD / 8, 256>>>(px1, kp1, pin1);
            /* feat0 attends to feat1 sampled @ kp1 (mask_cross1) */
            cross_att_kernel<<<MS, 256>>>(pq0, pq1, kp1, pin1, mc1, s.att);
            mlp_tail(px0, w, s);
            /* feat1 attends to feat0 sampled @ kp0 (mask_cross0) */
            cross_att_kernel<<<MS, 256>>>(pq1, pq0, kp0, pin0, mc0, s.att);
            mlp_tail(px1, w, s);
        }
    }

    cudaMemcpyAsync(d_out, px0, (size_t)MS * CC * sizeof(float),
                    cudaMemcpyDeviceToDevice, 0);
    cudaMemcpyAsync((float*)d_out + (size_t)MS * CC, px1,
                    (size_t)MS * CC * sizeof(float),
                    cudaMemcpyDeviceToDevice, 0);
}

// round 7
// speedup vs baseline: 1.9791x; 1.5374x over previous
#include <cuda_runtime.h>
#include <cuda_bf16.h>
#include <cstdint>
#include <math.h>

#define BB 2
#define LL 4096
#define CC 256
#define C2 512
#define QS 768
#define HH 8
#define DD 32
#define KK 9
#define MS (BB*LL)
#define MD (BB*LL*KK)

/* ------------------------------------------------------------------ */
/* scratch (device globals)                                            */
/* ------------------------------------------------------------------ */
__device__ float g_x0[MS*CC];
__device__ float g_x1[MS*CC];
__device__ float g_qkv0[MS*QS];
__device__ float g_qkv1[MS*QS];
__device__ float g_invn0[MD];
__device__ float g_invn1[MD];
__device__ float g_attb[MS*CC];
__device__ float g_tb[MS*CC];
__device__ float g_msgb[MS*CC];
__device__ float g_ub[MS*C2];
__device__ float g_kvb[BB*HH*DD*DD];
__device__ float g_ksb[BB*HH*DD];
/* pre-split transposed weights, bf16 hi/lo, layout [N, K] */
__device__ __nv_bfloat16 g_whP[QS*CC], g_wlP[QS*CC];     /* proj  768x256 */
__device__ __nv_bfloat16 g_whM[CC*CC], g_wlM[CC*CC];     /* Wm    256x256 */
__device__ __nv_bfloat16 g_wh1[C2*C2], g_wl1[C2*C2];     /* W1    512x512 */
__device__ __nv_bfloat16 g_wh2[CC*C2], g_wl2[CC*C2];     /* W2    256x512 */

__device__ __forceinline__ float elu1(float x) { return x > 0.f ? x + 1.f : expf(x); }
typedef const unsigned int* maskp;

__device__ __forceinline__ void bsplit2(float a, float b, uint32_t& h, uint32_t& l) {
    __nv_bfloat16 ah = __float2bfloat16(a), bh = __float2bfloat16(b);
    float ar = a - __bfloat162float(ah), br = b - __bfloat162float(bh);
    __nv_bfloat16 al = __float2bfloat16(ar), bl = __float2bfloat16(br);
    h = (uint32_t)__bfloat16_as_ushort(ah) | ((uint32_t)__bfloat16_as_ushort(bh) << 16);
    l = (uint32_t)__bfloat16_as_ushort(al) | ((uint32_t)__bfloat16_as_ushort(bl) << 16);
}

/* bf16 mma.sync m16n8k16 (sm_80+ baseline PTX, runs on tensor cores)  */
__device__ __forceinline__ void mma16816(float* c, const uint32_t* a,
                                         const uint32_t* b) {
    asm volatile(
        "mma.sync.aligned.m16n8k16.row.col.f32.bf16.bf16.f32 "
        "{%0,%1,%2,%3}, {%4,%5,%6,%7}, {%8,%9}, {%0,%1,%2,%3};"
        : "+f"(c[0]), "+f"(c[1]), "+f"(c[2]), "+f"(c[3])
        : "r"(a[0]), "r"(a[1]), "r"(a[2]), "r"(a[3]), "r"(b[0]), "r"(b[1]));
}

/* ------------------------------------------------------------------ */
/* HMMA GEMM: C[8192,N] = A[8192,Kd] @ W[Kd,N]  (W pre-split [N,Kd])   */
/* CTA tile 128x128, warp tile 64x32 (8 warps 2x4), k-chunk 32,        */
/* double-buffered smem, bf16x3 split. epi=1: tanh.                    */
/* split!=0: A = [A1 | A2], each row-stride 256 (Kd==512)              */
/* ------------------------------------------------------------------ */
#define TSTR 36                        /* halves per smem tile row     */
#define TILE_H (128*TSTR)              /* halves per tile              */
#define OFF_AH 0
#define OFF_AL TILE_H
#define OFF_BH (2*TILE_H)
#define OFF_BL (3*TILE_H)
#define STAGE_H (4*TILE_H)             /* halves per stage             */
#define DSMEM (2*STAGE_H*2)            /* bytes: 73728                 */

__global__ void __launch_bounds__(256)
hgemm_kernel(const float* __restrict__ A1, const float* __restrict__ A2,
             const __nv_bfloat16* __restrict__ Wh,
             const __nv_bfloat16* __restrict__ Wl,
             float* __restrict__ Cmat, int N, int Kd, int epi, int split)
{
    extern __shared__ __align__(16) unsigned short smh[];
    int tid = threadIdx.x, wid = tid >> 5, lane = tid & 31;
    int g = lane >> 2, q = lane & 3;
    int m0 = blockIdx.y << 7, n0 = blockIdx.x << 7;
    int wm = wid >> 2, wn = wid & 3;       /* 2 x 4 warp grid */
    int arow = wm << 6, brow = wn << 5;

    float acc[4][4][4];
#pragma unroll
    for (int i = 0; i < 4; ++i)
#pragma unroll
        for (int j = 0; j < 4; ++j)
#pragma unroll
            for (int k = 0; k < 4; ++k) acc[i][j][k] = 0.f;

    const int NC = Kd >> 5;

    /* ---- produce chunk 0 into stage 0 ---- */
    {
        const float* abase;
        int lda;
        if (split) { abase = A1; lda = 256; } else { abase = A1; lda = Kd; }
#pragma unroll
        for (int it = 0; it < 4; ++it) {
            int idx = tid + (it << 8);
            int r = idx >> 3, cg = (idx & 7) << 2;
            float4 f = *(const float4*)(abase + (size_t)(m0 + r) * lda + cg);
            uint2 h, l;
            bsplit2(f.x, f.y, h.x, l.x);
            bsplit2(f.z, f.w, h.y, l.y);
            *(uint2*)(smh + OFF_AH + r * TSTR + cg) = h;
            *(uint2*)(smh + OFF_AL + r * TSTR + cg) = l;
        }
#pragma unroll
        for (int it = 0; it < 4; ++it) {
            int idx = tid + (it << 8);
            int r = idx >> 3, cg = (idx & 7) << 2;
            size_t src = (size_t)(n0 + r) * Kd + cg;
            *(uint2*)(smh + OFF_BH + r * TSTR + cg) = *(const uint2*)(Wh + src);
            *(uint2*)(smh + OFF_BL + r * TSTR + cg) = *(const uint2*)(Wl + src);
        }
    }
    __syncthreads();

    for (int kt = 0; kt < NC; ++kt) {
        int s = kt & 1;
        const unsigned short* st = smh + s * STAGE_H;

        /* ---- prefetch chunk kt+1 from gmem into registers ---- */
        float4 fa[4];
        uint2 pbh[4], pbl[4];
        int k1 = (kt + 1) << 5;
        if (kt + 1 < NC) {
            const float* abase;
            int lda, koff;
            if (split) {
                if (k1 < 256) { abase = A1; koff = k1; }
                else          { abase = A2; koff = k1 - 256; }
                lda = 256;
            } else { abase = A1; koff = k1; lda = Kd; }
#pragma unroll
            for (int it = 0; it < 4; ++it) {
                int idx = tid + (it << 8);
                int r = idx >> 3, cg = (idx & 7) << 2;
                fa[it] = *(const float4*)(abase + (size_t)(m0 + r) * lda + koff + cg);
            }
#pragma unroll
            for (int it = 0; it < 4; ++it) {
                int idx = tid + (it << 8);
                int r = idx >> 3, cg = (idx & 7) << 2;
                size_t src = (size_t)(n0 + r) * Kd + k1 + cg;
                pbh[it] = *(const uint2*)(Wh + src);
                pbl[it] = *(const uint2*)(Wl + src);
            }
        }

        /* ---- compute on stage s ---- */
        const unsigned short* pAh = st + OFF_AH;
        const unsigned short* pAl = st + OFF_AL;
        const unsigned short* pBh = st + OFF_BH;
        const unsigned short* pBl = st + OFF_BL;
#pragma unroll
        for (int ks = 0; ks < 32; ks += 16) {
            uint32_t aH[4][4], bH[4][2];
#pragma unroll
            for (int mf = 0; mf < 4; ++mf) {
                const unsigned short* p =
                    pAh + (arow + (mf << 4) + g) * TSTR + ks + (q << 1);
                aH[mf][0] = *(const uint32_t*)p;
                aH[mf][1] = *(const uint32_t*)(p + 8 * TSTR);
                aH[mf][2] = *(const uint32_t*)(p + 8);
                aH[mf][3] = *(const uint32_t*)(p + 8 * TSTR + 8);
            }
#pragma unroll
            for (int nf = 0; nf < 4; ++nf) {
                const unsigned short* p =
                    pBh + (brow + (nf << 3) + g) * TSTR + ks + (q << 1);
                bH[nf][0] = *(const uint32_t*)p;
                bH[nf][1] = *(const uint32_t*)(p + 8);
            }
#pragma unroll
            for (int mf = 0; mf < 4; ++mf)
#pragma unroll
                for (int nf = 0; nf < 4; ++nf)
                    mma16816(acc[mf][nf], aH[mf], bH[nf]);
            {
                uint32_t bL[4][2];
#pragma unroll
                for (int nf = 0; nf < 4; ++nf) {
                    const unsigned short* p =
                        pBl + (brow + (nf << 3) + g) * TSTR + ks + (q << 1);
                    bL[nf][0] = *(const uint32_t*)p;
                    bL[nf][1] = *(const uint32_t*)(p + 8);
                }
#pragma unroll
                for (int mf = 0; mf < 4; ++mf)
#pragma unroll
                    for (int nf = 0; nf < 4; ++nf)
                        mma16816(acc[mf][nf], aH[mf], bL[nf]);
            }
            {
                uint32_t aL[4][4];
#pragma unroll
                for (int mf = 0; mf < 4; ++mf) {
                    const unsigned short* p =
                        pAl + (arow + (mf << 4) + g) * TSTR + ks + (q << 1);
                    aL[mf][0] = *(const uint32_t*)p;
                    aL[mf][1] = *(const uint32_t*)(p + 8 * TSTR);
                    aL[mf][2] = *(const uint32_t*)(p + 8);
                    aL[mf][3] = *(const uint32_t*)(p + 8 * TSTR + 8);
                }
#pragma unroll
                for (int mf = 0; mf < 4; ++mf)
#pragma unroll
                    for (int nf = 0; nf < 4; ++nf)
                        mma16816(acc[mf][nf], aL[mf], bH[nf]);
            }
        }

        /* ---- store prefetched chunk to stage s^1 ---- */
        if (kt + 1 < NC) {
            unsigned short* dst = smh + (s ^ 1) * STAGE_H;
#pragma unroll
            for (int it = 0; it < 4; ++it) {
                int idx = tid + (it << 8);
                int r = idx >> 3, cg = (idx & 7) << 2;
                uint2 h, l;
                bsplit2(fa[it].x, fa[it].y, h.x, l.x);
                bsplit2(fa[it].z, fa[it].w, h.y, l.y);
                *(uint2*)(dst + OFF_AH + r * TSTR + cg) = h;
                *(uint2*)(dst + OFF_AL + r * TSTR + cg) = l;
                *(uint2*)(dst + OFF_BH + r * TSTR + cg) = pbh[it];
                *(uint2*)(dst + OFF_BL + r * TSTR + cg) = pbl[it];
            }
        }
        __syncthreads();
    }

    /* ---- epilogue: direct stores ---- */
#pragma unroll
    for (int mf = 0; mf < 4; ++mf) {
#pragma unroll
        for (int nf = 0; nf < 4; ++nf) {
            int r = m0 + arow + (mf << 4) + g;
            int c = n0 + brow + (nf << 3) + (q << 1);
            float2 v0, v1;
            v0.x = acc[mf][nf][0]; v0.y = acc[mf][nf][1];
            v1.x = acc[mf][nf][2]; v1.y = acc[mf][nf][3];
            if (epi == 1) {
                v0.x = tanhf(v0.x); v0.y = tanhf(v0.y);
                v1.x = tanhf(v1.x); v1.y = tanhf(v1.y);
            }
            *(float2*)(Cmat + (size_t)r * N + c) = v0;
            *(float2*)(Cmat + (size_t)(r + 8) * N + c) = v1;
        }
    }
}

/* ------------------------------------------------------------------ */
/* weight prep: transpose + bf16 hi/lo split                           */
/* ------------------------------------------------------------------ */
__global__ void wtrans_kernel(const float* __restrict__ W,
                              __nv_bfloat16* __restrict__ wh,
                              __nv_bfloat16* __restrict__ wl, int Kd, int N)
{
    int idx = blockIdx.x * 256 + threadIdx.x;    /* N*Kd total */
    int k = idx / N, n = idx - k * N;
    float v = W[(size_t)k * N + n];
    __nv_bfloat16 h = __float2bfloat16(v);
    __nv_bfloat16 l = __float2bfloat16(v - __bfloat162float(h));
    wh[(size_t)n * Kd + k] = h;
    wl[(size_t)n * Kd + k] = l;
}

__global__ void wpackT_kernel(const float* __restrict__ Wq,
                              const float* __restrict__ Wk,
                              const float* __restrict__ Wv,
                              __nv_bfloat16* __restrict__ wh,
                              __nv_bfloat16* __restrict__ wl)
{
    int idx = blockIdx.x * 256 + threadIdx.x;    /* 256 (K) * 768 (N) */
    int k = idx / QS, n = idx - k * QS;
    const float* src = (n < 256) ? Wq : (n < 512) ? Wk : Wv;
    int nn = n & 255;
    float v = src[(size_t)k * 256 + nn];
    __nv_bfloat16 h = __float2bfloat16(v);
    __nv_bfloat16 l = __float2bfloat16(v - __bfloat162float(h));
    wh[(size_t)n * CC + k] = h;
    wl[(size_t)n * CC + k] = l;
}

/* ------------------------------------------------------------------ */
/* Self linear attention (packed qkv, stride 768)                      */
/* ------------------------------------------------------------------ */
__global__ void __launch_bounds__(256) self_kv_kernel(
    const float* __restrict__ qkv, maskp __restrict__ mask,
    float* __restrict__ KV, float* __restrict__ Ks)
{
    int blk = blockIdx.x;
    int ch = blk & 15;
    int h  = (blk >> 4) & 7;
    int b  = blk >> 7;
    int tid = threadIdx.x;
    int srow = tid >> 5, dloc = tid & 31;
    int d = tid >> 3, eq = tid & 7, e0 = eq << 2;
    __shared__ float sk[8][32], sv[8][32];
    float a0 = 0.f, a1 = 0.f, a2 = 0.f, a3 = 0.f, accs = 0.f;
    int sbase = ch << 8;
    for (int s0 = 0; s0 < 256; s0 += 8) {
        int row = b * LL + sbase + s0 + srow;
        float m = mask[row] ? 1.f : 0.f;
        float kr = qkv[(size_t)row * QS + 256 + h * DD + dloc];
        float vr = qkv[(size_t)row * QS + 512 + h * DD + dloc];
        sk[srow][dloc] = m * elu1(kr);
        sv[srow][dloc] = m * vr;
        __syncthreads();
#pragma unroll
        for (int j = 0; j < 8; ++j) {
            float kf = sk[j][d];
            a0 += kf * sv[j][e0 + 0];
            a1 += kf * sv[j][e0 + 1];
            a2 += kf * sv[j][e0 + 2];
            a3 += kf * sv[j][e0 + 3];
            if (eq == 0) accs += kf;
        }
        __syncthreads();
    }
    float* kvp = KV + ((size_t)((b * HH + h) * DD + d) * DD + e0);
    atomicAdd(kvp + 0, a0);
    atomicAdd(kvp + 1, a1);
    atomicAdd(kvp + 2, a2);
    atomicAdd(kvp + 3, a3);
    if (eq == 0) atomicAdd(Ks + (b * HH + h) * DD + d, accs);
}

__global__ void __launch_bounds__(256) self_att_kernel(
    const float* __restrict__ qkv, const float* __restrict__ KV,
    const float* __restrict__ Ks, float* __restrict__ Out)
{
    __shared__ float sKV[HH][DD][DD];
    __shared__ float sKs[HH][DD];
    __shared__ float sQf[CC];
    int tid = threadIdx.x;
    int t0 = blockIdx.x << 4;
    int b = t0 >> 12;
    for (int i = tid; i < HH * DD * DD; i += 256)
        (&sKV[0][0][0])[i] = KV[(size_t)b * HH * DD * DD + i];
    for (int i = tid; i < HH * DD; i += 256)
        (&sKs[0][0])[i] = Ks[b * HH * DD + i];
    __syncthreads();
    int h = tid >> 5, e = tid & 31;
    for (int tt = 0; tt < 16; ++tt) {
        int tok = t0 + tt;
        sQf[tid] = elu1(qkv[(size_t)tok * QS + tid]);
        __syncthreads();
        float den = sQf[(h << 5) + e] * sKs[h][e];
#pragma unroll
        for (int o = 16; o; o >>= 1) den += __shfl_xor_sync(0xffffffffu, den, o);
        float out = 0.f;
#pragma unroll
        for (int d = 0; d < 32; ++d)
            out += sQf[(h << 5) + d] * sKV[h][d][e];
        Out[(size_t)tok * CC + tid] = out / (den + 1e-6f);
        __syncthreads();
    }
}

/* ------------------------------------------------------------------ */
/* bilinear taps + invnorm + fused cross attention                     */
/* ------------------------------------------------------------------ */
__device__ __forceinline__ void taps_of(float kx, float ky, int base,
                                        int* r, float* w)
{
    float px = (((kx - 3.5f) / 507.5f * 2.f - 1.f) + 1.f) * 0.5f * 63.f;
    float py = (((ky - 3.5f) / 507.5f * 2.f - 1.f) + 1.f) * 0.5f * 63.f;
    float x0f = floorf(px), y0f = floorf(py);
    float wx = px - x0f, wy = py - y0f;
    int ix0 = min(max((int)x0f, 0), 63);
    int ix1 = min(max((int)x0f + 1, 0), 63);
    int iy0 = min(max((int)y0f, 0), 63);
    int iy1 = min(max((int)y0f + 1, 0), 63);
    r[0] = base + (iy0 << 6) + ix0;
    r[1] = base + (iy0 << 6) + ix1;
    r[2] = base + (iy1 << 6) + ix0;
    r[3] = base + (iy1 << 6) + ix1;
    w[0] = (1.f - wy) * (1.f - wx);
    w[1] = (1.f - wy) * wx;
    w[2] = wy * (1.f - wx);
    w[3] = wy * wx;
}

__global__ void __launch_bounds__(256) invnorm_kernel(
    const float* __restrict__ feat, const float* __restrict__ kp,
    float* __restrict__ invn)
{
    int p = (blockIdx.x << 3) + (threadIdx.x >> 5);
    int lane = threadIdx.x & 31;
    int b = p / (LL * KK);
    int r[4]; float w[4];
    taps_of(kp[(size_t)p * 2], kp[(size_t)p * 2 + 1], b * LL, r, w);
    const float* f0 = feat + (size_t)r[0] * CC;
    const float* f1 = feat + (size_t)r[1] * CC;
    const float* f2 = feat + (size_t)r[2] * CC;
    const float* f3 = feat + (size_t)r[3] * CC;
    float sq = 0.f;
#pragma unroll
    for (int j = 0; j < 8; ++j) {
        int c = lane + (j << 5);
        float val = w[0]*f0[c] + w[1]*f1[c] + w[2]*f2[c] + w[3]*f3[c];
        sq += val * val;
    }
#pragma unroll
    for (int o = 16; o; o >>= 1) sq += __shfl_xor_sync(0xffffffffu, sq, o);
    if (lane == 0) invn[p] = 1.f / (sqrtf(sq) + 1e-8f);
}

__global__ void __launch_bounds__(256) cross_att_kernel(
    const float* __restrict__ qkv_x, const float* __restrict__ qkv_src,
    const float* __restrict__ kp, const float* __restrict__ invn,
    maskp __restrict__ mask, float* __restrict__ Out)
{
    int t = blockIdx.x;
    int tid = threadIdx.x;
    int h = tid >> 5, lane = tid & 31;
    __shared__ float sQf[CC];
    __shared__ int   sTap[KK][4];
    __shared__ float sW[KK][4];
    __shared__ float sInv[KK];
    __shared__ float sM[KK];
    sQf[tid] = elu1(qkv_x[(size_t)t * QS + tid]);
    if (tid < KK) {
        int p = t * KK + tid;
        int b = t >> 12;
        int r[4]; float w[4];
        taps_of(kp[(size_t)p * 2], kp[(size_t)p * 2 + 1], b * LL, r, w);
#pragma unroll
        for (int i = 0; i < 4; ++i) { sTap[tid][i] = r[i]; sW[tid][i] = w[i]; }
        sInv[tid] = invn[p];
        sM[tid] = mask[p] ? 1.f : 0.f;
    }
    __syncthreads();
    int c = (h << 5) + lane;
    float qf = sQf[c];
    float wgt[KK];
    float den = 0.f;
#pragma unroll
    for (int s = 0; s < KK; ++s) {
        float kraw =
            sW[s][0] * qkv_src[(size_t)sTap[s][0] * QS + 256 + c] +
            sW[s][1] * qkv_src[(size_t)sTap[s][1] * QS + 256 + c] +
            sW[s][2] * qkv_src[(size_t)sTap[s][2] * QS + 256 + c] +
            sW[s][3] * qkv_src[(size_t)sTap[s][3] * QS + 256 + c];
        float kf = elu1(kraw * sInv[s]) * sM[s];
        float p = qf * kf;
#pragma unroll
        for (int o = 16; o; o >>= 1) p += __shfl_xor_sync(0xffffffffu, p, o);
        wgt[s] = p;
        den += p;
    }
    float inv = 1.f / (den + 1e-6f);
    float out = 0.f;
#pragma unroll
    for (int s = 0; s < KK; ++s) {
        float vraw =
            sW[s][0] * qkv_src[(size_t)sTap[s][0] * QS + 512 + c] +
            sW[s][1] * qkv_src[(size_t)sTap[s][1] * QS + 512 + c] +
            sW[s][2] * qkv_src[(size_t)sTap[s][2] * QS + 512 + c] +
            sW[s][3] * qkv_src[(size_t)sTap[s][3] * QS + 512 + c];
        out += wgt[s] * (vraw * sInv[s]);
    }
    Out[(size_t)t * CC + tid] = out * inv;
}

/* LayerNorm over C=256 (eps 1e-5); add!=0: Out += ln else Out = ln    */
__global__ void __launch_bounds__(256) ln_kernel(
    const float* __restrict__ X, const float* __restrict__ gam,
    const float* __restrict__ bet, float* __restrict__ Out, int add)
{
    int warp = threadIdx.x >> 5, lane = threadIdx.x & 31;
    int row = (blockIdx.x << 3) + warp;
    const float* xr = X + (size_t)row * CC;
    float v[8];
    float s = 0.f;
#pragma unroll
    for (int j = 0; j < 8; ++j) { v[j] = xr[lane + (j << 5)]; s += v[j]; }
#pragma unroll
    for (int o = 16; o; o >>= 1) s += __shfl_xor_sync(0xffffffffu, s, o);
    float mean = s * (1.f / 256.f);
    float q = 0.f;
#pragma unroll
    for (int j = 0; j < 8; ++j) { float d = v[j] - mean; q += d * d; }
#pragma unroll
    for (int o = 16; o; o >>= 1) q += __shfl_xor_sync(0xffffffffu, q, o);
    float rstd = rsqrtf(q * (1.f / 256.f) + 1e-5f);
#pragma unroll
    for (int j = 0; j < 8; ++j) {
        int cc = lane + (j << 5);
        float o = (v[j] - mean) * rstd * gam[cc] + bet[cc];
        if (add) Out[(size_t)row * CC + cc] += o;
        else     Out[(size_t)row * CC + cc]  = o;
    }
}

/* ------------------------------------------------------------------ */
/* host orchestration                                                  */
/* ------------------------------------------------------------------ */
struct LayerW {
    const float *g1, *b1, *g2, *b2;
    __nv_bfloat16 *whM, *wlM, *wh1, *wl1, *wh2, *wl2;
};
struct Scratch { float *att, *t, *msg, *u, *kv, *ks; };

static void mlp_tail(float* x, const LayerW& w, const Scratch& s)
{
    hgemm_kernel<<<dim3(2,64), 256, DSMEM>>>(
        s.att, (const float*)0, w.whM, w.wlM, s.t, CC, CC, 0, 0);
    ln_kernel<<<MS / 8, 256>>>(s.t, w.g1, w.b1, s.msg, 0);
    hgemm_kernel<<<dim3(4,64), 256, DSMEM>>>(
        x, s.msg, w.wh1, w.wl1, s.u, C2, C2, 1, 1);
    hgemm_kernel<<<dim3(2,64), 256, DSMEM>>>(
        s.u, (const float*)0, w.wh2, w.wl2, s.t, CC, C2, 0, 0);
    ln_kernel<<<MS / 8, 256>>>(s.t, w.g2, w.b2, x, 1);
}

extern "C" void kernel_launch(void* const* d_in, const int* in_sizes, int n_in,
                              void* d_out, int out_size)
{
    (void)in_sizes; (void)n_in; (void)out_size;
    const float* feat0 = (const float*)d_in[0];
    const float* feat1 = (const float*)d_in[1];
    const float* kp0   = (const float*)d_in[2];
    const float* kp1   = (const float*)d_in[3];
    maskp ms0 = (maskp)d_in[4];
    maskp ms1 = (maskp)d_in[5];
    maskp mc0 = (maskp)d_in[6];
    maskp mc1 = (maskp)d_in[7];
    const float* Wq = (const float*)d_in[8];
    const float* Wk = (const float*)d_in[9];
    const float* Wv = (const float*)d_in[10];
    const float* Wm = (const float*)d_in[11];
    const float* W1 = (const float*)d_in[12];
    const float* W2 = (const float*)d_in[13];
    const float* G1 = (const float*)d_in[14];
    const float* B1 = (const float*)d_in[15];
    const float* G2 = (const float*)d_in[16];
    const float* B2 = (const float*)d_in[17];

    cudaFuncSetAttribute(hgemm_kernel,
                         cudaFuncAttributeMaxDynamicSharedMemorySize, DSMEM);

    float *px0, *px1, *pq0, *pq1, *pin0, *pin1;
    __nv_bfloat16 *whP, *wlP, *whM, *wlM, *wh1, *wl1, *wh2, *wl2;
    Scratch s;
    cudaGetSymbolAddress((void**)&px0, g_x0);
    cudaGetSymbolAddress((void**)&px1, g_x1);
    cudaGetSymbolAddress((void**)&pq0, g_qkv0);
    cudaGetSymbolAddress((void**)&pq1, g_qkv1);
    cudaGetSymbolAddress((void**)&pin0, g_invn0);
    cudaGetSymbolAddress((void**)&pin1, g_invn1);
    cudaGetSymbolAddress((void**)&s.att, g_attb);
    cudaGetSymbolAddress((void**)&s.t, g_tb);
    cudaGetSymbolAddress((void**)&s.msg, g_msgb);
    cudaGetSymbolAddress((void**)&s.u, g_ub);
    cudaGetSymbolAddress((void**)&s.kv, g_kvb);
    cudaGetSymbolAddress((void**)&s.ks, g_ksb);
    cudaGetSymbolAddress((void**)&whP, g_whP);
    cudaGetSymbolAddress((void**)&wlP, g_wlP);
    cudaGetSymbolAddress((void**)&whM, g_whM);
    cudaGetSymbolAddress((void**)&wlM, g_wlM);
    cudaGetSymbolAddress((void**)&wh1, g_wh1);
    cudaGetSymbolAddress((void**)&wl1, g_wl1);
    cudaGetSymbolAddress((void**)&wh2, g_wh2);
    cudaGetSymbolAddress((void**)&wl2, g_wl2);

    cudaMemcpyAsync(px0, feat0, (size_t)MS * CC * sizeof(float),
                    cudaMemcpyDeviceToDevice, 0);
    cudaMemcpyAsync(px1, feat1, (size_t)MS * CC * sizeof(float),
                    cudaMemcpyDeviceToDevice, 0);

    for (int i = 0; i < 4; ++i) {
        LayerW w;
        w.g1 = G1 + (size_t)i * CC;
        w.b1 = B1 + (size_t)i * CC;
        w.g2 = G2 + (size_t)i * CC;
        w.b2 = B2 + (size_t)i * CC;
        w.whM = whM; w.wlM = wlM;
        w.wh1 = wh1; w.wl1 = wl1;
        w.wh2 = wh2; w.wl2 = wl2;

        /* weight prep (tiny) */
        wpackT_kernel<<<CC * QS / 256, 256>>>(
            Wq + (size_t)i * CC * CC, Wk + (size_t)i * CC * CC,
            Wv + (size_t)i * CC * CC, whP, wlP);
        wtrans_kernel<<<CC * CC / 256, 256>>>(Wm + (size_t)i * CC * CC,
                                              whM, wlM, CC, CC);
        wtrans_kernel<<<C2 * C2 / 256, 256>>>(W1 + (size_t)i * C2 * C2,
                                              wh1, wl1, C2, C2);
        wtrans_kernel<<<C2 * CC / 256, 256>>>(W2 + (size_t)i * C2 * CC,
                                              wh2, wl2, C2, CC);

        /* packed q|k|v projection for both features */
        hgemm_kernel<<<dim3(6,64), 256, DSMEM>>>(
            px0, (const float*)0, whP, wlP, pq0, QS, CC, 0, 0);
        hgemm_kernel<<<dim3(6,64), 256, DSMEM>>>(
            px1, (const float*)0, whP, wlP, pq1, QS, CC, 0, 0);

        if ((i & 1) == 0) {
            cudaMemsetAsync(s.kv, 0, (size_t)BB*HH*DD*DD*sizeof(float), 0);
            cudaMemsetAsync(s.ks, 0, (size_t)BB*HH*DD*sizeof(float), 0);
            self_kv_kernel<<<BB * HH * 16, 256>>>(pq0, ms0, s.kv, s.ks);
            self_att_kernel<<<MS / 16, 256>>>(pq0, s.kv, s.ks, s.att);
            mlp_tail(px0, w, s);
            cudaMemsetAsync(s.kv, 0, (size_t)BB*HH*DD*DD*sizeof(float), 0);
            cudaMemsetAsync(s.ks, 0, (size_t)BB*HH*DD*sizeof(float), 0);
            self_kv_kernel<<<BB * HH * 16, 256>>>(pq1, ms1, s.kv, s.ks);
            self_att_kernel<<<MS / 16, 256>>>(pq1, s.kv, s.ks, s.att);
            mlp_tail(px1, w, s);
        } else {
            invnorm_kernel<<<MD / 8, 256>>>(px0, kp0, pin0);
            invnorm_kernel<<<MD / 8, 256>>>(px1, kp1, pin1);
            cross_att_kernel<<<MS, 256>>>(pq0, pq1, kp1, pin1, mc1, s.att);
            mlp_tail(px0, w, s);
            cross_att_kernel<<<MS, 256>>>(pq1, pq0, kp0, pin0, mc0, s.att);
            mlp_tail(px1, w, s);
        }
    }

    cudaMemcpyAsync(d_out, px0, (size_t)MS * CC * sizeof(float),
                    cudaMemcpyDeviceToDevice, 0);
    cudaMemcpyAsync((float*)d_out + (size_t)MS * CC, px1,
                    (size_t)MS * CC * sizeof(float),
                    cudaMemcpyDeviceToDevice, 0);
}

// round 8
// speedup vs baseline: 2.0791x; 1.0506x over previous
#include <cuda_runtime.h>
#include <cuda_bf16.h>
#include <cstdint>
#include <math.h>

#define BB 2
#define LL 4096
#define CC 256
#define C2 512
#define QS 768
#define HH 8
#define DD 32
#define KK 9
#define NL 4
#define MS (BB*LL)
#define MD (BB*LL*KK)

typedef __nv_bfloat16 bf16;
typedef const unsigned int* maskp;

/* ------------------------------------------------------------------ */
/* device globals                                                      */
/* ------------------------------------------------------------------ */
__device__ float g_x0[MS*CC];
__device__ float g_x1[MS*CC];
__device__ bf16  g_xh0[MS*CC], g_xl0[MS*CC];
__device__ bf16  g_xh1[MS*CC], g_xl1[MS*CC];
__device__ float g_qkv0[MS*QS];
__device__ float g_qkv1[MS*QS];
__device__ float g_invn0[MD];
__device__ float g_invn1[MD];
__device__ bf16  g_atth[MS*CC], g_attl[MS*CC];
__device__ bf16  g_msgh[MS*CC], g_msgl[MS*CC];
__device__ bf16  g_uh[MS*C2],  g_ul[MS*C2];
__device__ float g_tb[MS*CC];
__device__ float g_kvb[BB*HH*DD*DD];
__device__ float g_ksb[BB*HH*DD];
/* per-layer pre-split transposed weights [N,K] bf16 hi/lo */
__device__ bf16 g_whP[NL*QS*CC], g_wlP[NL*QS*CC];
__device__ bf16 g_whM[NL*CC*CC], g_wlM[NL*CC*CC];
__device__ bf16 g_wh1[NL*C2*C2], g_wl1[NL*C2*C2];
__device__ bf16 g_wh2[NL*CC*C2], g_wl2[NL*CC*C2];

__device__ __forceinline__ float elu1(float x) { return x > 0.f ? x + 1.f : expf(x); }

__device__ __forceinline__ uint32_t smem_u32(const void* p) {
    uint32_t a;
    asm("{ .reg .u64 t; cvta.to.shared.u64 t, %1; cvt.u32.u64 %0, t; }"
        : "=r"(a) : "l"(p));
    return a;
}
__device__ __forceinline__ void cp16(uint32_t dst, const void* src) {
    asm volatile(
        "{ .reg .u64 g; cvta.to.global.u64 g, %1; "
        "cp.async.cg.shared.global [%0], [g], 16; }"
        :: "r"(dst), "l"(src));
}
#define CP_COMMIT() asm volatile("cp.async.commit_group;")
#define CP_WAIT(n)  asm volatile("cp.async.wait_group %0;" :: "n"(n))

__device__ __forceinline__ void ldsm4(uint32_t* r, uint32_t a) {
    asm volatile("ldmatrix.sync.aligned.m8n8.x4.shared.b16 {%0,%1,%2,%3}, [%4];"
                 : "=r"(r[0]), "=r"(r[1]), "=r"(r[2]), "=r"(r[3]) : "r"(a));
}
__device__ __forceinline__ void ldsm2(uint32_t* r, uint32_t a) {
    asm volatile("ldmatrix.sync.aligned.m8n8.x2.shared.b16 {%0,%1}, [%2];"
                 : "=r"(r[0]), "=r"(r[1]) : "r"(a));
}
__device__ __forceinline__ void mma16816(float* c, const uint32_t* a,
                                         const uint32_t* b) {
    asm volatile(
        "mma.sync.aligned.m16n8k16.row.col.f32.bf16.bf16.f32 "
        "{%0,%1,%2,%3}, {%4,%5,%6,%7}, {%8,%9}, {%0,%1,%2,%3};"
        : "+f"(c[0]), "+f"(c[1]), "+f"(c[2]), "+f"(c[3])
        : "r"(a[0]), "r"(a[1]), "r"(a[2]), "r"(a[3]), "r"(b[0]), "r"(b[1]));
}
__device__ __forceinline__ void bsplit1(float v, bf16& h, bf16& l) {
    h = __float2bfloat16(v);
    l = __float2bfloat16(v - __bfloat162float(h));
}

/* ------------------------------------------------------------------ */
/* HMMA GEMM v2: pre-split bf16 A+B, cp.async double buffer, ldmatrix  */
/* CTA 128x128, warp 64x32 (2x4), k-chunk 32, TSTR=40 (conflict-free)  */
/* mode bit0: split A (A2 pair for k>=256); bit1: tanh + bf16 out      */
/* ------------------------------------------------------------------ */
#define TSTR 40
#define TILE_B (128*TSTR*2)           /* 10240 bytes per tile */
#define OFFB_AH 0
#define OFFB_AL (1*TILE_B)
#define OFFB_BH (2*TILE_B)
#define OFFB_BL (3*TILE_B)
#define STAGE_B (4*TILE_B)            /* 40960 */
#define DSMEM   (2*STAGE_B)           /* 81920 */

__global__ void __launch_bounds__(256)
hgemm2_kernel(const bf16* __restrict__ Ah1, const bf16* __restrict__ Al1,
              const bf16* __restrict__ Ah2, const bf16* __restrict__ Al2,
              const bf16* __restrict__ Wh, const bf16* __restrict__ Wl,
              float* __restrict__ Cf, bf16* __restrict__ Ch,
              bf16* __restrict__ Cl, int N, int Kd, int mode)
{
    extern __shared__ __align__(16) char smh[];
    uint32_t smbase = smem_u32(smh);
    int tid = threadIdx.x, wid = tid >> 5, lane = tid & 31;
    int g = lane >> 2, q = lane & 3;
    int m0 = blockIdx.y << 7, n0 = blockIdx.x << 7;
    int wm = wid >> 2, wn = wid & 3;
    int arow = wm << 6, brow = wn << 5;

    /* ldmatrix per-thread offsets */
    int lr = lane & 7, sel = lane >> 3;
    uint32_t aoff = (uint32_t)(((arow + lr + (sel & 1) * 8) * TSTR
                                + (sel >> 1) * 8) * 2);
    uint32_t boff = (uint32_t)(((brow + lr) * TSTR + (sel & 1) * 8) * 2);

    float acc[4][4][4];
#pragma unroll
    for (int i = 0; i < 4; ++i)
#pragma unroll
        for (int j = 0; j < 4; ++j)
#pragma unroll
            for (int k = 0; k < 4; ++k) acc[i][j][k] = 0.f;

    const int NC = Kd >> 5;

    /* chunk issue lambda-ish macro */
#define ISSUE_CHUNK(CI) do {                                               \
        int k0_ = (CI) << 5;                                               \
        const bf16 *ah_, *al_; int lda_, kl_;                              \
        if (mode & 1) {                                                    \
            if (k0_ < 256) { ah_ = Ah1; al_ = Al1; kl_ = k0_; }            \
            else           { ah_ = Ah2; al_ = Al2; kl_ = k0_ - 256; }      \
            lda_ = 256;                                                    \
        } else { ah_ = Ah1; al_ = Al1; kl_ = k0_; lda_ = Kd; }             \
        uint32_t sb_ = smbase + ((CI) & 1) * STAGE_B;                      \
        _Pragma("unroll")                                                  \
        for (int i_ = 0; i_ < 2; ++i_) {                                   \
            int s_ = tid + (i_ << 8);                                      \
            int row_ = s_ >> 2, part_ = s_ & 3;                            \
            uint32_t dr_ = (uint32_t)(row_ * (TSTR * 2) + part_ * 16);     \
            size_t sa_ = (size_t)(m0 + row_) * lda_ + kl_ + part_ * 8;     \
            cp16(sb_ + OFFB_AH + dr_, ah_ + sa_);                          \
            cp16(sb_ + OFFB_AL + dr_, al_ + sa_);                          \
            size_t sbsrc_ = (size_t)(n0 + row_) * Kd + k0_ + part_ * 8;    \
            cp16(sb_ + OFFB_BH + dr_, Wh + sbsrc_);                        \
            cp16(sb_ + OFFB_BL + dr_, Wl + sbsrc_);                        \
        }                                                                  \
        CP_COMMIT();                                                       \
    } while (0)

    ISSUE_CHUNK(0);

    for (int kt = 0; kt < NC; ++kt) {
        if (kt + 1 < NC) { ISSUE_CHUNK(kt + 1); CP_WAIT(1); }
        else             { CP_WAIT(0); }
        __syncthreads();
        uint32_t sb = smbase + (kt & 1) * STAGE_B;
#pragma unroll
        for (int ks = 0; ks < 32; ks += 16) {
            uint32_t aH[4][4], aL[4][4], bH[4][2], bL[4][2];
#pragma unroll
            for (int mf = 0; mf < 4; ++mf)
                ldsm4(aH[mf], sb + OFFB_AH + aoff + mf * (16 * TSTR * 2) + ks * 2);
#pragma unroll
            for (int nf = 0; nf < 4; ++nf)
                ldsm2(bH[nf], sb + OFFB_BH + boff + nf * (8 * TSTR * 2) + ks * 2);
#pragma unroll
            for (int mf = 0; mf < 4; ++mf)
#pragma unroll
                for (int nf = 0; nf < 4; ++nf)
                    mma16816(acc[mf][nf], aH[mf], bH[nf]);
#pragma unroll
            for (int nf = 0; nf < 4; ++nf)
                ldsm2(bL[nf], sb + OFFB_BL + boff + nf * (8 * TSTR * 2) + ks * 2);
#pragma unroll
            for (int mf = 0; mf < 4; ++mf)
#pragma unroll
                for (int nf = 0; nf < 4; ++nf)
                    mma16816(acc[mf][nf], aH[mf], bL[nf]);
#pragma unroll
            for (int mf = 0; mf < 4; ++mf)
                ldsm4(aL[mf], sb + OFFB_AL + aoff + mf * (16 * TSTR * 2) + ks * 2);
#pragma unroll
            for (int mf = 0; mf < 4; ++mf)
#pragma unroll
                for (int nf = 0; nf < 4; ++nf)
                    mma16816(acc[mf][nf], aL[mf], bH[nf]);
        }
        __syncthreads();
    }
#undef ISSUE_CHUNK

    /* epilogue */
#pragma unroll
    for (int mf = 0; mf < 4; ++mf) {
#pragma unroll
        for (int nf = 0; nf < 4; ++nf) {
            int r = m0 + arow + (mf << 4) + g;
            int c = n0 + brow + (nf << 3) + (q << 1);
            if (mode & 2) {
                float t0 = tanhf(acc[mf][nf][0]), t1 = tanhf(acc[mf][nf][1]);
                float t2 = tanhf(acc[mf][nf][2]), t3 = tanhf(acc[mf][nf][3]);
                bf16 h0, l0, h1, l1;
                bsplit1(t0, h0, l0); bsplit1(t1, h1, l1);
                *(uint32_t*)(Ch + (size_t)r * N + c) =
                    (uint32_t)__bfloat16_as_ushort(h0) |
                    ((uint32_t)__bfloat16_as_ushort(h1) << 16);
                *(uint32_t*)(Cl + (size_t)r * N + c) =
                    (uint32_t)__bfloat16_as_ushort(l0) |
                    ((uint32_t)__bfloat16_as_ushort(l1) << 16);
                bsplit1(t2, h0, l0); bsplit1(t3, h1, l1);
                *(uint32_t*)(Ch + (size_t)(r + 8) * N + c) =
                    (uint32_t)__bfloat16_as_ushort(h0) |
                    ((uint32_t)__bfloat16_as_ushort(h1) << 16);
                *(uint32_t*)(Cl + (size_t)(r + 8) * N + c) =
                    (uint32_t)__bfloat16_as_ushort(l0) |
                    ((uint32_t)__bfloat16_as_ushort(l1) << 16);
            } else {
                float2 v0, v1;
                v0.x = acc[mf][nf][0]; v0.y = acc[mf][nf][1];
                v1.x = acc[mf][nf][2]; v1.y = acc[mf][nf][3];
                *(float2*)(Cf + (size_t)r * N + c) = v0;
                *(float2*)(Cf + (size_t)(r + 8) * N + c) = v1;
            }
        }
    }
}

/* ------------------------------------------------------------------ */
/* weight prep (all 4 layers per launch)                               */
/* ------------------------------------------------------------------ */
__global__ void wtrans_all_kernel(const float* __restrict__ W,
                                  bf16* __restrict__ wh, bf16* __restrict__ wl,
                                  int Kd, int N)
{
    int idx = blockIdx.x * 256 + threadIdx.x;   /* NL*Kd*N */
    int per = Kd * N;
    int layer = idx / per, r = idx - layer * per;
    int k = r / N, n = r - k * N;
    float v = W[(size_t)layer * per + (size_t)k * N + n];
    bf16 h, l; bsplit1(v, h, l);
    size_t dst = (size_t)layer * per + (size_t)n * Kd + k;
    wh[dst] = h; wl[dst] = l;
}

__global__ void wpackT_all_kernel(const float* __restrict__ Wq,
                                  const float* __restrict__ Wk,
                                  const float* __restrict__ Wv,
                                  bf16* __restrict__ wh, bf16* __restrict__ wl)
{
    int idx = blockIdx.x * 256 + threadIdx.x;   /* NL*CC*QS */
    int per = CC * QS;
    int layer = idx / per, r = idx - layer * per;
    int k = r / QS, n = r - k * QS;
    const float* src = (n < 256) ? Wq : (n < 512) ? Wk : Wv;
    float v = src[(size_t)layer * CC * CC + (size_t)k * 256 + (n & 255)];
    bf16 h, l; bsplit1(v, h, l);
    size_t dst = (size_t)layer * (QS * CC) + (size_t)n * CC + k;
    wh[dst] = h; wl[dst] = l;
}

/* initial x copy + split */
__global__ void split_in_kernel(const float* __restrict__ f,
                                float* __restrict__ x,
                                bf16* __restrict__ xh, bf16* __restrict__ xl)
{
    int i = blockIdx.x * 256 + threadIdx.x;
    float v = f[i];
    x[i] = v;
    bf16 h, l; bsplit1(v, h, l);
    xh[i] = h; xl[i] = l;
}

/* ------------------------------------------------------------------ */
/* Self linear attention                                               */
/* ------------------------------------------------------------------ */
__global__ void __launch_bounds__(256) self_kv_kernel(
    const float* __restrict__ qkv, maskp __restrict__ mask,
    float* __restrict__ KV, float* __restrict__ Ks)
{
    int blk = blockIdx.x;
    int ch = blk & 15, h = (blk >> 4) & 7, b = blk >> 7;
    int tid = threadIdx.x;
    int d = tid >> 3, eq = tid & 7, e0 = eq << 2;
    float a0 = 0.f, a1 = 0.f, a2 = 0.f, a3 = 0.f, accs = 0.f;
    int base = b * LL + (ch << 8);
    const float* kp = qkv + (size_t)base * QS + 256 + h * DD + d;
    const float* vp = qkv + (size_t)base * QS + 512 + h * DD + e0;
    const unsigned int* mp = mask + base;
#pragma unroll 4
    for (int r = 0; r < 256; ++r) {
        float m = mp[r] ? 1.f : 0.f;
        float kf = m * elu1(kp[(size_t)r * QS]);
        float4 v = *(const float4*)(vp + (size_t)r * QS);
        a0 += kf * v.x; a1 += kf * v.y; a2 += kf * v.z; a3 += kf * v.w;
        accs += kf;
    }
    float* kvp = KV + ((size_t)((b * HH + h) * DD + d) * DD + e0);
    atomicAdd(kvp + 0, a0);
    atomicAdd(kvp + 1, a1);
    atomicAdd(kvp + 2, a2);
    atomicAdd(kvp + 3, a3);
    if (eq == 0) atomicAdd(Ks + (b * HH + h) * DD + d, accs);
}

__global__ void __launch_bounds__(256) self_att_kernel(
    const float* __restrict__ qkv, const float* __restrict__ KV,
    const float* __restrict__ Ks, bf16* __restrict__ oh,
    bf16* __restrict__ ol)
{
    __shared__ float sKV[HH][DD][DD];
    __shared__ float sKs[HH][DD];
    __shared__ float sQf[8][CC];
    int tid = threadIdx.x;
    int t0 = blockIdx.x << 3;
    int b = t0 >> 12;
    for (int i = tid; i < HH * DD * DD; i += 256)
        (&sKV[0][0][0])[i] = KV[(size_t)b * HH * DD * DD + i];
    for (int i = tid; i < HH * DD; i += 256)
        (&sKs[0][0])[i] = Ks[b * HH * DD + i];
#pragma unroll
    for (int tt = 0; tt < 8; ++tt)
        sQf[tt][tid] = elu1(qkv[(size_t)(t0 + tt) * QS + tid]);
    __syncthreads();
    int h = tid >> 5, e = tid & 31;
#pragma unroll
    for (int tt = 0; tt < 8; ++tt) {
        float den = sQf[tt][(h << 5) + e] * sKs[h][e];
#pragma unroll
        for (int o = 16; o; o >>= 1) den += __shfl_xor_sync(0xffffffffu, den, o);
        float out = 0.f;
#pragma unroll
        for (int d = 0; d < 32; ++d)
            out += sQf[tt][(h << 5) + d] * sKV[h][d][e];
        float o = out / (den + 1e-6f);
        bf16 hh, lo; bsplit1(o, hh, lo);
        oh[(size_t)(t0 + tt) * CC + tid] = hh;
        ol[(size_t)(t0 + tt) * CC + tid] = lo;
    }
}

/* ------------------------------------------------------------------ */
/* bilinear taps + invnorm + fused cross attention                     */
/* ------------------------------------------------------------------ */
__device__ __forceinline__ void taps_of(float kx, float ky, int base,
                                        int* r, float* w)
{
    float px = (((kx - 3.5f) / 507.5f * 2.f - 1.f) + 1.f) * 0.5f * 63.f;
    float py = (((ky - 3.5f) / 507.5f * 2.f - 1.f) + 1.f) * 0.5f * 63.f;
    float x0f = floorf(px), y0f = floorf(py);
    float wx = px - x0f, wy = py - y0f;
    int ix0 = min(max((int)x0f, 0), 63);
    int ix1 = min(max((int)x0f + 1, 0), 63);
    int iy0 = min(max((int)y0f, 0), 63);
    int iy1 = min(max((int)y0f + 1, 0), 63);
    r[0] = base + (iy0 << 6) + ix0;
    r[1] = base + (iy0 << 6) + ix1;
    r[2] = base + (iy1 << 6) + ix0;
    r[3] = base + (iy1 << 6) + ix1;
    w[0] = (1.f - wy) * (1.f - wx);
    w[1] = (1.f - wy) * wx;
    w[2] = wy * (1.f - wx);
    w[3] = wy * wx;
}

__global__ void __launch_bounds__(256) invnorm_kernel(
    const float* __restrict__ feat, const float* __restrict__ kp,
    float* __restrict__ invn)
{
    int p = (blockIdx.x << 3) + (threadIdx.x >> 5);
    int lane = threadIdx.x & 31;
    int b = p / (LL * KK);
    int r[4]; float w[4];
    taps_of(kp[(size_t)p * 2], kp[(size_t)p * 2 + 1], b * LL, r, w);
    const float* f0 = feat + (size_t)r[0] * CC;
    const float* f1 = feat + (size_t)r[1] * CC;
    const float* f2 = feat + (size_t)r[2] * CC;
    const float* f3 = feat + (size_t)r[3] * CC;
    float sq = 0.f;
#pragma unroll
    for (int j = 0; j < 8; ++j) {
        int c = lane + (j << 5);
        float val = w[0]*f0[c] + w[1]*f1[c] + w[2]*f2[c] + w[3]*f3[c];
        sq += val * val;
    }
#pragma unroll
    for (int o = 16; o; o >>= 1) sq += __shfl_xor_sync(0xffffffffu, sq, o);
    if (lane == 0) invn[p] = 1.f / (sqrtf(sq) + 1e-8f);
}

__global__ void __launch_bounds__(256) cross_att_kernel(
    const float* __restrict__ qkv_x, const float* __restrict__ qkv_src,
    const float* __restrict__ kp, const float* __restrict__ invn,
    maskp __restrict__ mask, bf16* __restrict__ oh, bf16* __restrict__ ol)
{
    int t = blockIdx.x;
    int tid = threadIdx.x;
    int h = tid >> 5, lane = tid & 31;
    __shared__ float sQf[CC];
    __shared__ int   sTap[KK][4];
    __shared__ float sW[KK][4];
    __shared__ float sInv[KK];
    __shared__ float sM[KK];
    sQf[tid] = elu1(qkv_x[(size_t)t * QS + tid]);
    if (tid < KK) {
        int p = t * KK + tid;
        int b = t >> 12;
        int r[4]; float w[4];
        taps_of(kp[(size_t)p * 2], kp[(size_t)p * 2 + 1], b * LL, r, w);
#pragma unroll
        for (int i = 0; i < 4; ++i) { sTap[tid][i] = r[i]; sW[tid][i] = w[i]; }
        sInv[tid] = invn[p];
        sM[tid] = mask[p] ? 1.f : 0.f;
    }
    __syncthreads();
    int c = (h << 5) + lane;
    float qf = sQf[c];
    float wgt[KK];
    float den = 0.f;
#pragma unroll
    for (int s = 0; s < KK; ++s) {
        float kraw =
            sW[s][0] * qkv_src[(size_t)sTap[s][0] * QS + 256 + c] +
            sW[s][1] * qkv_src[(size_t)sTap[s][1] * QS + 256 + c] +
            sW[s][2] * qkv_src[(size_t)sTap[s][2] * QS + 256 + c] +
            sW[s][3] * qkv_src[(size_t)sTap[s][3] * QS + 256 + c];
        float kf = elu1(kraw * sInv[s]) * sM[s];
        float p = qf * kf;
#pragma unroll
        for (int o = 16; o; o >>= 1) p += __shfl_xor_sync(0xffffffffu, p, o);
        wgt[s] = p;
        den += p;
    }
    float inv = 1.f / (den + 1e-6f);
    float out = 0.f;
#pragma unroll
    for (int s = 0; s < KK; ++s) {
        float vraw =
            sW[s][0] * qkv_src[(size_t)sTap[s][0] * QS + 512 + c] +
            sW[s][1] * qkv_src[(size_t)sTap[s][1] * QS + 512 + c] +
            sW[s][2] * qkv_src[(size_t)sTap[s][2] * QS + 512 + c] +
            sW[s][3] * qkv_src[(size_t)sTap[s][3] * QS + 512 + c];
        out += wgt[s] * (vraw * sInv[s]);
    }
    float o = out * inv;
    bf16 hh, lo; bsplit1(o, hh, lo);
    oh[(size_t)t * CC + tid] = hh;
    ol[(size_t)t * CC + tid] = lo;
}

/* ------------------------------------------------------------------ */
/* LayerNorm (C=256, eps 1e-5) — split-out and residual-add variants   */
/* ------------------------------------------------------------------ */
__device__ __forceinline__ void ln_core(const float* xr, float* v,
                                        float& mean, float& rstd)
{
    int lane = threadIdx.x & 31;
    float s = 0.f;
#pragma unroll
    for (int j = 0; j < 8; ++j) { v[j] = xr[lane + (j << 5)]; s += v[j]; }
#pragma unroll
    for (int o = 16; o; o >>= 1) s += __shfl_xor_sync(0xffffffffu, s, o);
    mean = s * (1.f / 256.f);
    float q = 0.f;
#pragma unroll
    for (int j = 0; j < 8; ++j) { float d = v[j] - mean; q += d * d; }
#pragma unroll
    for (int o = 16; o; o >>= 1) q += __shfl_xor_sync(0xffffffffu, q, o);
    rstd = rsqrtf(q * (1.f / 256.f) + 1e-5f);
}

__global__ void __launch_bounds__(256) ln_split_kernel(
    const float* __restrict__ X, const float* __restrict__ gam,
    const float* __restrict__ bet, bf16* __restrict__ oh,
    bf16* __restrict__ ol)
{
    int warp = threadIdx.x >> 5, lane = threadIdx.x & 31;
    int row = (blockIdx.x << 3) + warp;
    float v[8], mean, rstd;
    ln_core(X + (size_t)row * CC, v, mean, rstd);
#pragma unroll
    for (int j = 0; j < 8; ++j) {
        int c = lane + (j << 5);
        float o = (v[j] - mean) * rstd * gam[c] + bet[c];
        bf16 h, l; bsplit1(o, h, l);
        oh[(size_t)row * CC + c] = h;
        ol[(size_t)row * CC + c] = l;
    }
}

__global__ void __launch_bounds__(256) ln_add_kernel(
    const float* __restrict__ X, const float* __restrict__ gam,
    const float* __restrict__ bet, float* __restrict__ x,
    bf16* __restrict__ xh, bf16* __restrict__ xl)
{
    int warp = threadIdx.x >> 5, lane = threadIdx.x & 31;
    int row = (blockIdx.x << 3) + warp;
    float v[8], mean, rstd;
    ln_core(X + (size_t)row * CC, v, mean, rstd);
#pragma unroll
    for (int j = 0; j < 8; ++j) {
        int c = lane + (j << 5);
        float o = (v[j] - mean) * rstd * gam[c] + bet[c];
        float nx = x[(size_t)row * CC + c] + o;
        x[(size_t)row * CC + c] = nx;
        bf16 h, l; bsplit1(nx, h, l);
        xh[(size_t)row * CC + c] = h;
        xl[(size_t)row * CC + c] = l;
    }
}

/* ------------------------------------------------------------------ */
/* host orchestration                                                  */
/* ------------------------------------------------------------------ */
struct LayerW {
    const float *g1, *b1, *g2, *b2;
    bf16 *whP, *wlP, *whM, *wlM, *wh1, *wl1, *wh2, *wl2;
};
struct Bufs {
    float *t, *kv, *ks;
    bf16 *atth, *attl, *msgh, *msgl, *uh, *ul;
};

static void mlp_tail(float* x, bf16* xh, bf16* xl, const LayerW& w,
                     const Bufs& s)
{
    hgemm2_kernel<<<dim3(2,64), 256, DSMEM>>>(
        s.atth, s.attl, (const bf16*)0, (const bf16*)0,
        w.whM, w.wlM, s.t, (bf16*)0, (bf16*)0, CC, CC, 0);
    ln_split_kernel<<<MS/8, 256>>>(s.t, w.g1, w.b1, s.msgh, s.msgl);
    hgemm2_kernel<<<dim3(4,64), 256, DSMEM>>>(
        xh, xl, s.msgh, s.msgl, w.wh1, w.wl1,
        (float*)0, s.uh, s.ul, C2, C2, 3);
    hgemm2_kernel<<<dim3(2,64), 256, DSMEM>>>(
        s.uh, s.ul, (const bf16*)0, (const bf16*)0,
        w.wh2, w.wl2, s.t, (bf16*)0, (bf16*)0, CC, C2, 0);
    ln_add_kernel<<<MS/8, 256>>>(s.t, w.g2, w.b2, x, xh, xl);
}

extern "C" void kernel_launch(void* const* d_in, const int* in_sizes, int n_in,
                              void* d_out, int out_size)
{
    (void)in_sizes; (void)n_in; (void)out_size;
    const float* feat0 = (const float*)d_in[0];
    const float* feat1 = (const float*)d_in[1];
    const float* kp0   = (const float*)d_in[2];
    const float* kp1   = (const float*)d_in[3];
    maskp ms0 = (maskp)d_in[4];
    maskp ms1 = (maskp)d_in[5];
    maskp mc0 = (maskp)d_in[6];
    maskp mc1 = (maskp)d_in[7];
    const float* Wq = (const float*)d_in[8];
    const float* Wk = (const float*)d_in[9];
    const float* Wv = (const float*)d_in[10];
    const float* Wm = (const float*)d_in[11];
    const float* W1 = (const float*)d_in[12];
    const float* W2 = (const float*)d_in[13];
    const float* G1 = (const float*)d_in[14];
    const float* B1 = (const float*)d_in[15];
    const float* G2 = (const float*)d_in[16];
    const float* B2 = (const float*)d_in[17];

    cudaFuncSetAttribute(hgemm2_kernel,
                         cudaFuncAttributeMaxDynamicSharedMemorySize, DSMEM);

    float *px0, *px1, *pq0, *pq1, *pin0, *pin1;
    bf16 *pxh0, *pxl0, *pxh1, *pxl1;
    bf16 *whP, *wlP, *whM, *wlM, *wh1, *wl1, *wh2, *wl2;
    Bufs s;
    cudaGetSymbolAddress((void**)&px0, g_x0);
    cudaGetSymbolAddress((void**)&px1, g_x1);
    cudaGetSymbolAddress((void**)&pxh0, g_xh0);
    cudaGetSymbolAddress((void**)&pxl0, g_xl0);
    cudaGetSymbolAddress((void**)&pxh1, g_xh1);
    cudaGetSymbolAddress((void**)&pxl1, g_xl1);
    cudaGetSymbolAddress((void**)&pq0, g_qkv0);
    cudaGetSymbolAddress((void**)&pq1, g_qkv1);
    cudaGetSymbolAddress((void**)&pin0, g_invn0);
    cudaGetSymbolAddress((void**)&pin1, g_invn1);
    cudaGetSymbolAddress((void**)&s.t, g_tb);
    cudaGetSymbolAddress((void**)&s.kv, g_kvb);
    cudaGetSymbolAddress((void**)&s.ks, g_ksb);
    cudaGetSymbolAddress((void**)&s.atth, g_atth);
    cudaGetSymbolAddress((void**)&s.attl, g_attl);
    cudaGetSymbolAddress((void**)&s.msgh, g_msgh);
    cudaGetSymbolAddress((void**)&s.msgl, g_msgl);
    cudaGetSymbolAddress((void**)&s.uh, g_uh);
    cudaGetSymbolAddress((void**)&s.ul, g_ul);
    cudaGetSymbolAddress((void**)&whP, g_whP);
    cudaGetSymbolAddress((void**)&wlP, g_wlP);
    cudaGetSymbolAddress((void**)&whM, g_whM);
    cudaGetSymbolAddress((void**)&wlM, g_wlM);
    cudaGetSymbolAddress((void**)&wh1, g_wh1);
    cudaGetSymbolAddress((void**)&wl1, g_wl1);
    cudaGetSymbolAddress((void**)&wh2, g_wh2);
    cudaGetSymbolAddress((void**)&wl2, g_wl2);

    /* front-loaded weight prep (all layers) + input split */
    wpackT_all_kernel<<<NL*CC*QS/256, 256>>>(Wq, Wk, Wv, whP, wlP);
    wtrans_all_kernel<<<NL*CC*CC/256, 256>>>(Wm, whM, wlM, CC, CC);
    wtrans_all_kernel<<<NL*C2*C2/256, 256>>>(W1, wh1, wl1, C2, C2);
    wtrans_all_kernel<<<NL*C2*CC/256, 256>>>(W2, wh2, wl2, C2, CC);
    split_in_kernel<<<MS*CC/256, 256>>>(feat0, px0, pxh0, pxl0);
    split_in_kernel<<<MS*CC/256, 256>>>(feat1, px1, pxh1, pxl1);

    for (int i = 0; i < 4; ++i) {
        LayerW w;
        w.g1 = G1 + (size_t)i * CC;
        w.b1 = B1 + (size_t)i * CC;
        w.g2 = G2 + (size_t)i * CC;
        w.b2 = B2 + (size_t)i * CC;
        w.whP = whP + (size_t)i * QS * CC; w.wlP = wlP + (size_t)i * QS * CC;
        w.whM = whM + (size_t)i * CC * CC; w.wlM = wlM + (size_t)i * CC * CC;
        w.wh1 = wh1 + (size_t)i * C2 * C2; w.wl1 = wl1 + (size_t)i * C2 * C2;
        w.wh2 = wh2 + (size_t)i * C2 * CC; w.wl2 = wl2 + (size_t)i * C2 * CC;

        /* packed q|k|v projection from pre-update features */
        hgemm2_kernel<<<dim3(6,64), 256, DSMEM>>>(
            pxh0, pxl0, (const bf16*)0, (const bf16*)0,
            w.whP, w.wlP, pq0, (bf16*)0, (bf16*)0, QS, CC, 0);
        hgemm2_kernel<<<dim3(6,64), 256, DSMEM>>>(
            pxh1, pxl1, (const bf16*)0, (const bf16*)0,
            w.whP, w.wlP, pq1, (bf16*)0, (bf16*)0, QS, CC, 0);

        if ((i & 1) == 0) {
            cudaMemsetAsync(s.kv, 0, (size_t)BB*HH*DD*DD*sizeof(float), 0);
            cudaMemsetAsync(s.ks, 0, (size_t)BB*HH*DD*sizeof(float), 0);
            self_kv_kernel<<<BB*HH*16, 256>>>(pq0, ms0, s.kv, s.ks);
            self_att_kernel<<<MS/8, 256>>>(pq0, s.kv, s.ks, s.atth, s.attl);
            mlp_tail(px0, pxh0, pxl0, w, s);
            cudaMemsetAsync(s.kv, 0, (size_t)BB*HH*DD*DD*sizeof(float), 0);
            cudaMemsetAsync(s.ks, 0, (size_t)BB*HH*DD*sizeof(float), 0);
            self_kv_kernel<<<BB*HH*16, 256>>>(pq1, ms1, s.kv, s.ks);
            self_att_kernel<<<MS/8, 256>>>(pq1, s.kv, s.ks, s.atth, s.attl);
            mlp_tail(px1, pxh1, pxl1, w, s);
        } else {
            invnorm_kernel<<<MD/8, 256>>>(px0, kp0, pin0);
            invnorm_kernel<<<MD/8, 256>>>(px1, kp1, pin1);
            cross_att_kernel<<<MS, 256>>>(pq0, pq1, kp1, pin1, mc1,
                                          s.atth, s.attl);
            mlp_tail(px0, pxh0, pxl0, w, s);
            cross_att_kernel<<<MS, 256>>>(pq1, pq0, kp0, pin0, mc0,
                                          s.atth, s.attl);
            mlp_tail(px1, pxh1, pxl1, w, s);
        }
    }

    cudaMemcpyAsync(d_out, px0, (size_t)MS * CC * sizeof(float),
                    cudaMemcpyDeviceToDevice, 0);
    cudaMemcpyAsync((float*)d_out + (size_t)MS * CC, px1,
                    (size_t)MS * CC * sizeof(float),
                    cudaMemcpyDeviceToDevice, 0);
}

// round 9
// speedup vs baseline: 2.9180x; 1.4035x over previous
#include <cuda_runtime.h>
#include <cuda_bf16.h>
#include <cstdint>
#include <math.h>

#define BB 2
#define LL 4096
#define CC 256
#define C2 512
#define QS 768
#define HH 8
#define DD 32
#define KK 9
#define NL 4
#define MS (BB*LL)          /* rows per feature   */
#define M2 (2*MS)           /* batched rows       */
#define MD (BB*LL*KK)       /* points per feature */

typedef __nv_bfloat16 bf16;
typedef const unsigned int* maskp;

/* ------------------------------------------------------------------ */
/* device globals — feat0 half then feat1 half, contiguous             */
/* ------------------------------------------------------------------ */
__device__ float g_x[M2*CC];
__device__ bf16  g_xh[M2*CC], g_xl[M2*CC];
__device__ float g_qkv[M2*QS];
__device__ float g_invn[2*MD];
__device__ bf16  g_atth[M2*CC], g_attl[M2*CC];
__device__ bf16  g_msgh[M2*CC], g_msgl[M2*CC];
__device__ bf16  g_uh[M2*C2],  g_ul[M2*C2];
__device__ float g_tb[M2*CC];
__device__ float g_kvb[4*HH*DD*DD];
__device__ float g_ksb[4*HH*DD];
__device__ bf16 g_whP[NL*QS*CC], g_wlP[NL*QS*CC];
__device__ bf16 g_whM[NL*CC*CC], g_wlM[NL*CC*CC];
__device__ bf16 g_wh1[NL*C2*C2], g_wl1[NL*C2*C2];
__device__ bf16 g_wh2[NL*CC*C2], g_wl2[NL*CC*C2];

__device__ __forceinline__ float elu1(float x) { return x > 0.f ? x + 1.f : expf(x); }

__device__ __forceinline__ uint32_t smem_u32(const void* p) {
    uint32_t a;
    asm("{ .reg .u64 t; cvta.to.shared.u64 t, %1; cvt.u32.u64 %0, t; }"
        : "=r"(a) : "l"(p));
    return a;
}
__device__ __forceinline__ void cp16(uint32_t dst, const void* src) {
    asm volatile(
        "{ .reg .u64 g; cvta.to.global.u64 g, %1; "
        "cp.async.cg.shared.global [%0], [g], 16; }"
        :: "r"(dst), "l"(src));
}
#define CP_COMMIT() asm volatile("cp.async.commit_group;")
#define CP_WAIT(n)  asm volatile("cp.async.wait_group %0;" :: "n"(n))

__device__ __forceinline__ void ldsm4(uint32_t* r, uint32_t a) {
    asm volatile("ldmatrix.sync.aligned.m8n8.x4.shared.b16 {%0,%1,%2,%3}, [%4];"
                 : "=r"(r[0]), "=r"(r[1]), "=r"(r[2]), "=r"(r[3]) : "r"(a));
}
__device__ __forceinline__ void ldsm2(uint32_t* r, uint32_t a) {
    asm volatile("ldmatrix.sync.aligned.m8n8.x2.shared.b16 {%0,%1}, [%2];"
                 : "=r"(r[0]), "=r"(r[1]) : "r"(a));
}
__device__ __forceinline__ void mma16816(float* c, const uint32_t* a,
                                         const uint32_t* b) {
    asm volatile(
        "mma.sync.aligned.m16n8k16.row.col.f32.bf16.bf16.f32 "
        "{%0,%1,%2,%3}, {%4,%5,%6,%7}, {%8,%9}, {%0,%1,%2,%3};"
        : "+f"(c[0]), "+f"(c[1]), "+f"(c[2]), "+f"(c[3])
        : "r"(a[0]), "r"(a[1]), "r"(a[2]), "r"(a[3]), "r"(b[0]), "r"(b[1]));
}
__device__ __forceinline__ void bsplit1(float v, bf16& h, bf16& l) {
    h = __float2bfloat16(v);
    l = __float2bfloat16(v - __bfloat162float(h));
}

/* ------------------------------------------------------------------ */
/* HMMA GEMM: pre-split bf16, cp.async dbl buffer, ldmatrix, TSTR=40   */
/* M from grid.y (rows 128*by), CTA 128x128, warp 64x32                */
/* mode bit0: K-split (k<256 from A pair, k>=256 from B pair, lda=256) */
/* mode bit1: tanh + bf16 hi/lo output                                 */
/* ------------------------------------------------------------------ */
#define TSTR 40
#define TILE_B (128*TSTR*2)
#define OFFB_AH 0
#define OFFB_AL (1*TILE_B)
#define OFFB_BH (2*TILE_B)
#define OFFB_BL (3*TILE_B)
#define STAGE_B (4*TILE_B)
#define DSMEM   (2*STAGE_B)

__global__ void __launch_bounds__(256)
hgemm2_kernel(const bf16* __restrict__ Ah1, const bf16* __restrict__ Al1,
              const bf16* __restrict__ Ah2, const bf16* __restrict__ Al2,
              const bf16* __restrict__ Wh, const bf16* __restrict__ Wl,
              float* __restrict__ Cf, bf16* __restrict__ Ch,
              bf16* __restrict__ Cl, int N, int Kd, int mode)
{
    extern __shared__ __align__(16) char smh[];
    uint32_t smbase = smem_u32(smh);
    int tid = threadIdx.x, wid = tid >> 5, lane = tid & 31;
    int g = lane >> 2, q = lane & 3;
    int m0 = blockIdx.y << 7, n0 = blockIdx.x << 7;
    int wm = wid >> 2, wn = wid & 3;
    int arow = wm << 6, brow = wn << 5;

    int lr = lane & 7, sel = lane >> 3;
    uint32_t aoff = (uint32_t)(((arow + lr + (sel & 1) * 8) * TSTR
                                + (sel >> 1) * 8) * 2);
    uint32_t boff = (uint32_t)(((brow + lr) * TSTR + (sel & 1) * 8) * 2);

    float acc[4][4][4];
#pragma unroll
    for (int i = 0; i < 4; ++i)
#pragma unroll
        for (int j = 0; j < 4; ++j)
#pragma unroll
            for (int k = 0; k < 4; ++k) acc[i][j][k] = 0.f;

    const int NC = Kd >> 5;

#define ISSUE_CHUNK(CI) do {                                               \
        int k0_ = (CI) << 5;                                               \
        const bf16 *ah_, *al_; int lda_, kl_;                              \
        if (mode & 1) {                                                    \
            if (k0_ < 256) { ah_ = Ah1; al_ = Al1; kl_ = k0_; }            \
            else           { ah_ = Ah2; al_ = Al2; kl_ = k0_ - 256; }      \
            lda_ = 256;                                                    \
        } else { ah_ = Ah1; al_ = Al1; kl_ = k0_; lda_ = Kd; }             \
        uint32_t sb_ = smbase + ((CI) & 1) * STAGE_B;                      \
        _Pragma("unroll")                                                  \
        for (int i_ = 0; i_ < 2; ++i_) {                                   \
            int s_ = tid + (i_ << 8);                                      \
            int row_ = s_ >> 2, part_ = s_ & 3;                            \
            uint32_t dr_ = (uint32_t)(row_ * (TSTR * 2) + part_ * 16);     \
            size_t sa_ = (size_t)(m0 + row_) * lda_ + kl_ + part_ * 8;     \
            cp16(sb_ + OFFB_AH + dr_, ah_ + sa_);                          \
            cp16(sb_ + OFFB_AL + dr_, al_ + sa_);                          \
            size_t sbsrc_ = (size_t)(n0 + row_) * Kd + k0_ + part_ * 8;    \
            cp16(sb_ + OFFB_BH + dr_, Wh + sbsrc_);                        \
            cp16(sb_ + OFFB_BL + dr_, Wl + sbsrc_);                        \
        }                                                                  \
        CP_COMMIT();                                                       \
    } while (0)

    ISSUE_CHUNK(0);

    for (int kt = 0; kt < NC; ++kt) {
        if (kt + 1 < NC) { ISSUE_CHUNK(kt + 1); CP_WAIT(1); }
        else             { CP_WAIT(0); }
        __syncthreads();
        uint32_t sb = smbase + (kt & 1) * STAGE_B;
#pragma unroll
        for (int ks = 0; ks < 32; ks += 16) {
            uint32_t aH[4][4], aL[4][4], bH[4][2], bL[4][2];
#pragma unroll
            for (int mf = 0; mf < 4; ++mf)
                ldsm4(aH[mf], sb + OFFB_AH + aoff + mf * (16 * TSTR * 2) + ks * 2);
#pragma unroll
            for (int nf = 0; nf < 4; ++nf)
                ldsm2(bH[nf], sb + OFFB_BH + boff + nf * (8 * TSTR * 2) + ks * 2);
#pragma unroll
            for (int mf = 0; mf < 4; ++mf)
#pragma unroll
                for (int nf = 0; nf < 4; ++nf)
                    mma16816(acc[mf][nf], aH[mf], bH[nf]);
#pragma unroll
            for (int nf = 0; nf < 4; ++nf)
                ldsm2(bL[nf], sb + OFFB_BL + boff + nf * (8 * TSTR * 2) + ks * 2);
#pragma unroll
            for (int mf = 0; mf < 4; ++mf)
#pragma unroll
                for (int nf = 0; nf < 4; ++nf)
                    mma16816(acc[mf][nf], aH[mf], bL[nf]);
#pragma unroll
            for (int mf = 0; mf < 4; ++mf)
                ldsm4(aL[mf], sb + OFFB_AL + aoff + mf * (16 * TSTR * 2) + ks * 2);
#pragma unroll
            for (int mf = 0; mf < 4; ++mf)
#pragma unroll
                for (int nf = 0; nf < 4; ++nf)
                    mma16816(acc[mf][nf], aL[mf], bH[nf]);
        }
        __syncthreads();
    }
#undef ISSUE_CHUNK

#pragma unroll
    for (int mf = 0; mf < 4; ++mf) {
#pragma unroll
        for (int nf = 0; nf < 4; ++nf) {
            int r = m0 + arow + (mf << 4) + g;
            int c = n0 + brow + (nf << 3) + (q << 1);
            if (mode & 2) {
                float t0 = tanhf(acc[mf][nf][0]), t1 = tanhf(acc[mf][nf][1]);
                float t2 = tanhf(acc[mf][nf][2]), t3 = tanhf(acc[mf][nf][3]);
                bf16 h0, l0, h1, l1;
                bsplit1(t0, h0, l0); bsplit1(t1, h1, l1);
                *(uint32_t*)(Ch + (size_t)r * N + c) =
                    (uint32_t)__bfloat16_as_ushort(h0) |
                    ((uint32_t)__bfloat16_as_ushort(h1) << 16);
                *(uint32_t*)(Cl + (size_t)r * N + c) =
                    (uint32_t)__bfloat16_as_ushort(l0) |
                    ((uint32_t)__bfloat16_as_ushort(l1) << 16);
                bsplit1(t2, h0, l0); bsplit1(t3, h1, l1);
                *(uint32_t*)(Ch + (size_t)(r + 8) * N + c) =
                    (uint32_t)__bfloat16_as_ushort(h0) |
                    ((uint32_t)__bfloat16_as_ushort(h1) << 16);
                *(uint32_t*)(Cl + (size_t)(r + 8) * N + c) =
                    (uint32_t)__bfloat16_as_ushort(l0) |
                    ((uint32_t)__bfloat16_as_ushort(l1) << 16);
            } else {
                float2 v0, v1;
                v0.x = acc[mf][nf][0]; v0.y = acc[mf][nf][1];
                v1.x = acc[mf][nf][2]; v1.y = acc[mf][nf][3];
                *(float2*)(Cf + (size_t)r * N + c) = v0;
                *(float2*)(Cf + (size_t)(r + 8) * N + c) = v1;
            }
        }
    }
}

/* ------------------------------------------------------------------ */
/* weight prep (all layers per launch)                                 */
/* ------------------------------------------------------------------ */
__global__ void wtrans_all_kernel(const float* __restrict__ W,
                                  bf16* __restrict__ wh, bf16* __restrict__ wl,
                                  int Kd, int N)
{
    int idx = blockIdx.x * 256 + threadIdx.x;
    int per = Kd * N;
    int layer = idx / per, r = idx - layer * per;
    int k = r / N, n = r - k * N;
    float v = W[(size_t)layer * per + (size_t)k * N + n];
    bf16 h, l; bsplit1(v, h, l);
    size_t dst = (size_t)layer * per + (size_t)n * Kd + k;
    wh[dst] = h; wl[dst] = l;
}

__global__ void wpackT_all_kernel(const float* __restrict__ Wq,
                                  const float* __restrict__ Wk,
                                  const float* __restrict__ Wv,
                                  bf16* __restrict__ wh, bf16* __restrict__ wl)
{
    int idx = blockIdx.x * 256 + threadIdx.x;
    int per = CC * QS;
    int layer = idx / per, r = idx - layer * per;
    int k = r / QS, n = r - k * QS;
    const float* src = (n < 256) ? Wq : (n < 512) ? Wk : Wv;
    float v = src[(size_t)layer * CC * CC + (size_t)k * 256 + (n & 255)];
    bf16 h, l; bsplit1(v, h, l);
    size_t dst = (size_t)layer * (QS * CC) + (size_t)n * CC + k;
    wh[dst] = h; wl[dst] = l;
}

/* initial x copy + split, both features into contiguous halves        */
__global__ void split_in_kernel(const float* __restrict__ f0,
                                const float* __restrict__ f1,
                                float* __restrict__ x,
                                bf16* __restrict__ xh, bf16* __restrict__ xl)
{
    int i = blockIdx.x * 256 + threadIdx.x;      /* 0 .. M2*CC */
    const float* src = (i < MS * CC) ? f0 : f1 - MS * CC;
    float v = src[i];
    x[i] = v;
    bf16 h, l; bsplit1(v, h, l);
    xh[i] = h; xl[i] = l;
}

/* ------------------------------------------------------------------ */
/* Self linear attention — batched over 4 slabs (feature x batch)      */
/* ------------------------------------------------------------------ */
__global__ void __launch_bounds__(256) self_kv_kernel(
    const float* __restrict__ qkv, maskp __restrict__ m0p,
    maskp __restrict__ m1p, float* __restrict__ KV, float* __restrict__ Ks)
{
    int blk = blockIdx.x;                /* 512 blocks */
    int ch = blk & 15, h = (blk >> 4) & 7, fb = blk >> 7;  /* fb 0..3 */
    int tid = threadIdx.x;
    int d = tid >> 3, eq = tid & 7, e0 = eq << 2;
    float a0 = 0.f, a1 = 0.f, a2 = 0.f, a3 = 0.f, accs = 0.f;
    int base = (fb << 12) + (ch << 8);   /* global row in [0, M2) */
    maskp mp = ((fb >> 1) ? m1p : m0p) + ((fb & 1) << 12) + (ch << 8);
    const float* kp = qkv + (size_t)base * QS + 256 + h * DD + d;
    const float* vp = qkv + (size_t)base * QS + 512 + h * DD + e0;
#pragma unroll 4
    for (int r = 0; r < 256; ++r) {
        float m = mp[r] ? 1.f : 0.f;
        float kf = m * elu1(kp[(size_t)r * QS]);
        float4 v = *(const float4*)(vp + (size_t)r * QS);
        a0 += kf * v.x; a1 += kf * v.y; a2 += kf * v.z; a3 += kf * v.w;
        accs += kf;
    }
    float* kvp = KV + ((size_t)((fb * HH + h) * DD + d) * DD + e0);
    atomicAdd(kvp + 0, a0);
    atomicAdd(kvp + 1, a1);
    atomicAdd(kvp + 2, a2);
    atomicAdd(kvp + 3, a3);
    if (eq == 0) atomicAdd(Ks + (fb * HH + h) * DD + d, accs);
}

__global__ void __launch_bounds__(256) self_att_kernel(
    const float* __restrict__ qkv, const float* __restrict__ KV,
    const float* __restrict__ Ks, bf16* __restrict__ oh,
    bf16* __restrict__ ol)
{
    __shared__ float sKV[HH][DD][DD];
    __shared__ float sKs[HH][DD];
    __shared__ float sQf[8][CC];
    int tid = threadIdx.x;
    int t0 = blockIdx.x << 3;            /* global row */
    int fb = t0 >> 12;
    for (int i = tid; i < HH * DD * DD; i += 256)
        (&sKV[0][0][0])[i] = KV[(size_t)fb * HH * DD * DD + i];
    for (int i = tid; i < HH * DD; i += 256)
        (&sKs[0][0])[i] = Ks[fb * HH * DD + i];
#pragma unroll
    for (int tt = 0; tt < 8; ++tt)
        sQf[tt][tid] = elu1(qkv[(size_t)(t0 + tt) * QS + tid]);
    __syncthreads();
    int h = tid >> 5, e = tid & 31;
#pragma unroll
    for (int tt = 0; tt < 8; ++tt) {
        float den = sQf[tt][(h << 5) + e] * sKs[h][e];
#pragma unroll
        for (int o = 16; o; o >>= 1) den += __shfl_xor_sync(0xffffffffu, den, o);
        float out = 0.f;
#pragma unroll
        for (int d = 0; d < 32; ++d)
            out += sQf[tt][(h << 5) + d] * sKV[h][d][e];
        float o = out / (den + 1e-6f);
        bf16 hh, lo; bsplit1(o, hh, lo);
        oh[(size_t)(t0 + tt) * CC + tid] = hh;
        ol[(size_t)(t0 + tt) * CC + tid] = lo;
    }
}

/* ------------------------------------------------------------------ */
/* bilinear taps + invnorm + cross attention (batched)                 */
/* ------------------------------------------------------------------ */
__device__ __forceinline__ void taps_of(float kx, float ky, int base,
                                        int* r, float* w)
{
    float px = (((kx - 3.5f) / 507.5f * 2.f - 1.f) + 1.f) * 0.5f * 63.f;
    float py = (((ky - 3.5f) / 507.5f * 2.f - 1.f) + 1.f) * 0.5f * 63.f;
    float x0f = floorf(px), y0f = floorf(py);
    float wx = px - x0f, wy = py - y0f;
    int ix0 = min(max((int)x0f, 0), 63);
    int ix1 = min(max((int)x0f + 1, 0), 63);
    int iy0 = min(max((int)y0f, 0), 63);
    int iy1 = min(max((int)y0f + 1, 0), 63);
    r[0] = base + (iy0 << 6) + ix0;
    r[1] = base + (iy0 << 6) + ix1;
    r[2] = base + (iy1 << 6) + ix0;
    r[3] = base + (iy1 << 6) + ix1;
    w[0] = (1.f - wy) * (1.f - wx);
    w[1] = (1.f - wy) * wx;
    w[2] = wy * (1.f - wx);
    w[3] = wy * wx;
}

/* invn[0:MD) = norms of feat-half-0 samples @ kp0; [MD:2MD) = half1@kp1 */
__global__ void __launch_bounds__(256) invnorm_kernel(
    const float* __restrict__ x, const float* __restrict__ kp0,
    const float* __restrict__ kp1, float* __restrict__ invn)
{
    int pg = (blockIdx.x << 3) + (threadIdx.x >> 5);   /* 0 .. 2*MD */
    int lane = threadIdx.x & 31;
    int f = pg >= MD;
    int pl = pg - f * MD;
    const float* kp = f ? kp1 : kp0;
    int b = pl / (LL * KK);
    int r[4]; float w[4];
    taps_of(kp[(size_t)pl * 2], kp[(size_t)pl * 2 + 1],
            f * MS + b * LL, r, w);
    const float* f0 = x + (size_t)r[0] * CC;
    const float* f1 = x + (size_t)r[1] * CC;
    const float* f2 = x + (size_t)r[2] * CC;
    const float* f3 = x + (size_t)r[3] * CC;
    float sq = 0.f;
#pragma unroll
    for (int j = 0; j < 8; ++j) {
        int c = lane + (j << 5);
        float val = w[0]*f0[c] + w[1]*f1[c] + w[2]*f2[c] + w[3]*f3[c];
        sq += val * val;
    }
#pragma unroll
    for (int o = 16; o; o >>= 1) sq += __shfl_xor_sync(0xffffffffu, sq, o);
    if (lane == 0) invn[pg] = 1.f / (sqrtf(sq) + 1e-8f);
}

__global__ void __launch_bounds__(256) cross_att_kernel(
    const float* __restrict__ qkv, const float* __restrict__ kp0,
    const float* __restrict__ kp1, const float* __restrict__ invn,
    maskp __restrict__ mc0, maskp __restrict__ mc1,
    bf16* __restrict__ oh, bf16* __restrict__ ol)
{
    int t = blockIdx.x;                  /* 0 .. M2 */
    int tid = threadIdx.x;
    int h = tid >> 5, lane = tid & 31;
    int f = t >> 13;                     /* feature of the query */
    int tok = t & (MS - 1);
    int b = tok >> 12;
    /* query-half f attends to samples from the OTHER half */
    const float* kp = f ? kp0 : kp1;
    const float* inv_base = invn + (size_t)(1 - f) * MD;
    maskp mask = f ? mc0 : mc1;
    int src_base = (1 - f) * MS + b * LL;

    __shared__ float sQf[CC];
    __shared__ int   sTap[KK][4];
    __shared__ float sW[KK][4];
    __shared__ float sInv[KK];
    __shared__ float sM[KK];
    sQf[tid] = elu1(qkv[(size_t)t * QS + tid]);
    if (tid < KK) {
        int p = tok * KK + tid;
        int r[4]; float w[4];
        taps_of(kp[(size_t)p * 2], kp[(size_t)p * 2 + 1], src_base, r, w);
#pragma unroll
        for (int i = 0; i < 4; ++i) { sTap[tid][i] = r[i]; sW[tid][i] = w[i]; }
        sInv[tid] = inv_base[p];
        sM[tid] = mask[p] ? 1.f : 0.f;
    }
    __syncthreads();
    int c = (h << 5) + lane;
    float qf = sQf[c];
    float wgt[KK];
    float den = 0.f;
#pragma unroll
    for (int s = 0; s < KK; ++s) {
        float kraw =
            sW[s][0] * qkv[(size_t)sTap[s][0] * QS + 256 + c] +
            sW[s][1] * qkv[(size_t)sTap[s][1] * QS + 256 + c] +
            sW[s][2] * qkv[(size_t)sTap[s][2] * QS + 256 + c] +
            sW[s][3] * qkv[(size_t)sTap[s][3] * QS + 256 + c];
        float kf = elu1(kraw * sInv[s]) * sM[s];
        float p = qf * kf;
#pragma unroll
        for (int o = 16; o; o >>= 1) p += __shfl_xor_sync(0xffffffffu, p, o);
        wgt[s] = p;
        den += p;
    }
    float inv = 1.f / (den + 1e-6f);
    float out = 0.f;
#pragma unroll
    for (int s = 0; s < KK; ++s) {
        float vraw =
            sW[s][0] * qkv[(size_t)sTap[s][0] * QS + 512 + c] +
            sW[s][1] * qkv[(size_t)sTap[s][1] * QS + 512 + c] +
            sW[s][2] * qkv[(size_t)sTap[s][2] * QS + 512 + c] +
            sW[s][3] * qkv[(size_t)sTap[s][3] * QS + 512 + c];
        out += wgt[s] * (vraw * sInv[s]);
    }
    float o = out * inv;
    bf16 hh, lo; bsplit1(o, hh, lo);
    oh[(size_t)t * CC + tid] = hh;
    ol[(size_t)t * CC + tid] = lo;
}

/* ------------------------------------------------------------------ */
/* LayerNorm (C=256, eps 1e-5)                                         */
/* ------------------------------------------------------------------ */
__device__ __forceinline__ void ln_core(const float* xr, float* v,
                                        float& mean, float& rstd)
{
    int lane = threadIdx.x & 31;
    float s = 0.f;
#pragma unroll
    for (int j = 0; j < 8; ++j) { v[j] = xr[lane + (j << 5)]; s += v[j]; }
#pragma unroll
    for (int o = 16; o; o >>= 1) s += __shfl_xor_sync(0xffffffffu, s, o);
    mean = s * (1.f / 256.f);
    float q = 0.f;
#pragma unroll
    for (int j = 0; j < 8; ++j) { float d = v[j] - mean; q += d * d; }
#pragma unroll
    for (int o = 16; o; o >>= 1) q += __shfl_xor_sync(0xffffffffu, q, o);
    rstd = rsqrtf(q * (1.f / 256.f) + 1e-5f);
}

__global__ void __launch_bounds__(256) ln_split_kernel(
    const float* __restrict__ X, const float* __restrict__ gam,
    const float* __restrict__ bet, bf16* __restrict__ oh,
    bf16* __restrict__ ol)
{
    int warp = threadIdx.x >> 5, lane = threadIdx.x & 31;
    int row = (blockIdx.x << 3) + warp;
    float v[8], mean, rstd;
    ln_core(X + (size_t)row * CC, v, mean, rstd);
#pragma unroll
    for (int j = 0; j < 8; ++j) {
        int c = lane + (j << 5);
        float o = (v[j] - mean) * rstd * gam[c] + bet[c];
        bf16 h, l; bsplit1(o, h, l);
        oh[(size_t)row * CC + c] = h;
        ol[(size_t)row * CC + c] = l;
    }
}

__global__ void __launch_bounds__(256) ln_add_kernel(
    const float* __restrict__ X, const float* __restrict__ gam,
    const float* __restrict__ bet, float* __restrict__ x,
    bf16* __restrict__ xh, bf16* __restrict__ xl)
{
    int warp = threadIdx.x >> 5, lane = threadIdx.x & 31;
    int row = (blockIdx.x << 3) + warp;
    float v[8], mean, rstd;
    ln_core(X + (size_t)row * CC, v, mean, rstd);
#pragma unroll
    for (int j = 0; j < 8; ++j) {
        int c = lane + (j << 5);
        float o = (v[j] - mean) * rstd * gam[c] + bet[c];
        float nx = x[(size_t)row * CC + c] + o;
        x[(size_t)row * CC + c] = nx;
        bf16 h, l; bsplit1(nx, h, l);
        xh[(size_t)row * CC + c] = h;
        xl[(size_t)row * CC + c] = l;
    }
}

/* ------------------------------------------------------------------ */
/* host orchestration                                                  */
/* ------------------------------------------------------------------ */
struct LayerW {
    const float *g1, *b1, *g2, *b2;
    bf16 *whP, *wlP, *whM, *wlM, *wh1, *wl1, *wh2, *wl2;
};
struct Bufs {
    float *t, *kv, *ks;
    bf16 *atth, *attl, *msgh, *msgl, *uh, *ul;
};

static void mlp_tail(float* x, bf16* xh, bf16* xl, const LayerW& w,
                     const Bufs& s)
{
    hgemm2_kernel<<<dim3(2,128), 256, DSMEM>>>(
        s.atth, s.attl, (const bf16*)0, (const bf16*)0,
        w.whM, w.wlM, s.t, (bf16*)0, (bf16*)0, CC, CC, 0);
    ln_split_kernel<<<M2/8, 256>>>(s.t, w.g1, w.b1, s.msgh, s.msgl);
    hgemm2_kernel<<<dim3(4,128), 256, DSMEM>>>(
        xh, xl, s.msgh, s.msgl, w.wh1, w.wl1,
        (float*)0, s.uh, s.ul, C2, C2, 3);
    hgemm2_kernel<<<dim3(2,128), 256, DSMEM>>>(
        s.uh, s.ul, (const bf16*)0, (const bf16*)0,
        w.wh2, w.wl2, s.t, (bf16*)0, (bf16*)0, CC, C2, 0);
    ln_add_kernel<<<M2/8, 256>>>(s.t, w.g2, w.b2, x, xh, xl);
}

extern "C" void kernel_launch(void* const* d_in, const int* in_sizes, int n_in,
                              void* d_out, int out_size)
{
    (void)in_sizes; (void)n_in; (void)out_size;
    const float* feat0 = (const float*)d_in[0];
    const float* feat1 = (const float*)d_in[1];
    const float* kp0   = (const float*)d_in[2];
    const float* kp1   = (const float*)d_in[3];
    maskp ms0 = (maskp)d_in[4];
    maskp ms1 = (maskp)d_in[5];
    maskp mc0 = (maskp)d_in[6];
    maskp mc1 = (maskp)d_in[7];
    const float* Wq = (const float*)d_in[8];
    const float* Wk = (const float*)d_in[9];
    const float* Wv = (const float*)d_in[10];
    const float* Wm = (const float*)d_in[11];
    const float* W1 = (const float*)d_in[12];
    const float* W2 = (const float*)d_in[13];
    const float* G1 = (const float*)d_in[14];
    const float* B1 = (const float*)d_in[15];
    const float* G2 = (const float*)d_in[16];
    const float* B2 = (const float*)d_in[17];

    cudaFuncSetAttribute(hgemm2_kernel,
                         cudaFuncAttributeMaxDynamicSharedMemorySize, DSMEM);

    float *px, *pq, *pin;
    bf16 *pxh, *pxl;
    bf16 *whP, *wlP, *whM, *wlM, *wh1, *wl1, *wh2, *wl2;
    Bufs s;
    cudaGetSymbolAddress((void**)&px, g_x);
    cudaGetSymbolAddress((void**)&pxh, g_xh);
    cudaGetSymbolAddress((void**)&pxl, g_xl);
    cudaGetSymbolAddress((void**)&pq, g_qkv);
    cudaGetSymbolAddress((void**)&pin, g_invn);
    cudaGetSymbolAddress((void**)&s.t, g_tb);
    cudaGetSymbolAddress((void**)&s.kv, g_kvb);
    cudaGetSymbolAddress((void**)&s.ks, g_ksb);
    cudaGetSymbolAddress((void**)&s.atth, g_atth);
    cudaGetSymbolAddress((void**)&s.attl, g_attl);
    cudaGetSymbolAddress((void**)&s.msgh, g_msgh);
    cudaGetSymbolAddress((void**)&s.msgl, g_msgl);
    cudaGetSymbolAddress((void**)&s.uh, g_uh);
    cudaGetSymbolAddress((void**)&s.ul, g_ul);
    cudaGetSymbolAddress((void**)&whP, g_whP);
    cudaGetSymbolAddress((void**)&wlP, g_wlP);
    cudaGetSymbolAddress((void**)&whM, g_whM);
    cudaGetSymbolAddress((void**)&wlM, g_wlM);
    cudaGetSymbolAddress((void**)&wh1, g_wh1);
    cudaGetSymbolAddress((void**)&wl1, g_wl1);
    cudaGetSymbolAddress((void**)&wh2, g_wh2);
    cudaGetSymbolAddress((void**)&wl2, g_wl2);

    /* front-loaded weight prep + input split */
    wpackT_all_kernel<<<NL*CC*QS/256, 256>>>(Wq, Wk, Wv, whP, wlP);
    wtrans_all_kernel<<<NL*CC*CC/256, 256>>>(Wm, whM, wlM, CC, CC);
    wtrans_all_kernel<<<NL*C2*C2/256, 256>>>(W1, wh1, wl1, C2, C2);
    wtrans_all_kernel<<<NL*C2*CC/256, 256>>>(W2, wh2, wl2, C2, CC);
    split_in_kernel<<<M2*CC/256, 256>>>(feat0, feat1, px, pxh, pxl);

    for (int i = 0; i < 4; ++i) {
        LayerW w;
        w.g1 = G1 + (size_t)i * CC;
        w.b1 = B1 + (size_t)i * CC;
        w.g2 = G2 + (size_t)i * CC;
        w.b2 = B2 + (size_t)i * CC;
        w.whP = whP + (size_t)i * QS * CC; w.wlP = wlP + (size_t)i * QS * CC;
        w.whM = whM + (size_t)i * CC * CC; w.wlM = wlM + (size_t)i * CC * CC;
        w.wh1 = wh1 + (size_t)i * C2 * C2; w.wl1 = wl1 + (size_t)i * C2 * C2;
        w.wh2 = wh2 + (size_t)i * C2 * CC; w.wl2 = wl2 + (size_t)i * C2 * CC;

        /* packed q|k|v projection, both features, one launch */
        hgemm2_kernel<<<dim3(6,128), 256, DSMEM>>>(
            pxh, pxl, (const bf16*)0, (const bf16*)0,
            w.whP, w.wlP, pq, (bf16*)0, (bf16*)0, QS, CC, 0);

        if ((i & 1) == 0) {
            cudaMemsetAsync(s.kv, 0, (size_t)4*HH*DD*DD*sizeof(float), 0);
            cudaMemsetAsync(s.ks, 0, (size_t)4*HH*DD*sizeof(float), 0);
            self_kv_kernel<<<512, 256>>>(pq, ms0, ms1, s.kv, s.ks);
            self_att_kernel<<<M2/8, 256>>>(pq, s.kv, s.ks, s.atth, s.attl);
        } else {
            invnorm_kernel<<<2*MD/8, 256>>>(px, kp0, kp1, pin);
            cross_att_kernel<<<M2, 256>>>(pq, kp0, kp1, pin, mc0, mc1,
                                          s.atth, s.attl);
        }
        mlp_tail(px, pxh, pxl, w, s);
    }

    cudaMemcpyAsync(d_out, px, (size_t)M2 * CC * sizeof(float),
                    cudaMemcpyDeviceToDevice, 0);
}

// round 10
// speedup vs baseline: 2.9463x; 1.0097x over previous
#include <cuda_runtime.h>
#include <cuda_bf16.h>
#include <cstdint>
#include <math.h>

#define BB 2
#define LL 4096
#define CC 256
#define C2 512
#define QS 768
#define HH 8
#define DD 32
#define KK 9
#define NL 4
#define MS (BB*LL)          /* rows per feature   */
#define M2 (2*MS)           /* batched rows       */
#define MD (BB*LL*KK)       /* points per feature */
#define KVSZ (4*HH*DD*DD)
#define KSSZ (4*HH*DD)

typedef __nv_bfloat16 bf16;
typedef const unsigned int* maskp;

/* ------------------------------------------------------------------ */
/* device globals — feat0 half then feat1 half, contiguous             */
/* ------------------------------------------------------------------ */
__device__ float g_x[M2*CC];
__device__ bf16  g_xh[M2*CC], g_xl[M2*CC];
__device__ float g_qkv[M2*QS];
__device__ float g_invn[2*MD];
__device__ bf16  g_atth[M2*CC], g_attl[M2*CC];
__device__ bf16  g_msgh[M2*CC], g_msgl[M2*CC];
__device__ bf16  g_uh[M2*C2],  g_ul[M2*C2];
__device__ float g_tb[M2*CC];
__device__ float g_kvks[KVSZ + KSSZ];    /* KV then Ksum, one memset   */
__device__ bf16 g_whP[NL*QS*CC], g_wlP[NL*QS*CC];
__device__ bf16 g_whM[NL*CC*CC], g_wlM[NL*CC*CC];
__device__ bf16 g_wh1[NL*C2*C2], g_wl1[NL*C2*C2];
__device__ bf16 g_wh2[NL*CC*C2], g_wl2[NL*CC*C2];

__device__ __forceinline__ float elu1(float x) { return x > 0.f ? x + 1.f : expf(x); }

__device__ __forceinline__ uint32_t smem_u32(const void* p) {
    uint32_t a;
    asm("{ .reg .u64 t; cvta.to.shared.u64 t, %1; cvt.u32.u64 %0, t; }"
        : "=r"(a) : "l"(p));
    return a;
}
__device__ __forceinline__ void cp16(uint32_t dst, const void* src) {
    asm volatile(
        "{ .reg .u64 g; cvta.to.global.u64 g, %1; "
        "cp.async.cg.shared.global [%0], [g], 16; }"
        :: "r"(dst), "l"(src));
}
#define CP_COMMIT() asm volatile("cp.async.commit_group;")
#define CP_WAIT(n)  asm volatile("cp.async.wait_group %0;" :: "n"(n))

__device__ __forceinline__ void ldsm4(uint32_t* r, uint32_t a) {
    asm volatile("ldmatrix.sync.aligned.m8n8.x4.shared.b16 {%0,%1,%2,%3}, [%4];"
                 : "=r"(r[0]), "=r"(r[1]), "=r"(r[2]), "=r"(r[3]) : "r"(a));
}
__device__ __forceinline__ void ldsm2(uint32_t* r, uint32_t a) {
    asm volatile("ldmatrix.sync.aligned.m8n8.x2.shared.b16 {%0,%1}, [%2];"
                 : "=r"(r[0]), "=r"(r[1]) : "r"(a));
}
__device__ __forceinline__ void mma16816(float* c, const uint32_t* a,
                                         const uint32_t* b) {
    asm volatile(
        "mma.sync.aligned.m16n8k16.row.col.f32.bf16.bf16.f32 "
        "{%0,%1,%2,%3}, {%4,%5,%6,%7}, {%8,%9}, {%0,%1,%2,%3};"
        : "+f"(c[0]), "+f"(c[1]), "+f"(c[2]), "+f"(c[3])
        : "r"(a[0]), "r"(a[1]), "r"(a[2]), "r"(a[3]), "r"(b[0]), "r"(b[1]));
}
__device__ __forceinline__ void bsplit1(float v, bf16& h, bf16& l) {
    h = __float2bfloat16(v);
    l = __float2bfloat16(v - __bfloat162float(h));
}

/* ------------------------------------------------------------------ */
/* HMMA GEMM: pre-split bf16, cp.async dbl buffer, ldmatrix, TSTR=40   */
/* CTA 128x128, warp 64x32, 2 CTAs/SM (regs<=128)                      */
/* mode bit0: K-split (k<256 from A pair, k>=256 from B pair, lda=256) */
/* mode bit1: tanh + bf16 hi/lo output                                 */
/* ------------------------------------------------------------------ */
#define TSTR 40
#define TILE_B (128*TSTR*2)
#define OFFB_AH 0
#define OFFB_AL (1*TILE_B)
#define OFFB_BH (2*TILE_B)
#define OFFB_BL (3*TILE_B)
#define STAGE_B (4*TILE_B)
#define DSMEM   (2*STAGE_B)           /* 81920 B; x2 CTAs = 160 KB/SM  */

__global__ void __launch_bounds__(256, 2)
hgemm2_kernel(const bf16* __restrict__ Ah1, const bf16* __restrict__ Al1,
              const bf16* __restrict__ Ah2, const bf16* __restrict__ Al2,
              const bf16* __restrict__ Wh, const bf16* __restrict__ Wl,
              float* __restrict__ Cf, bf16* __restrict__ Ch,
              bf16* __restrict__ Cl, int N, int Kd, int mode)
{
    extern __shared__ __align__(16) char smh[];
    uint32_t smbase = smem_u32(smh);
    int tid = threadIdx.x, wid = tid >> 5, lane = tid & 31;
    int g = lane >> 2, q = lane & 3;
    int m0 = blockIdx.y << 7, n0 = blockIdx.x << 7;
    int wm = wid >> 2, wn = wid & 3;
    int arow = wm << 6, brow = wn << 5;

    int lr = lane & 7, sel = lane >> 3;
    uint32_t aoff = (uint32_t)(((arow + lr + (sel & 1) * 8) * TSTR
                                + (sel >> 1) * 8) * 2);
    uint32_t boff = (uint32_t)(((brow + lr) * TSTR + (sel & 1) * 8) * 2);

    float acc[4][4][4];
#pragma unroll
    for (int i = 0; i < 4; ++i)
#pragma unroll
        for (int j = 0; j < 4; ++j)
#pragma unroll
            for (int k = 0; k < 4; ++k) acc[i][j][k] = 0.f;

    const int NC = Kd >> 5;

#define ISSUE_CHUNK(CI) do {                                               \
        int k0_ = (CI) << 5;                                               \
        const bf16 *ah_, *al_; int lda_, kl_;                              \
        if (mode & 1) {                                                    \
            if (k0_ < 256) { ah_ = Ah1; al_ = Al1; kl_ = k0_; }            \
            else           { ah_ = Ah2; al_ = Al2; kl_ = k0_ - 256; }      \
            lda_ = 256;                                                    \
        } else { ah_ = Ah1; al_ = Al1; kl_ = k0_; lda_ = Kd; }             \
        uint32_t sb_ = smbase + ((CI) & 1) * STAGE_B;                      \
        _Pragma("unroll")                                                  \
        for (int i_ = 0; i_ < 2; ++i_) {                                   \
            int s_ = tid + (i_ << 8);                                      \
            int row_ = s_ >> 2, part_ = s_ & 3;                            \
            uint32_t dr_ = (uint32_t)(row_ * (TSTR * 2) + part_ * 16);     \
            size_t sa_ = (size_t)(m0 + row_) * lda_ + kl_ + part_ * 8;     \
            cp16(sb_ + OFFB_AH + dr_, ah_ + sa_);                          \
            cp16(sb_ + OFFB_AL + dr_, al_ + sa_);                          \
            size_t sbsrc_ = (size_t)(n0 + row_) * Kd + k0_ + part_ * 8;    \
            cp16(sb_ + OFFB_BH + dr_, Wh + sbsrc_);                        \
            cp16(sb_ + OFFB_BL + dr_, Wl + sbsrc_);                        \
        }                                                                  \
        CP_COMMIT();                                                       \
    } while (0)

    ISSUE_CHUNK(0);

    for (int kt = 0; kt < NC; ++kt) {
        if (kt + 1 < NC) { ISSUE_CHUNK(kt + 1); CP_WAIT(1); }
        else             { CP_WAIT(0); }
        __syncthreads();
        uint32_t sb = smbase + (kt & 1) * STAGE_B;
#pragma unroll
        for (int ks = 0; ks < 32; ks += 16) {
            /* liveness-ordered: aH+bH -> +bL (then bL dies) -> aL+bH */
            uint32_t aH[4][4], bH[4][2];
#pragma unroll
            for (int mf = 0; mf < 4; ++mf)
                ldsm4(aH[mf], sb + OFFB_AH + aoff + mf * (16 * TSTR * 2) + ks * 2);
#pragma unroll
            for (int nf = 0; nf < 4; ++nf)
                ldsm2(bH[nf], sb + OFFB_BH + boff + nf * (8 * TSTR * 2) + ks * 2);
#pragma unroll
            for (int mf = 0; mf < 4; ++mf)
#pragma unroll
                for (int nf = 0; nf < 4; ++nf)
                    mma16816(acc[mf][nf], aH[mf], bH[nf]);
            {
                uint32_t bL[4][2];
#pragma unroll
                for (int nf = 0; nf < 4; ++nf)
                    ldsm2(bL[nf], sb + OFFB_BL + boff + nf * (8 * TSTR * 2) + ks * 2);
#pragma unroll
                for (int mf = 0; mf < 4; ++mf)
#pragma unroll
                    for (int nf = 0; nf < 4; ++nf)
                        mma16816(acc[mf][nf], aH[mf], bL[nf]);
            }
            {
                uint32_t aL[4][4];
#pragma unroll
                for (int mf = 0; mf < 4; ++mf)
                    ldsm4(aL[mf], sb + OFFB_AL + aoff + mf * (16 * TSTR * 2) + ks * 2);
#pragma unroll
                for (int mf = 0; mf < 4; ++mf)
#pragma unroll
                    for (int nf = 0; nf < 4; ++nf)
                        mma16816(acc[mf][nf], aL[mf], bH[nf]);
            }
        }
        __syncthreads();
    }
#undef ISSUE_CHUNK

#pragma unroll
    for (int mf = 0; mf < 4; ++mf) {
#pragma unroll
        for (int nf = 0; nf < 4; ++nf) {
            int r = m0 + arow + (mf << 4) + g;
            int c = n0 + brow + (nf << 3) + (q << 1);
            if (mode & 2) {
                float t0 = tanhf(acc[mf][nf][0]), t1 = tanhf(acc[mf][nf][1]);
                float t2 = tanhf(acc[mf][nf][2]), t3 = tanhf(acc[mf][nf][3]);
                bf16 h0, l0, h1, l1;
                bsplit1(t0, h0, l0); bsplit1(t1, h1, l1);
                *(uint32_t*)(Ch + (size_t)r * N + c) =
                    (uint32_t)__bfloat16_as_ushort(h0) |
                    ((uint32_t)__bfloat16_as_ushort(h1) << 16);
                *(uint32_t*)(Cl + (size_t)r * N + c) =
                    (uint32_t)__bfloat16_as_ushort(l0) |
                    ((uint32_t)__bfloat16_as_ushort(l1) << 16);
                bsplit1(t2, h0, l0); bsplit1(t3, h1, l1);
                *(uint32_t*)(Ch + (size_t)(r + 8) * N + c) =
                    (uint32_t)__bfloat16_as_ushort(h0) |
                    ((uint32_t)__bfloat16_as_ushort(h1) << 16);
                *(uint32_t*)(Cl + (size_t)(r + 8) * N + c) =
                    (uint32_t)__bfloat16_as_ushort(l0) |
                    ((uint32_t)__bfloat16_as_ushort(l1) << 16);
            } else {
                float2 v0, v1;
                v0.x = acc[mf][nf][0]; v0.y = acc[mf][nf][1];
                v1.x = acc[mf][nf][2]; v1.y = acc[mf][nf][3];
                *(float2*)(Cf + (size_t)r * N + c) = v0;
                *(float2*)(Cf + (size_t)(r + 8) * N + c) = v1;
            }
        }
    }
}

/* ------------------------------------------------------------------ */
/* weight prep (all layers per launch)                                 */
/* ------------------------------------------------------------------ */
__global__ void wtrans_all_kernel(const float* __restrict__ W,
                                  bf16* __restrict__ wh, bf16* __restrict__ wl,
                                  int Kd, int N)
{
    int idx = blockIdx.x * 256 + threadIdx.x;
    int per = Kd * N;
    int layer = idx / per, r = idx - layer * per;
    int k = r / N, n = r - k * N;
    float v = W[(size_t)layer * per + (size_t)k * N + n];
    bf16 h, l; bsplit1(v, h, l);
    size_t dst = (size_t)layer * per + (size_t)n * Kd + k;
    wh[dst] = h; wl[dst] = l;
}

__global__ void wpackT_all_kernel(const float* __restrict__ Wq,
                                  const float* __restrict__ Wk,
                                  const float* __restrict__ Wv,
                                  bf16* __restrict__ wh, bf16* __restrict__ wl)
{
    int idx = blockIdx.x * 256 + threadIdx.x;
    int per = CC * QS;
    int layer = idx / per, r = idx - layer * per;
    int k = r / QS, n = r - k * QS;
    const float* src = (n < 256) ? Wq : (n < 512) ? Wk : Wv;
    float v = src[(size_t)layer * CC * CC + (size_t)k * 256 + (n & 255)];
    bf16 h, l; bsplit1(v, h, l);
    size_t dst = (size_t)layer * (QS * CC) + (size_t)n * CC + k;
    wh[dst] = h; wl[dst] = l;
}

/* initial x copy + split, both features into contiguous halves        */
__global__ void split_in_kernel(const float* __restrict__ f0,
                                const float* __restrict__ f1,
                                float* __restrict__ x,
                                bf16* __restrict__ xh, bf16* __restrict__ xl)
{
    int i = blockIdx.x * 256 + threadIdx.x;
    const float* src = (i < MS * CC) ? f0 : f1 - MS * CC;
    float v = src[i];
    x[i] = v;
    bf16 h, l; bsplit1(v, h, l);
    xh[i] = h; xl[i] = l;
}

/* ------------------------------------------------------------------ */
/* Self linear attention — batched over 4 slabs (feature x batch)      */
/* ------------------------------------------------------------------ */
__global__ void __launch_bounds__(256) self_kv_kernel(
    const float* __restrict__ qkv, maskp __restrict__ m0p,
    maskp __restrict__ m1p, float* __restrict__ KVKS)
{
    int blk = blockIdx.x;                /* 512 blocks */
    int ch = blk & 15, h = (blk >> 4) & 7, fb = blk >> 7;  /* fb 0..3 */
    int tid = threadIdx.x;
    int d = tid >> 3, eq = tid & 7, e0 = eq << 2;
    float a0 = 0.f, a1 = 0.f, a2 = 0.f, a3 = 0.f, accs = 0.f;
    int base = (fb << 12) + (ch << 8);
    maskp mp = ((fb >> 1) ? m1p : m0p) + ((fb & 1) << 12) + (ch << 8);
    const float* kp = qkv + (size_t)base * QS + 256 + h * DD + d;
    const float* vp = qkv + (size_t)base * QS + 512 + h * DD + e0;
#pragma unroll 4
    for (int r = 0; r < 256; ++r) {
        float m = mp[r] ? 1.f : 0.f;
        float kf = m * elu1(kp[(size_t)r * QS]);
        float4 v = *(const float4*)(vp + (size_t)r * QS);
        a0 += kf * v.x; a1 += kf * v.y; a2 += kf * v.z; a3 += kf * v.w;
        accs += kf;
    }
    float* kvp = KVKS + ((size_t)((fb * HH + h) * DD + d) * DD + e0);
    atomicAdd(kvp + 0, a0);
    atomicAdd(kvp + 1, a1);
    atomicAdd(kvp + 2, a2);
    atomicAdd(kvp + 3, a3);
    if (eq == 0) atomicAdd(KVKS + KVSZ + (fb * HH + h) * DD + d, accs);
}

__global__ void __launch_bounds__(256) self_att_kernel(
    const float* __restrict__ qkv, const float* __restrict__ KVKS,
    bf16* __restrict__ oh, bf16* __restrict__ ol)
{
    __shared__ float sKV[HH][DD][DD];
    __shared__ float sKs[HH][DD];
    __shared__ float sQf[8][CC];
    int tid = threadIdx.x;
    int t0 = blockIdx.x << 3;
    int fb = t0 >> 12;
    for (int i = tid; i < HH * DD * DD; i += 256)
        (&sKV[0][0][0])[i] = KVKS[(size_t)fb * HH * DD * DD + i];
    for (int i = tid; i < HH * DD; i += 256)
        (&sKs[0][0])[i] = KVKS[KVSZ + fb * HH * DD + i];
#pragma unroll
    for (int tt = 0; tt < 8; ++tt)
        sQf[tt][tid] = elu1(qkv[(size_t)(t0 + tt) * QS + tid]);
    __syncthreads();
    int h = tid >> 5, e = tid & 31;
#pragma unroll
    for (int tt = 0; tt < 8; ++tt) {
        float den = sQf[tt][(h << 5) + e] * sKs[h][e];
#pragma unroll
        for (int o = 16; o; o >>= 1) den += __shfl_xor_sync(0xffffffffu, den, o);
        float out = 0.f;
#pragma unroll
        for (int d = 0; d < 32; ++d)
            out += sQf[tt][(h << 5) + d] * sKV[h][d][e];
        float o = out / (den + 1e-6f);
        bf16 hh, lo; bsplit1(o, hh, lo);
        oh[(size_t)(t0 + tt) * CC + tid] = hh;
        ol[(size_t)(t0 + tt) * CC + tid] = lo;
    }
}

/* ------------------------------------------------------------------ */
/* bilinear taps + invnorm + cross attention (batched)                 */
/* ------------------------------------------------------------------ */
__device__ __forceinline__ void taps_of(float kx, float ky, int base,
                                        int* r, float* w)
{
    float px = (((kx - 3.5f) / 507.5f * 2.f - 1.f) + 1.f) * 0.5f * 63.f;
    float py = (((ky - 3.5f) / 507.5f * 2.f - 1.f) + 1.f) * 0.5f * 63.f;
    float x0f = floorf(px), y0f = floorf(py);
    float wx = px - x0f, wy = py - y0f;
    int ix0 = min(max((int)x0f, 0), 63);
    int ix1 = min(max((int)x0f + 1, 0), 63);
    int iy0 = min(max((int)y0f, 0), 63);
    int iy1 = min(max((int)y0f + 1, 0), 63);
    r[0] = base + (iy0 << 6) + ix0;
    r[1] = base + (iy0 << 6) + ix1;
    r[2] = base + (iy1 << 6) + ix0;
    r[3] = base + (iy1 << 6) + ix1;
    w[0] = (1.f - wy) * (1.f - wx);
    w[1] = (1.f - wy) * wx;
    w[2] = wy * (1.f - wx);
    w[3] = wy * wx;
}

__global__ void __launch_bounds__(256) invnorm_kernel(
    const float* __restrict__ x, const float* __restrict__ kp0,
    const float* __restrict__ kp1, float* __restrict__ invn)
{
    int pg = (blockIdx.x << 3) + (threadIdx.x >> 5);
    int lane = threadIdx.x & 31;
    int f = pg >= MD;
    int pl = pg - f * MD;
    const float* kp = f ? kp1 : kp0;
    int b = pl / (LL * KK);
    int r[4]; float w[4];
    taps_of(kp[(size_t)pl * 2], kp[(size_t)pl * 2 + 1],
            f * MS + b * LL, r, w);
    const float* f0 = x + (size_t)r[0] * CC;
    const float* f1 = x + (size_t)r[1] * CC;
    const float* f2 = x + (size_t)r[2] * CC;
    const float* f3 = x + (size_t)r[3] * CC;
    float sq = 0.f;
#pragma unroll
    for (int j = 0; j < 8; ++j) {
        int c = lane + (j << 5);
        float val = w[0]*f0[c] + w[1]*f1[c] + w[2]*f2[c] + w[3]*f3[c];
        sq += val * val;
    }
#pragma unroll
    for (int o = 16; o; o >>= 1) sq += __shfl_xor_sync(0xffffffffu, sq, o);
    if (lane == 0) invn[pg] = 1.f / (sqrtf(sq) + 1e-8f);
}

__global__ void __launch_bounds__(256) cross_att_kernel(
    const float* __restrict__ qkv, const float* __restrict__ kp0,
    const float* __restrict__ kp1, const float* __restrict__ invn,
    maskp __restrict__ mc0, maskp __restrict__ mc1,
    bf16* __restrict__ oh, bf16* __restrict__ ol)
{
    int t = blockIdx.x;
    int tid = threadIdx.x;
    int h = tid >> 5, lane = tid & 31;
    int f = t >> 13;
    int tok = t & (MS - 1);
    int b = tok >> 12;
    const float* kp = f ? kp0 : kp1;
    const float* inv_base = invn + (size_t)(1 - f) * MD;
    maskp mask = f ? mc0 : mc1;
    int src_base = (1 - f) * MS + b * LL;

    __shared__ float sQf[CC];
    __shared__ int   sTap[KK][4];
    __shared__ float sW[KK][4];
    __shared__ float sInv[KK];
    __shared__ float sM[KK];
    sQf[tid] = elu1(qkv[(size_t)t * QS + tid]);
    if (tid < KK) {
        int p = tok * KK + tid;
        int r[4]; float w[4];
        taps_of(kp[(size_t)p * 2], kp[(size_t)p * 2 + 1], src_base, r, w);
#pragma unroll
        for (int i = 0; i < 4; ++i) { sTap[tid][i] = r[i]; sW[tid][i] = w[i]; }
        sInv[tid] = inv_base[p];
        sM[tid] = mask[p] ? 1.f : 0.f;
    }
    __syncthreads();
    int c = (h << 5) + lane;
    float qf = sQf[c];
    float wgt[KK];
    float den = 0.f;
#pragma unroll
    for (int s = 0; s < KK; ++s) {
        float kraw =
            sW[s][0] * qkv[(size_t)sTap[s][0] * QS + 256 + c] +
            sW[s][1] * qkv[(size_t)sTap[s][1] * QS + 256 + c] +
            sW[s][2] * qkv[(size_t)sTap[s][2] * QS + 256 + c] +
            sW[s][3] * qkv[(size_t)sTap[s][3] * QS + 256 + c];
        float kf = elu1(kraw * sInv[s]) * sM[s];
        float p = qf * kf;
#pragma unroll
        for (int o = 16; o; o >>= 1) p += __shfl_xor_sync(0xffffffffu, p, o);
        wgt[s] = p;
        den += p;
    }
    float inv = 1.f / (den + 1e-6f);
    float out = 0.f;
#pragma unroll
    for (int s = 0; s < KK; ++s) {
        float vraw =
            sW[s][0] * qkv[(size_t)sTap[s][0] * QS + 512 + c] +
            sW[s][1] * qkv[(size_t)sTap[s][1] * QS + 512 + c] +
            sW[s][2] * qkv[(size_t)sTap[s][2] * QS + 512 + c] +
            sW[s][3] * qkv[(size_t)sTap[s][3] * QS + 512 + c];
        out += wgt[s] * (vraw * sInv[s]);
    }
    float o = out * inv;
    bf16 hh, lo; bsplit1(o, hh, lo);
    oh[(size_t)t * CC + tid] = hh;
    ol[(size_t)t * CC + tid] = lo;
}

/* ------------------------------------------------------------------ */
/* LayerNorm (C=256, eps 1e-5)                                         */
/* ------------------------------------------------------------------ */
__device__ __forceinline__ void ln_core(const float* xr, float* v,
                                        float& mean, float& rstd)
{
    int lane = threadIdx.x & 31;
    float s = 0.f;
#pragma unroll
    for (int j = 0; j < 8; ++j) { v[j] = xr[lane + (j << 5)]; s += v[j]; }
#pragma unroll
    for (int o = 16; o; o >>= 1) s += __shfl_xor_sync(0xffffffffu, s, o);
    mean = s * (1.f / 256.f);
    float q = 0.f;
#pragma unroll
    for (int j = 0; j < 8; ++j) { float d = v[j] - mean; q += d * d; }
#pragma unroll
    for (int o = 16; o; o >>= 1) q += __shfl_xor_sync(0xffffffffu, q, o);
    rstd = rsqrtf(q * (1.f / 256.f) + 1e-5f);
}

__global__ void __launch_bounds__(256) ln_split_kernel(
    const float* __restrict__ X, const float* __restrict__ gam,
    const float* __restrict__ bet, bf16* __restrict__ oh,
    bf16* __restrict__ ol)
{
    int warp = threadIdx.x >> 5, lane = threadIdx.x & 31;
    int row = (blockIdx.x << 3) + warp;
    float v[8], mean, rstd;
    ln_core(X + (size_t)row * CC, v, mean, rstd);
#pragma unroll
    for (int j = 0; j < 8; ++j) {
        int c = lane + (j << 5);
        float o = (v[j] - mean) * rstd * gam[c] + bet[c];
        bf16 h, l; bsplit1(o, h, l);
        oh[(size_t)row * CC + c] = h;
        ol[(size_t)row * CC + c] = l;
    }
}

__global__ void __launch_bounds__(256) ln_add_kernel(
    const float* __restrict__ X, const float* __restrict__ gam,
    const float* __restrict__ bet, float* __restrict__ x,
    bf16* __restrict__ xh, bf16* __restrict__ xl)
{
    int warp = threadIdx.x >> 5, lane = threadIdx.x & 31;
    int row = (blockIdx.x << 3) + warp;
    float v[8], mean, rstd;
    ln_core(X + (size_t)row * CC, v, mean, rstd);
#pragma unroll
    for (int j = 0; j < 8; ++j) {
        int c = lane + (j << 5);
        float o = (v[j] - mean) * rstd * gam[c] + bet[c];
        float nx = x[(size_t)row * CC + c] + o;
        x[(size_t)row * CC + c] = nx;
        bf16 h, l; bsplit1(nx, h, l);
        xh[(size_t)row * CC + c] = h;
        xl[(size_t)row * CC + c] = l;
    }
}

/* ------------------------------------------------------------------ */
/* host orchestration                                                  */
/* ------------------------------------------------------------------ */
struct LayerW {
    const float *g1, *b1, *g2, *b2;
    bf16 *whP, *wlP, *whM, *wlM, *wh1, *wl1, *wh2, *wl2;
};
struct Bufs {
    float *t, *kvks;
    bf16 *atth, *attl, *msgh, *msgl, *uh, *ul;
};

static void mlp_tail(float* x, bf16* xh, bf16* xl, const LayerW& w,
                     const Bufs& s)
{
    hgemm2_kernel<<<dim3(2,128), 256, DSMEM>>>(
        s.atth, s.attl, (const bf16*)0, (const bf16*)0,
        w.whM, w.wlM, s.t, (bf16*)0, (bf16*)0, CC, CC, 0);
    ln_split_kernel<<<M2/8, 256>>>(s.t, w.g1, w.b1, s.msgh, s.msgl);
    hgemm2_kernel<<<dim3(4,128), 256, DSMEM>>>(
        xh, xl, s.msgh, s.msgl, w.wh1, w.wl1,
        (float*)0, s.uh, s.ul, C2, C2, 3);
    hgemm2_kernel<<<dim3(2,128), 256, DSMEM>>>(
        s.uh, s.ul, (const bf16*)0, (const bf16*)0,
        w.wh2, w.wl2, s.t, (bf16*)0, (bf16*)0, CC, C2, 0);
    ln_add_kernel<<<M2/8, 256>>>(s.t, w.g2, w.b2, x, xh, xl);
}

extern "C" void kernel_launch(void* const* d_in, const int* in_sizes, int n_in,
                              void* d_out, int out_size)
{
    (void)in_sizes; (void)n_in; (void)out_size;
    const float* feat0 = (const float*)d_in[0];
    const float* feat1 = (const float*)d_in[1];
    const float* kp0   = (const float*)d_in[2];
    const float* kp1   = (const float*)d_in[3];
    maskp ms0 = (maskp)d_in[4];
    maskp ms1 = (maskp)d_in[5];
    maskp mc0 = (maskp)d_in[6];
    maskp mc1 = (maskp)d_in[7];
    const float* Wq = (const float*)d_in[8];
    const float* Wk = (const float*)d_in[9];
    const float* Wv = (const float*)d_in[10];
    const float* Wm = (const float*)d_in[11];
    const float* W1 = (const float*)d_in[12];
    const float* W2 = (const float*)d_in[13];
    const float* G1 = (const float*)d_in[14];
    const float* B1 = (const float*)d_in[15];
    const float* G2 = (const float*)d_in[16];
    const float* B2 = (const float*)d_in[17];

    cudaFuncSetAttribute(hgemm2_kernel,
                         cudaFuncAttributeMaxDynamicSharedMemorySize, DSMEM);

    float *px, *pq, *pin;
    bf16 *pxh, *pxl;
    bf16 *whP, *wlP, *whM, *wlM, *wh1, *wl1, *wh2, *wl2;
    Bufs s;
    cudaGetSymbolAddress((void**)&px, g_x);
    cudaGetSymbolAddress((void**)&pxh, g_xh);
    cudaGetSymbolAddress((void**)&pxl, g_xl);
    cudaGetSymbolAddress((void**)&pq, g_qkv);
    cudaGetSymbolAddress((void**)&pin, g_invn);
    cudaGetSymbolAddress((void**)&s.t, g_tb);
    cudaGetSymbolAddress((void**)&s.kvks, g_kvks);
    cudaGetSymbolAddress((void**)&s.atth, g_atth);
    cudaGetSymbolAddress((void**)&s.attl, g_attl);
    cudaGetSymbolAddress((void**)&s.msgh, g_msgh);
    cudaGetSymbolAddress((void**)&s.msgl, g_msgl);
    cudaGetSymbolAddress((void**)&s.uh, g_uh);
    cudaGetSymbolAddress((void**)&s.ul, g_ul);
    cudaGetSymbolAddress((void**)&whP, g_whP);
    cudaGetSymbolAddress((void**)&wlP, g_wlP);
    cudaGetSymbolAddress((void**)&whM, g_whM);
    cudaGetSymbolAddress((void**)&wlM, g_wlM);
    cudaGetSymbolAddress((void**)&wh1, g_wh1);
    cudaGetSymbolAddress((void**)&wl1, g_wl1);
    cudaGetSymbolAddress((void**)&wh2, g_wh2);
    cudaGetSymbolAddress((void**)&wl2, g_wl2);

    /* front-loaded weight prep + input split */
    wpackT_all_kernel<<<NL*CC*QS/256, 256>>>(Wq, Wk, Wv, whP, wlP);
    wtrans_all_kernel<<<NL*CC*CC/256, 256>>>(Wm, whM, wlM, CC, CC);
    wtrans_all_kernel<<<NL*C2*C2/256, 256>>>(W1, wh1, wl1, C2, C2);
    wtrans_all_kernel<<<NL*C2*CC/256, 256>>>(W2, wh2, wl2, C2, CC);
    split_in_kernel<<<M2*CC/256, 256>>>(feat0, feat1, px, pxh, pxl);

    for (int i = 0; i < 4; ++i) {
        LayerW w;
        w.g1 = G1 + (size_t)i * CC;
        w.b1 = B1 + (size_t)i * CC;
        w.g2 = G2 + (size_t)i * CC;
        w.b2 = B2 + (size_t)i * CC;
        w.whP = whP + (size_t)i * QS * CC; w.wlP = wlP + (size_t)i * QS * CC;
        w.whM = whM + (size_t)i * CC * CC; w.wlM = wlM + (size_t)i * CC * CC;
        w.wh1 = wh1 + (size_t)i * C2 * C2; w.wl1 = wl1 + (size_t)i * C2 * C2;
        w.wh2 = wh2 + (size_t)i * C2 * CC; w.wl2 = wl2 + (size_t)i * C2 * CC;

        hgemm2_kernel<<<dim3(6,128), 256, DSMEM>>>(
            pxh, pxl, (const bf16*)0, (const bf16*)0,
            w.whP, w.wlP, pq, (bf16*)0, (bf16*)0, QS, CC, 0);

        if ((i & 1) == 0) {
            cudaMemsetAsync(s.kvks, 0, (size_t)(KVSZ + KSSZ) * sizeof(float), 0);
            self_kv_kernel<<<512, 256>>>(pq, ms0, ms1, s.kvks);
            self_att_kernel<<<M2/8, 256>>>(pq, s.kvks, s.atth, s.attl);
        } else {
            invnorm_kernel<<<2*MD/8, 256>>>(px, kp0, kp1, pin);
            cross_att_kernel<<<M2, 256>>>(pq, kp0, kp1, pin, mc0, mc1,
                                          s.atth, s.attl);
        }
        mlp_tail(px, pxh, pxl, w, s);
    }

    cudaMemcpyAsync(d_out, px, (size_t)M2 * CC * sizeof(float),
                    cudaMemcpyDeviceToDevice, 0);
}

// round 11
// speedup vs baseline: 3.4458x; 1.1695x over previous
#include <cuda_runtime.h>
#include <cuda_fp16.h>
#include <cstdint>
#include <math.h>

#define BB 2
#define LL 4096
#define CC 256
#define C2 512
#define QS 768
#define HH 8
#define DD 32
#define KK 9
#define NL 4
#define MS (BB*LL)          /* rows per feature   */
#define M2 (2*MS)           /* batched rows       */
#define MD (BB*LL*KK)       /* points per feature */
#define KVSZ (4*HH*DD*DD)
#define KSSZ (4*HH*DD)

typedef const unsigned int* maskp;

/* ------------------------------------------------------------------ */
/* device globals — feat0 half then feat1 half, contiguous             */
/* ------------------------------------------------------------------ */
__device__ float  g_x[M2*CC];
__device__ __half g_xh[M2*CC];
__device__ float  g_qkv[M2*QS];
__device__ float  g_invn[2*MD];
__device__ __half g_atth[M2*CC];
__device__ __half g_msgh[M2*CC];
__device__ __half g_uh[M2*C2];
__device__ float  g_tb[M2*CC];
__device__ float  g_kvks[KVSZ + KSSZ];
/* per-layer fp16 hi/lo split transposed weights [N,K] */
__device__ __half g_whP[NL*QS*CC], g_wlP[NL*QS*CC];
__device__ __half g_whM[NL*CC*CC], g_wlM[NL*CC*CC];
__device__ __half g_wh1[NL*C2*C2], g_wl1[NL*C2*C2];
__device__ __half g_wh2[NL*CC*C2], g_wl2[NL*CC*C2];

__device__ __forceinline__ float elu1(float x) { return x > 0.f ? x + 1.f : expf(x); }

__device__ __forceinline__ uint32_t smem_u32(const void* p) {
    uint32_t a;
    asm("{ .reg .u64 t; cvta.to.shared.u64 t, %1; cvt.u32.u64 %0, t; }"
        : "=r"(a) : "l"(p));
    return a;
}
__device__ __forceinline__ void cp16(uint32_t dst, const void* src) {
    asm volatile(
        "{ .reg .u64 g; cvta.to.global.u64 g, %1; "
        "cp.async.cg.shared.global [%0], [g], 16; }"
        :: "r"(dst), "l"(src));
}
#define CP_COMMIT() asm volatile("cp.async.commit_group;")
#define CP_WAIT(n)  asm volatile("cp.async.wait_group %0;" :: "n"(n))

__device__ __forceinline__ void ldsm4(uint32_t* r, uint32_t a) {
    asm volatile("ldmatrix.sync.aligned.m8n8.x4.shared.b16 {%0,%1,%2,%3}, [%4];"
                 : "=r"(r[0]), "=r"(r[1]), "=r"(r[2]), "=r"(r[3]) : "r"(a));
}
__device__ __forceinline__ void ldsm2(uint32_t* r, uint32_t a) {
    asm volatile("ldmatrix.sync.aligned.m8n8.x2.shared.b16 {%0,%1}, [%2];"
                 : "=r"(r[0]), "=r"(r[1]) : "r"(a));
}
__device__ __forceinline__ void mma16816(float* c, const uint32_t* a,
                                         const uint32_t* b) {
    asm volatile(
        "mma.sync.aligned.m16n8k16.row.col.f32.f16.f16.f32 "
        "{%0,%1,%2,%3}, {%4,%5,%6,%7}, {%8,%9}, {%0,%1,%2,%3};"
        : "+f"(c[0]), "+f"(c[1]), "+f"(c[2]), "+f"(c[3])
        : "r"(a[0]), "r"(a[1]), "r"(a[2]), "r"(a[3]), "r"(b[0]), "r"(b[1]));
}
__device__ __forceinline__ void hsplit1(float v, __half& h, __half& l) {
    h = __float2half_rn(v);
    l = __float2half_rn(v - __half2float(h));
}

/* ------------------------------------------------------------------ */
/* HMMA GEMM: A fp16 single, W fp16 hi/lo split, cp.async dbl buffer   */
/* CTA 128x128, warp 64x32, k-chunk 32, TSTR=40 conflict-free          */
/* mode bit0: A split across two arrays ([A1|A2], lda=256, Kd=512)     */
/* mode bit1: tanh epilogue + fp16 output (Ch)                         */
/* ------------------------------------------------------------------ */
#define TSTR 40
#define TILE_B (128*TSTR*2)           /* 10240 bytes per tile */
#define OFFB_A  0
#define OFFB_BH (1*TILE_B)
#define OFFB_BL (2*TILE_B)
#define STAGE_B (3*TILE_B)            /* 30720 */
#define DSMEM   (2*STAGE_B)           /* 61440 */

__global__ void __launch_bounds__(256, 2)
hgemm3_kernel(const __half* __restrict__ A1, const __half* __restrict__ A2,
              const __half* __restrict__ Wh, const __half* __restrict__ Wl,
              float* __restrict__ Cf, __half* __restrict__ Ch,
              int N, int Kd, int mode)
{
    extern __shared__ __align__(16) char smh[];
    uint32_t smbase = smem_u32(smh);
    int tid = threadIdx.x, wid = tid >> 5, lane = tid & 31;
    int g = lane >> 2, q = lane & 3;
    int m0 = blockIdx.y << 7, n0 = blockIdx.x << 7;
    int wm = wid >> 2, wn = wid & 3;
    int arow = wm << 6, brow = wn << 5;

    int lr = lane & 7, sel = lane >> 3;
    uint32_t aoff = (uint32_t)(((arow + lr + (sel & 1) * 8) * TSTR
                                + (sel >> 1) * 8) * 2);
    uint32_t boff = (uint32_t)(((brow + lr) * TSTR + (sel & 1) * 8) * 2);

    float acc[4][4][4];
#pragma unroll
    for (int i = 0; i < 4; ++i)
#pragma unroll
        for (int j = 0; j < 4; ++j)
#pragma unroll
            for (int k = 0; k < 4; ++k) acc[i][j][k] = 0.f;

    const int NC = Kd >> 5;

#define ISSUE_CHUNK(CI) do {                                               \
        int k0_ = (CI) << 5;                                               \
        const __half* a_; int lda_, kl_;                                   \
        if (mode & 1) {                                                    \
            if (k0_ < 256) { a_ = A1; kl_ = k0_; }                         \
            else           { a_ = A2; kl_ = k0_ - 256; }                   \
            lda_ = 256;                                                    \
        } else { a_ = A1; kl_ = k0_; lda_ = Kd; }                          \
        uint32_t sb_ = smbase + ((CI) & 1) * STAGE_B;                      \
        _Pragma("unroll")                                                  \
        for (int i_ = 0; i_ < 2; ++i_) {                                   \
            int s_ = tid + (i_ << 8);                                      \
            int row_ = s_ >> 2, part_ = s_ & 3;                            \
            uint32_t dr_ = (uint32_t)(row_ * (TSTR * 2) + part_ * 16);     \
            cp16(sb_ + OFFB_A + dr_,                                       \
                 a_ + (size_t)(m0 + row_) * lda_ + kl_ + part_ * 8);       \
            size_t wsrc_ = (size_t)(n0 + row_) * Kd + k0_ + part_ * 8;     \
            cp16(sb_ + OFFB_BH + dr_, Wh + wsrc_);                         \
            cp16(sb_ + OFFB_BL + dr_, Wl + wsrc_);                         \
        }                                                                  \
        CP_COMMIT();                                                       \
    } while (0)

    ISSUE_CHUNK(0);

    for (int kt = 0; kt < NC; ++kt) {
        if (kt + 1 < NC) { ISSUE_CHUNK(kt + 1); CP_WAIT(1); }
        else             { CP_WAIT(0); }
        __syncthreads();
        uint32_t sb = smbase + (kt & 1) * STAGE_B;
#pragma unroll
        for (int ks = 0; ks < 32; ks += 16) {
            uint32_t aR[4][4], bH[4][2], bL[4][2];
#pragma unroll
            for (int mf = 0; mf < 4; ++mf)
                ldsm4(aR[mf], sb + OFFB_A + aoff + mf * (16 * TSTR * 2) + ks * 2);
#pragma unroll
            for (int nf = 0; nf < 4; ++nf)
                ldsm2(bH[nf], sb + OFFB_BH + boff + nf * (8 * TSTR * 2) + ks * 2);
#pragma unroll
            for (int mf = 0; mf < 4; ++mf)
#pragma unroll
                for (int nf = 0; nf < 4; ++nf)
                    mma16816(acc[mf][nf], aR[mf], bH[nf]);
#pragma unroll
            for (int nf = 0; nf < 4; ++nf)
                ldsm2(bL[nf], sb + OFFB_BL + boff + nf * (8 * TSTR * 2) + ks * 2);
#pragma unroll
            for (int mf = 0; mf < 4; ++mf)
#pragma unroll
                for (int nf = 0; nf < 4; ++nf)
                    mma16816(acc[mf][nf], aR[mf], bL[nf]);
        }
        __syncthreads();
    }
#undef ISSUE_CHUNK

#pragma unroll
    for (int mf = 0; mf < 4; ++mf) {
#pragma unroll
        for (int nf = 0; nf < 4; ++nf) {
            int r = m0 + arow + (mf << 4) + g;
            int c = n0 + brow + (nf << 3) + (q << 1);
            if (mode & 2) {
                float t0 = tanhf(acc[mf][nf][0]), t1 = tanhf(acc[mf][nf][1]);
                float t2 = tanhf(acc[mf][nf][2]), t3 = tanhf(acc[mf][nf][3]);
                __half2 p01 = __floats2half2_rn(t0, t1);
                __half2 p23 = __floats2half2_rn(t2, t3);
                *(__half2*)(Ch + (size_t)r * N + c) = p01;
                *(__half2*)(Ch + (size_t)(r + 8) * N + c) = p23;
            } else {
                float2 v0, v1;
                v0.x = acc[mf][nf][0]; v0.y = acc[mf][nf][1];
                v1.x = acc[mf][nf][2]; v1.y = acc[mf][nf][3];
                *(float2*)(Cf + (size_t)r * N + c) = v0;
                *(float2*)(Cf + (size_t)(r + 8) * N + c) = v1;
            }
        }
    }
}

/* ------------------------------------------------------------------ */
/* weight prep (all layers per launch): transpose + fp16 hi/lo split   */
/* ------------------------------------------------------------------ */
__global__ void wtrans_all_kernel(const float* __restrict__ W,
                                  __half* __restrict__ wh,
                                  __half* __restrict__ wl, int Kd, int N)
{
    int idx = blockIdx.x * 256 + threadIdx.x;
    int per = Kd * N;
    int layer = idx / per, r = idx - layer * per;
    int k = r / N, n = r - k * N;
    float v = W[(size_t)layer * per + (size_t)k * N + n];
    __half h, l; hsplit1(v, h, l);
    size_t dst = (size_t)layer * per + (size_t)n * Kd + k;
    wh[dst] = h; wl[dst] = l;
}

__global__ void wpackT_all_kernel(const float* __restrict__ Wq,
                                  const float* __restrict__ Wk,
                                  const float* __restrict__ Wv,
                                  __half* __restrict__ wh,
                                  __half* __restrict__ wl)
{
    int idx = blockIdx.x * 256 + threadIdx.x;
    int per = CC * QS;
    int layer = idx / per, r = idx - layer * per;
    int k = r / QS, n = r - k * QS;
    const float* src = (n < 256) ? Wq : (n < 512) ? Wk : Wv;
    float v = src[(size_t)layer * CC * CC + (size_t)k * 256 + (n & 255)];
    __half h, l; hsplit1(v, h, l);
    size_t dst = (size_t)layer * (QS * CC) + (size_t)n * CC + k;
    wh[dst] = h; wl[dst] = l;
}

/* initial x copy + fp16 round, both features into contiguous halves   */
__global__ void split_in_kernel(const float* __restrict__ f0,
                                const float* __restrict__ f1,
                                float* __restrict__ x,
                                __half* __restrict__ xh)
{
    int i = blockIdx.x * 256 + threadIdx.x;
    const float* src = (i < MS * CC) ? f0 : f1 - MS * CC;
    float v = src[i];
    x[i] = v;
    xh[i] = __float2half_rn(v);
}

/* ------------------------------------------------------------------ */
/* Self linear attention — batched over 4 slabs (feature x batch)      */
/* ------------------------------------------------------------------ */
__global__ void __launch_bounds__(256) self_kv_kernel(
    const float* __restrict__ qkv, maskp __restrict__ m0p,
    maskp __restrict__ m1p, float* __restrict__ KVKS)
{
    int blk = blockIdx.x;                /* 512 blocks */
    int ch = blk & 15, h = (blk >> 4) & 7, fb = blk >> 7;
    int tid = threadIdx.x;
    int d = tid >> 3, eq = tid & 7, e0 = eq << 2;
    float a0 = 0.f, a1 = 0.f, a2 = 0.f, a3 = 0.f, accs = 0.f;
    int base = (fb << 12) + (ch << 8);
    maskp mp = ((fb >> 1) ? m1p : m0p) + ((fb & 1) << 12) + (ch << 8);
    const float* kp = qkv + (size_t)base * QS + 256 + h * DD + d;
    const float* vp = qkv + (size_t)base * QS + 512 + h * DD + e0;
#pragma unroll 4
    for (int r = 0; r < 256; ++r) {
        float m = mp[r] ? 1.f : 0.f;
        float kf = m * elu1(kp[(size_t)r * QS]);
        float4 v = *(const float4*)(vp + (size_t)r * QS);
        a0 += kf * v.x; a1 += kf * v.y; a2 += kf * v.z; a3 += kf * v.w;
        accs += kf;
    }
    float* kvp = KVKS + ((size_t)((fb * HH + h) * DD + d) * DD + e0);
    atomicAdd(kvp + 0, a0);
    atomicAdd(kvp + 1, a1);
    atomicAdd(kvp + 2, a2);
    atomicAdd(kvp + 3, a3);
    if (eq == 0) atomicAdd(KVKS + KVSZ + (fb * HH + h) * DD + d, accs);
}

__global__ void __launch_bounds__(256) self_att_kernel(
    const float* __restrict__ qkv, const float* __restrict__ KVKS,
    __half* __restrict__ oh)
{
    __shared__ float sKV[HH][DD][DD];
    __shared__ float sKs[HH][DD];
    __shared__ float sQf[8][CC];
    int tid = threadIdx.x;
    int t0 = blockIdx.x << 3;
    int fb = t0 >> 12;
    for (int i = tid; i < HH * DD * DD; i += 256)
        (&sKV[0][0][0])[i] = KVKS[(size_t)fb * HH * DD * DD + i];
    for (int i = tid; i < HH * DD; i += 256)
        (&sKs[0][0])[i] = KVKS[KVSZ + fb * HH * DD + i];
#pragma unroll
    for (int tt = 0; tt < 8; ++tt)
        sQf[tt][tid] = elu1(qkv[(size_t)(t0 + tt) * QS + tid]);
    __syncthreads();
    int h = tid >> 5, e = tid & 31;
#pragma unroll
    for (int tt = 0; tt < 8; ++tt) {
        float den = sQf[tt][(h << 5) + e] * sKs[h][e];
#pragma unroll
        for (int o = 16; o; o >>= 1) den += __shfl_xor_sync(0xffffffffu, den, o);
        float out = 0.f;
#pragma unroll
        for (int d = 0; d < 32; ++d)
            out += sQf[tt][(h << 5) + d] * sKV[h][d][e];
        oh[(size_t)(t0 + tt) * CC + tid] = __float2half_rn(out / (den + 1e-6f));
    }
}

/* ------------------------------------------------------------------ */
/* bilinear taps + invnorm + cross attention (batched)                 */
/* ------------------------------------------------------------------ */
__device__ __forceinline__ void taps_of(float kx, float ky, int base,
                                        int* r, float* w)
{
    float px = (((kx - 3.5f) / 507.5f * 2.f - 1.f) + 1.f) * 0.5f * 63.f;
    float py = (((ky - 3.5f) / 507.5f * 2.f - 1.f) + 1.f) * 0.5f * 63.f;
    float x0f = floorf(px), y0f = floorf(py);
    float wx = px - x0f, wy = py - y0f;
    int ix0 = min(max((int)x0f, 0), 63);
    int ix1 = min(max((int)x0f + 1, 0), 63);
    int iy0 = min(max((int)y0f, 0), 63);
    int iy1 = min(max((int)y0f + 1, 0), 63);
    r[0] = base + (iy0 << 6) + ix0;
    r[1] = base + (iy0 << 6) + ix1;
    r[2] = base + (iy1 << 6) + ix0;
    r[3] = base + (iy1 << 6) + ix1;
    w[0] = (1.f - wy) * (1.f - wx);
    w[1] = (1.f - wy) * wx;
    w[2] = wy * (1.f - wx);
    w[3] = wy * wx;
}

__global__ void __launch_bounds__(256) invnorm_kernel(
    const float* __restrict__ x, const float* __restrict__ kp0,
    const float* __restrict__ kp1, float* __restrict__ invn)
{
    int pg = (blockIdx.x << 3) + (threadIdx.x >> 5);
    int lane = threadIdx.x & 31;
    int f = pg >= MD;
    int pl = pg - f * MD;
    const float* kp = f ? kp1 : kp0;
    int b = pl / (LL * KK);
    int r[4]; float w[4];
    taps_of(kp[(size_t)pl * 2], kp[(size_t)pl * 2 + 1],
            f * MS + b * LL, r, w);
    const float* f0 = x + (size_t)r[0] * CC;
    const float* f1 = x + (size_t)r[1] * CC;
    const float* f2 = x + (size_t)r[2] * CC;
    const float* f3 = x + (size_t)r[3] * CC;
    float sq = 0.f;
#pragma unroll
    for (int j = 0; j < 8; ++j) {
        int c = lane + (j << 5);
        float val = w[0]*f0[c] + w[1]*f1[c] + w[2]*f2[c] + w[3]*f3[c];
        sq += val * val;
    }
#pragma unroll
    for (int o = 16; o; o >>= 1) sq += __shfl_xor_sync(0xffffffffu, sq, o);
    if (lane == 0) invn[pg] = 1.f / (sqrtf(sq) + 1e-8f);
}

__global__ void __launch_bounds__(256) cross_att_kernel(
    const float* __restrict__ qkv, const float* __restrict__ kp0,
    const float* __restrict__ kp1, const float* __restrict__ invn,
    maskp __restrict__ mc0, maskp __restrict__ mc1,
    __half* __restrict__ oh)
{
    int t = blockIdx.x;
    int tid = threadIdx.x;
    int h = tid >> 5, lane = tid & 31;
    int f = t >> 13;
    int tok = t & (MS - 1);
    int b = tok >> 12;
    const float* kp = f ? kp0 : kp1;
    const float* inv_base = invn + (size_t)(1 - f) * MD;
    maskp mask = f ? mc0 : mc1;
    int src_base = (1 - f) * MS + b * LL;

    __shared__ float sQf[CC];
    __shared__ int   sTap[KK][4];
    __shared__ float sW[KK][4];
    __shared__ float sInv[KK];
    __shared__ float sM[KK];
    sQf[tid] = elu1(qkv[(size_t)t * QS + tid]);
    if (tid < KK) {
        int p = tok * KK + tid;
        int r[4]; float w[4];
        taps_of(kp[(size_t)p * 2], kp[(size_t)p * 2 + 1], src_base, r, w);
#pragma unroll
        for (int i = 0; i < 4; ++i) { sTap[tid][i] = r[i]; sW[tid][i] = w[i]; }
        sInv[tid] = inv_base[p];
        sM[tid] = mask[p] ? 1.f : 0.f;
    }
    __syncthreads();
    int c = (h << 5) + lane;
    float qf = sQf[c];
    float wgt[KK];
    float den = 0.f;
#pragma unroll
    for (int s = 0; s < KK; ++s) {
        float kraw =
            sW[s][0] * qkv[(size_t)sTap[s][0] * QS + 256 + c] +
            sW[s][1] * qkv[(size_t)sTap[s][1] * QS + 256 + c] +
            sW[s][2] * qkv[(size_t)sTap[s][2] * QS + 256 + c] +
            sW[s][3] * qkv[(size_t)sTap[s][3] * QS + 256 + c];
        float kf = elu1(kraw * sInv[s]) * sM[s];
        float p = qf * kf;
#pragma unroll
        for (int o = 16; o; o >>= 1) p += __shfl_xor_sync(0xffffffffu, p, o);
        wgt[s] = p;
        den += p;
    }
    float inv = 1.f / (den + 1e-6f);
    float out = 0.f;
#pragma unroll
    for (int s = 0; s < KK; ++s) {
        float vraw =
            sW[s][0] * qkv[(size_t)sTap[s][0] * QS + 512 + c] +
            sW[s][1] * qkv[(size_t)sTap[s][1] * QS + 512 + c] +
            sW[s][2] * qkv[(size_t)sTap[s][2] * QS + 512 + c] +
            sW[s][3] * qkv[(size_t)sTap[s][3] * QS + 512 + c];
        out += wgt[s] * (vraw * sInv[s]);
    }
    oh[(size_t)t * CC + tid] = __float2half_rn(out * inv);
}

/* ------------------------------------------------------------------ */
/* LayerNorm (C=256, eps 1e-5)                                         */
/* ------------------------------------------------------------------ */
__device__ __forceinline__ void ln_core(const float* xr, float* v,
                                        float& mean, float& rstd)
{
    int lane = threadIdx.x & 31;
    float s = 0.f;
#pragma unroll
    for (int j = 0; j < 8; ++j) { v[j] = xr[lane + (j << 5)]; s += v[j]; }
#pragma unroll
    for (int o = 16; o; o >>= 1) s += __shfl_xor_sync(0xffffffffu, s, o);
    mean = s * (1.f / 256.f);
    float q = 0.f;
#pragma unroll
    for (int j = 0; j < 8; ++j) { float d = v[j] - mean; q += d * d; }
#pragma unroll
    for (int o = 16; o; o >>= 1) q += __shfl_xor_sync(0xffffffffu, q, o);
    rstd = rsqrtf(q * (1.f / 256.f) + 1e-5f);
}

__global__ void __launch_bounds__(256) ln_split_kernel(
    const float* __restrict__ X, const float* __restrict__ gam,
    const float* __restrict__ bet, __half* __restrict__ oh)
{
    int warp = threadIdx.x >> 5, lane = threadIdx.x & 31;
    int row = (blockIdx.x << 3) + warp;
    float v[8], mean, rstd;
    ln_core(X + (size_t)row * CC, v, mean, rstd);
#pragma unroll
    for (int j = 0; j < 8; ++j) {
        int c = lane + (j << 5);
        float o = (v[j] - mean) * rstd * gam[c] + bet[c];
        oh[(size_t)row * CC + c] = __float2half_rn(o);
    }
}

__global__ void __launch_bounds__(256) ln_add_kernel(
    const float* __restrict__ X, const float* __restrict__ gam,
    const float* __restrict__ bet, float* __restrict__ x,
    __half* __restrict__ xh)
{
    int warp = threadIdx.x >> 5, lane = threadIdx.x & 31;
    int row = (blockIdx.x << 3) + warp;
    float v[8], mean, rstd;
    ln_core(X + (size_t)row * CC, v, mean, rstd);
#pragma unroll
    for (int j = 0; j < 8; ++j) {
        int c = lane + (j << 5);
        float o = (v[j] - mean) * rstd * gam[c] + bet[c];
        float nx = x[(size_t)row * CC + c] + o;
        x[(size_t)row * CC + c] = nx;
        xh[(size_t)row * CC + c] = __float2half_rn(nx);
    }
}

/* ------------------------------------------------------------------ */
/* host orchestration                                                  */
/* ------------------------------------------------------------------ */
struct LayerW {
    const float *g1, *b1, *g2, *b2;
    __half *whP, *wlP, *whM, *wlM, *wh1, *wl1, *wh2, *wl2;
};
struct Bufs {
    float *t, *kvks;
    __half *atth, *msgh, *uh;
};

static void mlp_tail(float* x, __half* xh, const LayerW& w, const Bufs& s)
{
    hgemm3_kernel<<<dim3(2,128), 256, DSMEM>>>(
        s.atth, (const __half*)0, w.whM, w.wlM, s.t, (__half*)0, CC, CC, 0);
    ln_split_kernel<<<M2/8, 256>>>(s.t, w.g1, w.b1, s.msgh);
    hgemm3_kernel<<<dim3(4,128), 256, DSMEM>>>(
        xh, s.msgh, w.wh1, w.wl1, (float*)0, s.uh, C2, C2, 3);
    hgemm3_kernel<<<dim3(2,128), 256, DSMEM>>>(
        s.uh, (const __half*)0, w.wh2, w.wl2, s.t, (__half*)0, CC, C2, 0);
    ln_add_kernel<<<M2/8, 256>>>(s.t, w.g2, w.b2, x, xh);
}

extern "C" void kernel_launch(void* const* d_in, const int* in_sizes, int n_in,
                              void* d_out, int out_size)
{
    (void)in_sizes; (void)n_in; (void)out_size;
    const float* feat0 = (const float*)d_in[0];
    const float* feat1 = (const float*)d_in[1];
    const float* kp0   = (const float*)d_in[2];
    const float* kp1   = (const float*)d_in[3];
    maskp ms0 = (maskp)d_in[4];
    maskp ms1 = (maskp)d_in[5];
    maskp mc0 = (maskp)d_in[6];
    maskp mc1 = (maskp)d_in[7];
    const float* Wq = (const float*)d_in[8];
    const float* Wk = (const float*)d_in[9];
    const float* Wv = (const float*)d_in[10];
    const float* Wm = (const float*)d_in[11];
    const float* W1 = (const float*)d_in[12];
    const float* W2 = (const float*)d_in[13];
    const float* G1 = (const float*)d_in[14];
    const float* B1 = (const float*)d_in[15];
    const float* G2 = (const float*)d_in[16];
    const float* B2 = (const float*)d_in[17];

    cudaFuncSetAttribute(hgemm3_kernel,
                         cudaFuncAttributeMaxDynamicSharedMemorySize, DSMEM);

    float *px, *pq, *pin;
    __half *pxh;
    __half *whP, *wlP, *whM, *wlM, *wh1, *wl1, *wh2, *wl2;
    Bufs s;
    cudaGetSymbolAddress((void**)&px, g_x);
    cudaGetSymbolAddress((void**)&pxh, g_xh);
    cudaGetSymbolAddress((void**)&pq, g_qkv);
    cudaGetSymbolAddress((void**)&pin, g_invn);
    cudaGetSymbolAddress((void**)&s.t, g_tb);
    cudaGetSymbolAddress((void**)&s.kvks, g_kvks);
    cudaGetSymbolAddress((void**)&s.atth, g_atth);
    cudaGetSymbolAddress((void**)&s.msgh, g_msgh);
    cudaGetSymbolAddress((void**)&s.uh, g_uh);
    cudaGetSymbolAddress((void**)&whP, g_whP);
    cudaGetSymbolAddress((void**)&wlP, g_wlP);
    cudaGetSymbolAddress((void**)&whM, g_whM);
    cudaGetSymbolAddress((void**)&wlM, g_wlM);
    cudaGetSymbolAddress((void**)&wh1, g_wh1);
    cudaGetSymbolAddress((void**)&wl1, g_wl1);
    cudaGetSymbolAddress((void**)&wh2, g_wh2);
    cudaGetSymbolAddress((void**)&wl2, g_wl2);

    /* front-loaded weight prep + input round */
    wpackT_all_kernel<<<NL*CC*QS/256, 256>>>(Wq, Wk, Wv, whP, wlP);
    wtrans_all_kernel<<<NL*CC*CC/256, 256>>>(Wm, whM, wlM, CC, CC);
    wtrans_all_kernel<<<NL*C2*C2/256, 256>>>(W1, wh1, wl1, C2, C2);
    wtrans_all_kernel<<<NL*C2*CC/256, 256>>>(W2, wh2, wl2, C2, CC);
    split_in_kernel<<<M2*CC/256, 256>>>(feat0, feat1, px, pxh);

    for (int i = 0; i < 4; ++i) {
        LayerW w;
        w.g1 = G1 + (size_t)i * CC;
        w.b1 = B1 + (size_t)i * CC;
        w.g2 = G2 + (size_t)i * CC;
        w.b2 = B2 + (size_t)i * CC;
        w.whP = whP + (size_t)i * QS * CC; w.wlP = wlP + (size_t)i * QS * CC;
        w.whM = whM + (size_t)i * CC * CC; w.wlM = wlM + (size_t)i * CC * CC;
        w.wh1 = wh1 + (size_t)i * C2 * C2; w.wl1 = wl1 + (size_t)i * C2 * C2;
        w.wh2 = wh2 + (size_t)i * C2 * CC; w.wl2 = wl2 + (size_t)i * C2 * CC;

        hgemm3_kernel<<<dim3(6,128), 256, DSMEM>>>(
            pxh, (const __half*)0, w.whP, w.wlP, pq, (__half*)0, QS, CC, 0);

        if ((i & 1) == 0) {
            cudaMemsetAsync(s.kvks, 0, (size_t)(KVSZ + KSSZ) * sizeof(float), 0);
            self_kv_kernel<<<512, 256>>>(pq, ms0, ms1, s.kvks);
            self_att_kernel<<<M2/8, 256>>>(pq, s.kvks, s.atth);
        } else {
            invnorm_kernel<<<2*MD/8, 256>>>(px, kp0, kp1, pin);
            cross_att_kernel<<<M2, 256>>>(pq, kp0, kp1, pin, mc0, mc1, s.atth);
        }
        mlp_tail(px, pxh, w, s);
    }

    cudaMemcpyAsync(d_out, px, (size_t)M2 * CC * sizeof(float),
                    cudaMemcpyDeviceToDevice, 0);
}